// round 5
// baseline (speedup 1.0000x reference)
#include <cuda_runtime.h>
#include <cstdint>

// Problem constants
constexpr int Bn  = 4;
constexpr int Cn  = 64;
constexpr int CHn = 32;
constexpr int Fn  = 256;
constexpr int Tn  = 256;
constexpr int Sn  = Fn * Tn;          // 65536 spatial positions
constexpr float EPSc = 1e-5f;

// -------- device scratch (layouts chosen for the consumers) --------
__device__ float g_qf[Bn*Tn*Fn*CHn];
__device__ float g_kf[Bn*Tn*Fn*CHn];
__device__ float g_vf[Bn*Tn*Fn*CHn];
__device__ float g_qt[Bn*Fn*Tn*CHn];
__device__ float g_kt[Bn*Fn*Tn*CHn];
__device__ float g_fout[Bn*Fn*Tn*CHn];
__device__ float g_tout[Bn*Fn*Tn*CHn];

// dynamic-smem sizes (bytes)
constexpr int QK_SMEM   = (64*128 + 64*128 + 128 + 2) * 4;       // 66056
constexpr int CV_SMEM   = (64*32 + 64*256 + 32 + 1) * 4;         // 73860
constexpr int ATTN_SMEM = (8192 + 8192 + 1024 + 32*260 + 32) * 4;// 103040

// =====================================================================
// Kernel 1: fused fqk + tqk pointwise conv + BN + LeakyReLU.
// =====================================================================
__global__ void __launch_bounds__(256) conv_qk_kernel(
    const float* __restrict__ inp,
    const float* __restrict__ W1, const float* __restrict__ b1,
    const float* __restrict__ g1, const float* __restrict__ be1,
    const float* __restrict__ m1, const float* __restrict__ v1,
    const float* __restrict__ a1,
    const float* __restrict__ W2, const float* __restrict__ b2,
    const float* __restrict__ g2, const float* __restrict__ be2,
    const float* __restrict__ m2, const float* __restrict__ v2,
    const float* __restrict__ a2)
{
    extern __shared__ float smqk[];
    float* sW    = smqk;               // [64][128]  sW[k][o]
    float* sIn   = smqk + 64*128;      // [64][128]  sIn[k][p]
    float* sBias = smqk + 2*64*128;    // [128]
    float* sAlpha= sBias + 128;        // [2]

    int tid  = threadIdx.x;
    int b    = blockIdx.y;
    int tile = blockIdx.x;          // 0..511
    int p0   = tile * 128;
    int f    = p0 >> 8;             // T = 256
    int t0   = p0 & 255;

    #pragma unroll 4
    for (int jj = 0; jj < 32; jj++) {
        int idx = tid + jj * 256;
        int k = idx >> 7;
        int o = idx & 127;
        float w;
        if (o < 64) {
            float sc = g1[o] * rsqrtf(v1[o] + EPSc);
            w = W1[o*64 + k] * sc;
        } else {
            int oo = o - 64;
            float sc = g2[oo] * rsqrtf(v2[oo] + EPSc);
            w = W2[oo*64 + k] * sc;
        }
        sW[k*128 + o] = w;
    }
    if (tid < 128) {
        int o = tid;
        float bias;
        if (o < 64) {
            float sc = g1[o] * rsqrtf(v1[o] + EPSc);
            bias = (b1[o] - m1[o]) * sc + be1[o];
        } else {
            int oo = o - 64;
            float sc = g2[oo] * rsqrtf(v2[oo] + EPSc);
            bias = (b2[oo] - m2[oo]) * sc + be2[oo];
        }
        sBias[o] = bias;
    }
    if (tid == 0) { sAlpha[0] = a1[0]; sAlpha[1] = a2[0]; }

    const float* ip = inp + (size_t)b * Cn * Sn + p0;
    #pragma unroll
    for (int jj = 0; jj < 8; jj++) {
        int idx4 = tid + jj * 256;       // 0..2047
        int k  = idx4 >> 5;
        int pq = idx4 & 31;
        float4 val = *(const float4*)(ip + (size_t)k * Sn + pq * 4);
        *(float4*)&sIn[k*128 + pq*4] = val;
    }
    __syncthreads();

    int lane = tid & 31, w = tid >> 5;
    float acc[16][4];
    #pragma unroll
    for (int i = 0; i < 16; i++)
        #pragma unroll
        for (int j = 0; j < 4; j++) acc[i][j] = 0.f;

    #pragma unroll 2
    for (int k = 0; k < 64; k++) {
        float4 A0 = *(const float4*)&sW[k*128 + w*16 + 0];
        float4 A1 = *(const float4*)&sW[k*128 + w*16 + 4];
        float4 A2 = *(const float4*)&sW[k*128 + w*16 + 8];
        float4 A3 = *(const float4*)&sW[k*128 + w*16 + 12];
        float4 Bv = *(const float4*)&sIn[k*128 + lane*4];
        float av[16] = {A0.x,A0.y,A0.z,A0.w, A1.x,A1.y,A1.z,A1.w,
                        A2.x,A2.y,A2.z,A2.w, A3.x,A3.y,A3.z,A3.w};
        float bv[4]  = {Bv.x,Bv.y,Bv.z,Bv.w};
        #pragma unroll
        for (int i = 0; i < 16; i++)
            #pragma unroll
            for (int j = 0; j < 4; j++)
                acc[i][j] = fmaf(av[i], bv[j], acc[i][j]);
    }

    float alpha = (w < 4) ? sAlpha[0] : sAlpha[1];
    #pragma unroll
    for (int i = 0; i < 16; i++) {
        float bias = sBias[w*16 + i];
        #pragma unroll
        for (int j = 0; j < 4; j++) {
            float y = acc[i][j] + bias;
            acc[i][j] = (y > 0.f) ? y : alpha * y;
        }
    }

    int t = t0 + lane * 4;
    if (w < 4) {
        // fqk: channel o=2c+s -> q (s=0), k (s=1)
        int cb = w * 8;
        #pragma unroll
        for (int j = 0; j < 4; j++) {
            size_t off = (((size_t)b*Tn + (t+j))*Fn + f)*CHn + cb;
            *(float4*)(g_qf+off)   = make_float4(acc[0][j],acc[2][j],acc[4][j],acc[6][j]);
            *(float4*)(g_qf+off+4) = make_float4(acc[8][j],acc[10][j],acc[12][j],acc[14][j]);
            *(float4*)(g_kf+off)   = make_float4(acc[1][j],acc[3][j],acc[5][j],acc[7][j]);
            *(float4*)(g_kf+off+4) = make_float4(acc[9][j],acc[11][j],acc[13][j],acc[15][j]);
        }
    } else {
        int cb = (w - 4) * 8;
        #pragma unroll
        for (int j = 0; j < 4; j++) {
            size_t off = (((size_t)b*Fn + f)*Tn + (t+j))*CHn + cb;
            *(float4*)(g_qt+off)   = make_float4(acc[0][j],acc[2][j],acc[4][j],acc[6][j]);
            *(float4*)(g_qt+off+4) = make_float4(acc[8][j],acc[10][j],acc[12][j],acc[14][j]);
            *(float4*)(g_kt+off)   = make_float4(acc[1][j],acc[3][j],acc[5][j],acc[7][j]);
            *(float4*)(g_kt+off+4) = make_float4(acc[9][j],acc[11][j],acc[13][j],acc[15][j]);
        }
    }
}

// =====================================================================
// Kernel 2: fv conv (64 -> 32) + BN + LeakyReLU, writes v_f[b,t,f,c].
// =====================================================================
__global__ void __launch_bounds__(256) conv_v_kernel(
    const float* __restrict__ xin,
    const float* __restrict__ W,  const float* __restrict__ bb,
    const float* __restrict__ gg, const float* __restrict__ be,
    const float* __restrict__ mm, const float* __restrict__ vv,
    const float* __restrict__ aa)
{
    extern __shared__ float smcv[];
    float* sW    = smcv;              // [64][32]
    float* sIn   = smcv + 64*32;      // [64][256]
    float* sBias = sIn + 64*256;      // [32]
    float* sAlpha= sBias + 32;        // [1]

    int tid = threadIdx.x;
    int f = blockIdx.x, b = blockIdx.y;

    for (int idx = tid; idx < 2048; idx += 256) {
        int k = idx >> 5, o = idx & 31;
        float sc = gg[o] * rsqrtf(vv[o] + EPSc);
        sW[k*32 + o] = W[o*64 + k] * sc;
    }
    if (tid < 32) {
        float sc = gg[tid] * rsqrtf(vv[tid] + EPSc);
        sBias[tid] = (bb[tid] - mm[tid]) * sc + be[tid];
    }
    if (tid == 0) sAlpha[0] = aa[0];

    const float* ip = xin + (size_t)b*Cn*Sn + (size_t)f*Tn;
    #pragma unroll
    for (int jj = 0; jj < 16; jj++) {
        int idx4 = tid + jj*256;          // 0..4095
        int k = idx4 >> 6, pq = idx4 & 63;
        *(float4*)&sIn[k*256 + pq*4] = *(const float4*)(ip + (size_t)k*Sn + pq*4);
    }
    __syncthreads();

    int lane = tid & 31, w = tid >> 5;
    int cg = w & 3, ph = w >> 2;          // channels cg*8.., positions ph*128..
    float acc[8][4];
    #pragma unroll
    for (int i = 0; i < 8; i++)
        #pragma unroll
        for (int j = 0; j < 4; j++) acc[i][j] = 0.f;

    #pragma unroll 2
    for (int k = 0; k < 64; k++) {
        float4 A0 = *(const float4*)&sW[k*32 + cg*8];
        float4 A1 = *(const float4*)&sW[k*32 + cg*8 + 4];
        float4 Bv = *(const float4*)&sIn[k*256 + ph*128 + lane*4];
        float av[8] = {A0.x,A0.y,A0.z,A0.w, A1.x,A1.y,A1.z,A1.w};
        float bv[4] = {Bv.x,Bv.y,Bv.z,Bv.w};
        #pragma unroll
        for (int i = 0; i < 8; i++)
            #pragma unroll
            for (int j = 0; j < 4; j++)
                acc[i][j] = fmaf(av[i], bv[j], acc[i][j]);
    }

    float alpha = sAlpha[0];
    int c = cg * 8;
    #pragma unroll
    for (int j = 0; j < 4; j++) {
        int t = ph*128 + lane*4 + j;
        float r[8];
        #pragma unroll
        for (int i = 0; i < 8; i++) {
            float y = acc[i][j] + sBias[c + i];
            r[i] = (y > 0.f) ? y : alpha * y;
        }
        size_t off = (((size_t)b*Tn + t)*Fn + f)*CHn + c;
        *(float4*)(g_vf + off)     = make_float4(r[0],r[1],r[2],r[3]);
        *(float4*)(g_vf + off + 4) = make_float4(r[4],r[5],r[6],r[7]);
    }
}

// =====================================================================
// Attention kernel. q/k/v/out arrays selected INSIDE device code via the
// CAUSAL template parameter (never pass __device__ symbols from host).
// =====================================================================
template<bool CAUSAL>
__global__ void __launch_bounds__(256) attn_kernel()
{
    const float* __restrict__ qg = CAUSAL ? g_qt : g_qf;
    const float* __restrict__ kg = CAUSAL ? g_kt : g_kf;
    const float* __restrict__ vg = CAUSAL ? g_fout : g_vf;
    float* __restrict__ outg     = CAUSAL ? g_tout : g_fout;

    extern __shared__ float sm[];
    float* sK   = sm;                 // [32][256]  transposed K: sK[c][y]
    float* sV   = sm + 8192;          // [256][32]  V[y][c]
    float* sQ   = sm + 16384;         // [32][32]   transposed Q chunk
    float* sS   = sm + 17408;         // [32][260]  scores (padded pitch)
    float* sInv = sS + 32*260;        // [32]

    int tid = threadIdx.x, lane = tid & 31, w = tid >> 5;
    int col = blockIdx.x;             // t for F-attn, f for T-attn
    int b   = blockIdx.y;
    size_t base = ((size_t)b * 256 + col) * 256 * CHn;
    const float* qp = qg + base;
    const float* kp = kg + base;
    const float* vp = vg + base;
    size_t out_base, out_stride;
    if (CAUSAL) { out_base = base; out_stride = CHn; }
    else { out_base = ((size_t)b * Sn + col) * CHn; out_stride = (size_t)Tn * CHn; }

    // Load K (transposed) and V
    #pragma unroll
    for (int jj = 0; jj < 8; jj++) {
        int idx4 = tid + jj*256;          // 0..2047
        int y = idx4 >> 3, cq = idx4 & 7;
        float4 kv = ((const float4*)kp)[idx4];
        sK[(cq*4+0)*256 + y] = kv.x;
        sK[(cq*4+1)*256 + y] = kv.y;
        sK[(cq*4+2)*256 + y] = kv.z;
        sK[(cq*4+3)*256 + y] = kv.w;
        ((float4*)sV)[idx4] = ((const float4*)vp)[idx4];
    }

    const float scale = 0.17677669529663687f;  // 1/sqrt(32)

    for (int ch = 0; ch < 8; ch++) {
        int r0 = ch * 32;
        // load Q chunk transposed
        {
            int fi = tid >> 3, cq = tid & 7;
            float4 qv = *(const float4*)(qp + (size_t)(r0 + fi)*CHn + cq*4);
            sQ[(cq*4+0)*32 + fi] = qv.x;
            sQ[(cq*4+1)*32 + fi] = qv.y;
            sQ[(cq*4+2)*32 + fi] = qv.z;
            sQ[(cq*4+3)*32 + fi] = qv.w;
        }
        __syncthreads();

        // ---- score GEMM: warp w -> rows w*4..w*4+3, lane -> cols lane*8..+7
        float acc[4][8];
        #pragma unroll
        for (int i = 0; i < 4; i++)
            #pragma unroll
            for (int j = 0; j < 8; j++) acc[i][j] = 0.f;

        #pragma unroll 4
        for (int c = 0; c < 32; c++) {
            float4 A  = *(const float4*)&sQ[c*32 + w*4];
            float4 B0 = *(const float4*)&sK[c*256 + lane*8];
            float4 B1 = *(const float4*)&sK[c*256 + lane*8 + 4];
            float av[4] = {A.x,A.y,A.z,A.w};
            float bv[8] = {B0.x,B0.y,B0.z,B0.w, B1.x,B1.y,B1.z,B1.w};
            #pragma unroll
            for (int i = 0; i < 4; i++)
                #pragma unroll
                for (int j = 0; j < 8; j++)
                    acc[i][j] = fmaf(av[i], bv[j], acc[i][j]);
        }
        #pragma unroll
        for (int i = 0; i < 4; i++) {
            int r = w*4 + i;
            *(float4*)&sS[r*260 + lane*8] =
                make_float4(acc[i][0]*scale, acc[i][1]*scale, acc[i][2]*scale, acc[i][3]*scale);
            *(float4*)&sS[r*260 + lane*8 + 4] =
                make_float4(acc[i][4]*scale, acc[i][5]*scale, acc[i][6]*scale, acc[i][7]*scale);
        }
        __syncthreads();

        // ---- softmax: warp w handles rows w*4..w*4+3
        #pragma unroll
        for (int i = 0; i < 4; i++) {
            int r = w*4 + i;
            int tg = r0 + r;               // causal limit
            float vals[8]; float mx = -1e30f;
            #pragma unroll
            for (int u = 0; u < 8; u++) {
                int y = lane + u*32;
                float s = sS[r*260 + y];
                if (CAUSAL && y > tg) s = -1e30f;
                vals[u] = s;
                mx = fmaxf(mx, s);
            }
            #pragma unroll
            for (int off = 16; off > 0; off >>= 1)
                mx = fmaxf(mx, __shfl_xor_sync(0xffffffffu, mx, off));
            float sum = 0.f;
            #pragma unroll
            for (int u = 0; u < 8; u++) {
                int y = lane + u*32;
                float e = (CAUSAL && y > tg) ? 0.f : __expf(vals[u] - mx);
                sum += e;
                sS[r*260 + y] = e;
            }
            #pragma unroll
            for (int off = 16; off > 0; off >>= 1)
                sum += __shfl_xor_sync(0xffffffffu, sum, off);
            if (lane == 0) sInv[r] = 1.f / sum;
        }
        __syncthreads();

        // ---- PV: thread -> (row fi, channels cg*4..cg*4+3)
        {
            int fi = tid >> 3, cg = tid & 7;
            float ox = 0.f, oy = 0.f, oz = 0.f, ow = 0.f;
            const float* srow = &sS[fi*260];
            int yend = CAUSAL ? (r0 + 32) : 256;
            #pragma unroll 2
            for (int y = 0; y < yend; y += 4) {
                float4 p4 = *(const float4*)&srow[y];
                float4 v0 = *(const float4*)&sV[(y+0)*32 + cg*4];
                float4 v1 = *(const float4*)&sV[(y+1)*32 + cg*4];
                float4 v2 = *(const float4*)&sV[(y+2)*32 + cg*4];
                float4 v3 = *(const float4*)&sV[(y+3)*32 + cg*4];
                ox = fmaf(p4.x, v0.x, ox); oy = fmaf(p4.x, v0.y, oy);
                oz = fmaf(p4.x, v0.z, oz); ow = fmaf(p4.x, v0.w, ow);
                ox = fmaf(p4.y, v1.x, ox); oy = fmaf(p4.y, v1.y, oy);
                oz = fmaf(p4.y, v1.z, oz); ow = fmaf(p4.y, v1.w, ow);
                ox = fmaf(p4.z, v2.x, ox); oy = fmaf(p4.z, v2.y, oy);
                oz = fmaf(p4.z, v2.z, oz); ow = fmaf(p4.z, v2.w, ow);
                ox = fmaf(p4.w, v3.x, ox); oy = fmaf(p4.w, v3.y, oy);
                oz = fmaf(p4.w, v3.z, oz); ow = fmaf(p4.w, v3.w, ow);
            }
            float inv = sInv[fi];
            *(float4*)(outg + out_base + (size_t)(r0 + fi)*out_stride + cg*4) =
                make_float4(ox*inv, oy*inv, oz*inv, ow*inv);
        }
        __syncthreads();
    }
}

// =====================================================================
// Kernel 5: proj conv (32 -> 64) + BN + LeakyReLU + residual -> d_out.
// =====================================================================
__global__ void __launch_bounds__(256) proj_kernel(
    const float* __restrict__ xin,
    const float* __restrict__ W,  const float* __restrict__ bb,
    const float* __restrict__ gg, const float* __restrict__ be,
    const float* __restrict__ mm, const float* __restrict__ vv,
    const float* __restrict__ aa,
    float* __restrict__ outp)
{
    __shared__ float sW[32][64];      // sW[k][o]
    __shared__ float sIn[32][132];    // transposed tout chunk, padded pitch
    __shared__ float sBias[64];
    __shared__ float sAlpha;

    int tid = threadIdx.x;
    int tile = blockIdx.x, b = blockIdx.y;
    int p0 = tile * 128;

    for (int idx = tid; idx < 2048; idx += 256) {
        int o = idx & 63, k = idx >> 6;
        float sc = gg[o] * rsqrtf(vv[o] + EPSc);
        sW[k][o] = W[o*32 + k] * sc;
    }
    if (tid < 64) {
        float sc = gg[tid] * rsqrtf(vv[tid] + EPSc);
        sBias[tid] = (bb[tid] - mm[tid]) * sc + be[tid];
    }
    if (tid == 0) sAlpha = aa[0];

    const float* tp = g_tout + ((size_t)b*Sn + p0) * CHn;
    #pragma unroll
    for (int jj = 0; jj < 4; jj++) {
        int idx4 = tid + jj*256;          // 0..1023
        int p = idx4 >> 3, cq = idx4 & 7;
        float4 tv = ((const float4*)tp)[idx4];
        sIn[cq*4+0][p] = tv.x;
        sIn[cq*4+1][p] = tv.y;
        sIn[cq*4+2][p] = tv.z;
        sIn[cq*4+3][p] = tv.w;
    }
    __syncthreads();

    int lane = tid & 31, w = tid >> 5;   // warp w -> out channels w*8..+7
    float acc[8][4];
    #pragma unroll
    for (int i = 0; i < 8; i++)
        #pragma unroll
        for (int j = 0; j < 4; j++) acc[i][j] = 0.f;

    #pragma unroll 2
    for (int k = 0; k < 32; k++) {
        float4 A0 = *(const float4*)&sW[k][w*8];
        float4 A1 = *(const float4*)&sW[k][w*8 + 4];
        float4 Bv = *(const float4*)&sIn[k][lane*4];
        float av[8] = {A0.x,A0.y,A0.z,A0.w, A1.x,A1.y,A1.z,A1.w};
        float bv[4] = {Bv.x,Bv.y,Bv.z,Bv.w};
        #pragma unroll
        for (int i = 0; i < 8; i++)
            #pragma unroll
            for (int j = 0; j < 4; j++)
                acc[i][j] = fmaf(av[i], bv[j], acc[i][j]);
    }

    float alpha = sAlpha;
    const float* xb = xin + (size_t)b*Cn*Sn + p0 + lane*4;
    float*       ob = outp + (size_t)b*Cn*Sn + p0 + lane*4;
    #pragma unroll
    for (int i = 0; i < 8; i++) {
        int o = w*8 + i;
        float bias = sBias[o];
        float4 xr = *(const float4*)(xb + (size_t)o*Sn);
        float r0 = acc[i][0] + bias; r0 = (r0 > 0.f) ? r0 : alpha*r0; r0 += xr.x;
        float r1 = acc[i][1] + bias; r1 = (r1 > 0.f) ? r1 : alpha*r1; r1 += xr.y;
        float r2 = acc[i][2] + bias; r2 = (r2 > 0.f) ? r2 : alpha*r2; r2 += xr.z;
        float r3 = acc[i][3] + bias; r3 = (r3 > 0.f) ? r3 : alpha*r3; r3 += xr.w;
        *(float4*)(ob + (size_t)o*Sn) = make_float4(r0, r1, r2, r3);
    }
}

// =====================================================================
// Launch
// =====================================================================
extern "C" void kernel_launch(void* const* d_in, const int* in_sizes, int n_in,
                              void* d_out, int out_size) {
    const float* inp  = (const float*)d_in[0];
    const float* x    = (const float*)d_in[1];
    const float* fqkW = (const float*)d_in[2];
    const float* fqkb = (const float*)d_in[3];
    const float* fqkg = (const float*)d_in[4];
    const float* fqkbe= (const float*)d_in[5];
    const float* fqkm = (const float*)d_in[6];
    const float* fqkv = (const float*)d_in[7];
    const float* fqka = (const float*)d_in[8];
    const float* fvW  = (const float*)d_in[9];
    const float* fvb  = (const float*)d_in[10];
    const float* fvg  = (const float*)d_in[11];
    const float* fvbe = (const float*)d_in[12];
    const float* fvm  = (const float*)d_in[13];
    const float* fvv  = (const float*)d_in[14];
    const float* fva  = (const float*)d_in[15];
    const float* tqkW = (const float*)d_in[16];
    const float* tqkb = (const float*)d_in[17];
    const float* tqkg = (const float*)d_in[18];
    const float* tqkbe= (const float*)d_in[19];
    const float* tqkm = (const float*)d_in[20];
    const float* tqkv = (const float*)d_in[21];
    const float* tqka = (const float*)d_in[22];
    const float* prW  = (const float*)d_in[23];
    const float* prb  = (const float*)d_in[24];
    const float* prg  = (const float*)d_in[25];
    const float* prbe = (const float*)d_in[26];
    const float* prm  = (const float*)d_in[27];
    const float* prv  = (const float*)d_in[28];
    const float* pra  = (const float*)d_in[29];
    float* out = (float*)d_out;

    cudaFuncSetAttribute(conv_qk_kernel,
                         cudaFuncAttributeMaxDynamicSharedMemorySize, QK_SMEM);
    cudaFuncSetAttribute(conv_v_kernel,
                         cudaFuncAttributeMaxDynamicSharedMemorySize, CV_SMEM);
    cudaFuncSetAttribute(attn_kernel<false>,
                         cudaFuncAttributeMaxDynamicSharedMemorySize, ATTN_SMEM);
    cudaFuncSetAttribute(attn_kernel<true>,
                         cudaFuncAttributeMaxDynamicSharedMemorySize, ATTN_SMEM);

    conv_qk_kernel<<<dim3(512, Bn), 256, QK_SMEM>>>(inp,
        fqkW, fqkb, fqkg, fqkbe, fqkm, fqkv, fqka,
        tqkW, tqkb, tqkg, tqkbe, tqkm, tqkv, tqka);

    conv_v_kernel<<<dim3(256, Bn), 256, CV_SMEM>>>(x,
        fvW, fvb, fvg, fvbe, fvm, fvv, fva);

    attn_kernel<false><<<dim3(256, Bn), 256, ATTN_SMEM>>>();

    attn_kernel<true><<<dim3(256, Bn), 256, ATTN_SMEM>>>();

    proj_kernel<<<dim3(512, Bn), 256>>>(x,
        prW, prb, prg, prbe, prm, prv, pra, out);
}

// round 6
// speedup vs baseline: 1.0989x; 1.0989x over previous
#include <cuda_runtime.h>
#include <cstdint>

// Problem constants
constexpr int Bn  = 4;
constexpr int Cn  = 64;
constexpr int CHn = 32;
constexpr int Fn  = 256;
constexpr int Tn  = 256;
constexpr int Sn  = Fn * Tn;          // 65536 spatial positions
constexpr float EPSc = 1e-5f;

// -------- device scratch --------
__device__ float g_qf[Bn*Tn*Fn*CHn];
__device__ float g_kf[Bn*Tn*Fn*CHn];
__device__ float g_vf[Bn*Tn*Fn*CHn];
__device__ float g_qt[Bn*Fn*Tn*CHn];
__device__ float g_kt[Bn*Fn*Tn*CHn];
__device__ float g_fout[Bn*Fn*Tn*CHn];
__device__ float g_tout[Bn*Fn*Tn*CHn];

// dynamic-smem sizes (bytes)
constexpr int QK_SMEM   = (64*128 + 64*128 + 128 + 2) * 4;       // 66056
constexpr int CV_SMEM   = (64*32 + 64*256 + 32 + 1) * 4;         // 73860
constexpr int ATTN_SMEM = (8192 + 8192 + 1024 + 32*260 + 32) * 4;// 103040

// =====================================================================
// Kernel 1: fused fqk + tqk pointwise conv + BN + LeakyReLU. (unchanged)
// =====================================================================
__global__ void __launch_bounds__(256) conv_qk_kernel(
    const float* __restrict__ inp,
    const float* __restrict__ W1, const float* __restrict__ b1,
    const float* __restrict__ g1, const float* __restrict__ be1,
    const float* __restrict__ m1, const float* __restrict__ v1,
    const float* __restrict__ a1,
    const float* __restrict__ W2, const float* __restrict__ b2,
    const float* __restrict__ g2, const float* __restrict__ be2,
    const float* __restrict__ m2, const float* __restrict__ v2,
    const float* __restrict__ a2)
{
    extern __shared__ float smqk[];
    float* sW    = smqk;               // [64][128]
    float* sIn   = smqk + 64*128;      // [64][128]
    float* sBias = smqk + 2*64*128;    // [128]
    float* sAlpha= sBias + 128;        // [2]

    int tid  = threadIdx.x;
    int b    = blockIdx.y;
    int tile = blockIdx.x;
    int p0   = tile * 128;
    int f    = p0 >> 8;
    int t0   = p0 & 255;

    #pragma unroll 4
    for (int jj = 0; jj < 32; jj++) {
        int idx = tid + jj * 256;
        int k = idx >> 7;
        int o = idx & 127;
        float w;
        if (o < 64) {
            float sc = g1[o] * rsqrtf(v1[o] + EPSc);
            w = W1[o*64 + k] * sc;
        } else {
            int oo = o - 64;
            float sc = g2[oo] * rsqrtf(v2[oo] + EPSc);
            w = W2[oo*64 + k] * sc;
        }
        sW[k*128 + o] = w;
    }
    if (tid < 128) {
        int o = tid;
        float bias;
        if (o < 64) {
            float sc = g1[o] * rsqrtf(v1[o] + EPSc);
            bias = (b1[o] - m1[o]) * sc + be1[o];
        } else {
            int oo = o - 64;
            float sc = g2[oo] * rsqrtf(v2[oo] + EPSc);
            bias = (b2[oo] - m2[oo]) * sc + be2[oo];
        }
        sBias[o] = bias;
    }
    if (tid == 0) { sAlpha[0] = a1[0]; sAlpha[1] = a2[0]; }

    const float* ip = inp + (size_t)b * Cn * Sn + p0;
    #pragma unroll
    for (int jj = 0; jj < 8; jj++) {
        int idx4 = tid + jj * 256;
        int k  = idx4 >> 5;
        int pq = idx4 & 31;
        float4 val = *(const float4*)(ip + (size_t)k * Sn + pq * 4);
        *(float4*)&sIn[k*128 + pq*4] = val;
    }
    __syncthreads();

    int lane = tid & 31, w = tid >> 5;
    float acc[16][4];
    #pragma unroll
    for (int i = 0; i < 16; i++)
        #pragma unroll
        for (int j = 0; j < 4; j++) acc[i][j] = 0.f;

    #pragma unroll 2
    for (int k = 0; k < 64; k++) {
        float4 A0 = *(const float4*)&sW[k*128 + w*16 + 0];
        float4 A1 = *(const float4*)&sW[k*128 + w*16 + 4];
        float4 A2 = *(const float4*)&sW[k*128 + w*16 + 8];
        float4 A3 = *(const float4*)&sW[k*128 + w*16 + 12];
        float4 Bv = *(const float4*)&sIn[k*128 + lane*4];
        float av[16] = {A0.x,A0.y,A0.z,A0.w, A1.x,A1.y,A1.z,A1.w,
                        A2.x,A2.y,A2.z,A2.w, A3.x,A3.y,A3.z,A3.w};
        float bv[4]  = {Bv.x,Bv.y,Bv.z,Bv.w};
        #pragma unroll
        for (int i = 0; i < 16; i++)
            #pragma unroll
            for (int j = 0; j < 4; j++)
                acc[i][j] = fmaf(av[i], bv[j], acc[i][j]);
    }

    float alpha = (w < 4) ? sAlpha[0] : sAlpha[1];
    #pragma unroll
    for (int i = 0; i < 16; i++) {
        float bias = sBias[w*16 + i];
        #pragma unroll
        for (int j = 0; j < 4; j++) {
            float y = acc[i][j] + bias;
            acc[i][j] = (y > 0.f) ? y : alpha * y;
        }
    }

    int t = t0 + lane * 4;
    if (w < 4) {
        int cb = w * 8;
        #pragma unroll
        for (int j = 0; j < 4; j++) {
            size_t off = (((size_t)b*Tn + (t+j))*Fn + f)*CHn + cb;
            *(float4*)(g_qf+off)   = make_float4(acc[0][j],acc[2][j],acc[4][j],acc[6][j]);
            *(float4*)(g_qf+off+4) = make_float4(acc[8][j],acc[10][j],acc[12][j],acc[14][j]);
            *(float4*)(g_kf+off)   = make_float4(acc[1][j],acc[3][j],acc[5][j],acc[7][j]);
            *(float4*)(g_kf+off+4) = make_float4(acc[9][j],acc[11][j],acc[13][j],acc[15][j]);
        }
    } else {
        int cb = (w - 4) * 8;
        #pragma unroll
        for (int j = 0; j < 4; j++) {
            size_t off = (((size_t)b*Fn + f)*Tn + (t+j))*CHn + cb;
            *(float4*)(g_qt+off)   = make_float4(acc[0][j],acc[2][j],acc[4][j],acc[6][j]);
            *(float4*)(g_qt+off+4) = make_float4(acc[8][j],acc[10][j],acc[12][j],acc[14][j]);
            *(float4*)(g_kt+off)   = make_float4(acc[1][j],acc[3][j],acc[5][j],acc[7][j]);
            *(float4*)(g_kt+off+4) = make_float4(acc[9][j],acc[11][j],acc[13][j],acc[15][j]);
        }
    }
}

// =====================================================================
// Kernel 2: fv conv (64 -> 32) + BN + LeakyReLU. (unchanged)
// =====================================================================
__global__ void __launch_bounds__(256) conv_v_kernel(
    const float* __restrict__ xin,
    const float* __restrict__ W,  const float* __restrict__ bb,
    const float* __restrict__ gg, const float* __restrict__ be,
    const float* __restrict__ mm, const float* __restrict__ vv,
    const float* __restrict__ aa)
{
    extern __shared__ float smcv[];
    float* sW    = smcv;              // [64][32]
    float* sIn   = smcv + 64*32;      // [64][256]
    float* sBias = sIn + 64*256;      // [32]
    float* sAlpha= sBias + 32;        // [1]

    int tid = threadIdx.x;
    int f = blockIdx.x, b = blockIdx.y;

    for (int idx = tid; idx < 2048; idx += 256) {
        int k = idx >> 5, o = idx & 31;
        float sc = gg[o] * rsqrtf(vv[o] + EPSc);
        sW[k*32 + o] = W[o*64 + k] * sc;
    }
    if (tid < 32) {
        float sc = gg[tid] * rsqrtf(vv[tid] + EPSc);
        sBias[tid] = (bb[tid] - mm[tid]) * sc + be[tid];
    }
    if (tid == 0) sAlpha[0] = aa[0];

    const float* ip = xin + (size_t)b*Cn*Sn + (size_t)f*Tn;
    #pragma unroll
    for (int jj = 0; jj < 16; jj++) {
        int idx4 = tid + jj*256;
        int k = idx4 >> 6, pq = idx4 & 63;
        *(float4*)&sIn[k*256 + pq*4] = *(const float4*)(ip + (size_t)k*Sn + pq*4);
    }
    __syncthreads();

    int lane = tid & 31, w = tid >> 5;
    int cg = w & 3, ph = w >> 2;
    float acc[8][4];
    #pragma unroll
    for (int i = 0; i < 8; i++)
        #pragma unroll
        for (int j = 0; j < 4; j++) acc[i][j] = 0.f;

    #pragma unroll 2
    for (int k = 0; k < 64; k++) {
        float4 A0 = *(const float4*)&sW[k*32 + cg*8];
        float4 A1 = *(const float4*)&sW[k*32 + cg*8 + 4];
        float4 Bv = *(const float4*)&sIn[k*256 + ph*128 + lane*4];
        float av[8] = {A0.x,A0.y,A0.z,A0.w, A1.x,A1.y,A1.z,A1.w};
        float bv[4] = {Bv.x,Bv.y,Bv.z,Bv.w};
        #pragma unroll
        for (int i = 0; i < 8; i++)
            #pragma unroll
            for (int j = 0; j < 4; j++)
                acc[i][j] = fmaf(av[i], bv[j], acc[i][j]);
    }

    float alpha = sAlpha[0];
    int c = cg * 8;
    #pragma unroll
    for (int j = 0; j < 4; j++) {
        int t = ph*128 + lane*4 + j;
        float r[8];
        #pragma unroll
        for (int i = 0; i < 8; i++) {
            float y = acc[i][j] + sBias[c + i];
            r[i] = (y > 0.f) ? y : alpha * y;
        }
        size_t off = (((size_t)b*Tn + t)*Fn + f)*CHn + c;
        *(float4*)(g_vf + off)     = make_float4(r[0],r[1],r[2],r[3]);
        *(float4*)(g_vf + off + 4) = make_float4(r[4],r[5],r[6],r[7]);
    }
}

// =====================================================================
// Attention kernel — REWORKED:
//  * score GEMM in 64-col quarters, lane covers 2 consecutive cols
//    (float2 B loads: 2 wavefronts/instr instead of 8)
//  * softmax entirely in registers (S never staged raw; P written once)
//  * causal: skip quarters beyond the mask (qmax), PV bounded at r0+32
// =====================================================================
template<bool CAUSAL>
__global__ void __launch_bounds__(256, 2) attn_kernel()
{
    const float* __restrict__ qg = CAUSAL ? g_qt : g_qf;
    const float* __restrict__ kg = CAUSAL ? g_kt : g_kf;
    const float* __restrict__ vg = CAUSAL ? g_fout : g_vf;
    float* __restrict__ outg     = CAUSAL ? g_tout : g_fout;

    extern __shared__ float sm[];
    float* sK   = sm;                 // [32][256]  K^T: sK[c][y]
    float* sV   = sm + 8192;          // [256][32]  V[y][c]
    float* sQT  = sm + 16384;         // [32][32]   Q chunk transposed
    float* sS   = sm + 17408;         // [32][260]  probabilities (padded)
    float* sInv = sS + 32*260;        // [32]

    int tid = threadIdx.x, lane = tid & 31, w = tid >> 5;
    int col = blockIdx.x;
    int b   = blockIdx.y;
    size_t base = ((size_t)b * 256 + col) * 256 * CHn;
    const float* qp = qg + base;
    const float* kp = kg + base;
    const float* vp = vg + base;
    size_t out_base, out_stride;
    if (CAUSAL) { out_base = base; out_stride = CHn; }
    else { out_base = ((size_t)b * Sn + col) * CHn; out_stride = (size_t)Tn * CHn; }

    // Load K (transposed) and V
    #pragma unroll
    for (int jj = 0; jj < 8; jj++) {
        int idx4 = tid + jj*256;          // 0..2047
        int y = idx4 >> 3, cq = idx4 & 7;
        float4 kv = ((const float4*)kp)[idx4];
        sK[(cq*4+0)*256 + y] = kv.x;
        sK[(cq*4+1)*256 + y] = kv.y;
        sK[(cq*4+2)*256 + y] = kv.z;
        sK[(cq*4+3)*256 + y] = kv.w;
        ((float4*)sV)[idx4] = ((const float4*)vp)[idx4];
    }

    const float scale = 0.17677669529663687f;  // 1/sqrt(32)

    for (int ch = 0; ch < 8; ch++) {
        int r0 = ch * 32;

        // load Q chunk transposed: sQT[c][fi]
        {
            int fi = tid >> 3, cq = tid & 7;
            float4 qv = *(const float4*)(qp + (size_t)(r0 + fi)*CHn + cq*4);
            sQT[(cq*4+0)*32 + fi] = qv.x;
            sQT[(cq*4+1)*32 + fi] = qv.y;
            sQT[(cq*4+2)*32 + fi] = qv.z;
            sQT[(cq*4+3)*32 + fi] = qv.w;
        }
        __syncthreads();

        // number of 64-col quarters needed (causal: cols <= r0+31 suffice)
        const int qmax = CAUSAL ? ((r0 + 95) >> 6) : 4;

        // ---- score GEMM: warp w -> rows w*4..w*4+3,
        //      quarter q -> cols q*64 + lane*2 + {0,1}
        float acc[4][8];   // [row i][q*2 + v]
        #pragma unroll
        for (int i = 0; i < 4; i++)
            #pragma unroll
            for (int j = 0; j < 8; j++) acc[i][j] = 0.f;

        for (int q = 0; q < qmax; q++) {
            const float* kq = &sK[q*64 + lane*2];
            #pragma unroll 8
            for (int c = 0; c < 32; c++) {
                float4 A  = *(const float4*)&sQT[c*32 + w*4];
                float2 Bv = *(const float2*)&kq[c*256];
                acc[0][q*2+0] = fmaf(A.x, Bv.x, acc[0][q*2+0]);
                acc[0][q*2+1] = fmaf(A.x, Bv.y, acc[0][q*2+1]);
                acc[1][q*2+0] = fmaf(A.y, Bv.x, acc[1][q*2+0]);
                acc[1][q*2+1] = fmaf(A.y, Bv.y, acc[1][q*2+1]);
                acc[2][q*2+0] = fmaf(A.z, Bv.x, acc[2][q*2+0]);
                acc[2][q*2+1] = fmaf(A.z, Bv.y, acc[2][q*2+1]);
                acc[3][q*2+0] = fmaf(A.w, Bv.x, acc[3][q*2+0]);
                acc[3][q*2+1] = fmaf(A.w, Bv.y, acc[3][q*2+1]);
            }
        }

        // ---- register softmax per row (max/sum via shuffles)
        #pragma unroll
        for (int i = 0; i < 4; i++) {
            int r  = w*4 + i;
            int tg = r0 + r;
            float mx = -1e30f;
            #pragma unroll
            for (int q = 0; q < 4; q++) {
                if (q < qmax) {
                    #pragma unroll
                    for (int v = 0; v < 2; v++) {
                        int y = q*64 + lane*2 + v;
                        float s = acc[i][q*2+v] * scale;
                        if (CAUSAL && y > tg) s = -1e30f;
                        acc[i][q*2+v] = s;
                        mx = fmaxf(mx, s);
                    }
                }
            }
            #pragma unroll
            for (int off = 16; off > 0; off >>= 1)
                mx = fmaxf(mx, __shfl_xor_sync(0xffffffffu, mx, off));

            float sum = 0.f;
            #pragma unroll
            for (int q = 0; q < 4; q++) {
                if (q < qmax) {
                    float e0 = __expf(acc[i][q*2+0] - mx);
                    float e1 = __expf(acc[i][q*2+1] - mx);
                    sum += e0 + e1;
                    *(float2*)&sS[r*260 + q*64 + lane*2] = make_float2(e0, e1);
                }
            }
            #pragma unroll
            for (int off = 16; off > 0; off >>= 1)
                sum += __shfl_xor_sync(0xffffffffu, sum, off);
            if (lane == 0) sInv[r] = 1.f / sum;
        }
        __syncthreads();

        // ---- PV: thread -> (row fi, channels cg*4..cg*4+3)
        {
            int fi = tid >> 3, cg = tid & 7;
            float ox = 0.f, oy = 0.f, oz = 0.f, ow = 0.f;
            const float* srow = &sS[fi*260];
            int yend = CAUSAL ? (r0 + 32) : 256;
            #pragma unroll 2
            for (int y = 0; y < yend; y += 4) {
                float4 p4 = *(const float4*)&srow[y];
                float4 v0 = *(const float4*)&sV[(y+0)*32 + cg*4];
                float4 v1 = *(const float4*)&sV[(y+1)*32 + cg*4];
                float4 v2 = *(const float4*)&sV[(y+2)*32 + cg*4];
                float4 v3 = *(const float4*)&sV[(y+3)*32 + cg*4];
                ox = fmaf(p4.x, v0.x, ox); oy = fmaf(p4.x, v0.y, oy);
                oz = fmaf(p4.x, v0.z, oz); ow = fmaf(p4.x, v0.w, ow);
                ox = fmaf(p4.y, v1.x, ox); oy = fmaf(p4.y, v1.y, oy);
                oz = fmaf(p4.y, v1.z, oz); ow = fmaf(p4.y, v1.w, ow);
                ox = fmaf(p4.z, v2.x, ox); oy = fmaf(p4.z, v2.y, oy);
                oz = fmaf(p4.z, v2.z, oz); ow = fmaf(p4.z, v2.w, ow);
                ox = fmaf(p4.w, v3.x, ox); oy = fmaf(p4.w, v3.y, oy);
                oz = fmaf(p4.w, v3.z, oz); ow = fmaf(p4.w, v3.w, ow);
            }
            float inv = sInv[fi];
            *(float4*)(outg + out_base + (size_t)(r0 + fi)*out_stride + cg*4) =
                make_float4(ox*inv, oy*inv, oz*inv, ow*inv);
        }
        __syncthreads();
    }
}

// =====================================================================
// Kernel 5: proj conv (32 -> 64) + BN + LeakyReLU + residual. (unchanged)
// =====================================================================
__global__ void __launch_bounds__(256) proj_kernel(
    const float* __restrict__ xin,
    const float* __restrict__ W,  const float* __restrict__ bb,
    const float* __restrict__ gg, const float* __restrict__ be,
    const float* __restrict__ mm, const float* __restrict__ vv,
    const float* __restrict__ aa,
    float* __restrict__ outp)
{
    __shared__ float sW[32][64];
    __shared__ float sIn[32][132];
    __shared__ float sBias[64];
    __shared__ float sAlpha;

    int tid = threadIdx.x;
    int tile = blockIdx.x, b = blockIdx.y;
    int p0 = tile * 128;

    for (int idx = tid; idx < 2048; idx += 256) {
        int o = idx & 63, k = idx >> 6;
        float sc = gg[o] * rsqrtf(vv[o] + EPSc);
        sW[k][o] = W[o*32 + k] * sc;
    }
    if (tid < 64) {
        float sc = gg[tid] * rsqrtf(vv[tid] + EPSc);
        sBias[tid] = (bb[tid] - mm[tid]) * sc + be[tid];
    }
    if (tid == 0) sAlpha = aa[0];

    const float* tp = g_tout + ((size_t)b*Sn + p0) * CHn;
    #pragma unroll
    for (int jj = 0; jj < 4; jj++) {
        int idx4 = tid + jj*256;
        int p = idx4 >> 3, cq = idx4 & 7;
        float4 tv = ((const float4*)tp)[idx4];
        sIn[cq*4+0][p] = tv.x;
        sIn[cq*4+1][p] = tv.y;
        sIn[cq*4+2][p] = tv.z;
        sIn[cq*4+3][p] = tv.w;
    }
    __syncthreads();

    int lane = tid & 31, w = tid >> 5;
    float acc[8][4];
    #pragma unroll
    for (int i = 0; i < 8; i++)
        #pragma unroll
        for (int j = 0; j < 4; j++) acc[i][j] = 0.f;

    #pragma unroll 2
    for (int k = 0; k < 32; k++) {
        float4 A0 = *(const float4*)&sW[k][w*8];
        float4 A1 = *(const float4*)&sW[k][w*8 + 4];
        float4 Bv = *(const float4*)&sIn[k][lane*4];
        float av[8] = {A0.x,A0.y,A0.z,A0.w, A1.x,A1.y,A1.z,A1.w};
        float bv[4] = {Bv.x,Bv.y,Bv.z,Bv.w};
        #pragma unroll
        for (int i = 0; i < 8; i++)
            #pragma unroll
            for (int j = 0; j < 4; j++)
                acc[i][j] = fmaf(av[i], bv[j], acc[i][j]);
    }

    float alpha = sAlpha;
    const float* xb = xin + (size_t)b*Cn*Sn + p0 + lane*4;
    float*       ob = outp + (size_t)b*Cn*Sn + p0 + lane*4;
    #pragma unroll
    for (int i = 0; i < 8; i++) {
        int o = w*8 + i;
        float bias = sBias[o];
        float4 xr = *(const float4*)(xb + (size_t)o*Sn);
        float r0 = acc[i][0] + bias; r0 = (r0 > 0.f) ? r0 : alpha*r0; r0 += xr.x;
        float r1 = acc[i][1] + bias; r1 = (r1 > 0.f) ? r1 : alpha*r1; r1 += xr.y;
        float r2 = acc[i][2] + bias; r2 = (r2 > 0.f) ? r2 : alpha*r2; r2 += xr.z;
        float r3 = acc[i][3] + bias; r3 = (r3 > 0.f) ? r3 : alpha*r3; r3 += xr.w;
        *(float4*)(ob + (size_t)o*Sn) = make_float4(r0, r1, r2, r3);
    }
}

// =====================================================================
// Launch
// =====================================================================
extern "C" void kernel_launch(void* const* d_in, const int* in_sizes, int n_in,
                              void* d_out, int out_size) {
    const float* inp  = (const float*)d_in[0];
    const float* x    = (const float*)d_in[1];
    const float* fqkW = (const float*)d_in[2];
    const float* fqkb = (const float*)d_in[3];
    const float* fqkg = (const float*)d_in[4];
    const float* fqkbe= (const float*)d_in[5];
    const float* fqkm = (const float*)d_in[6];
    const float* fqkv = (const float*)d_in[7];
    const float* fqka = (const float*)d_in[8];
    const float* fvW  = (const float*)d_in[9];
    const float* fvb  = (const float*)d_in[10];
    const float* fvg  = (const float*)d_in[11];
    const float* fvbe = (const float*)d_in[12];
    const float* fvm  = (const float*)d_in[13];
    const float* fvv  = (const float*)d_in[14];
    const float* fva  = (const float*)d_in[15];
    const float* tqkW = (const float*)d_in[16];
    const float* tqkb = (const float*)d_in[17];
    const float* tqkg = (const float*)d_in[18];
    const float* tqkbe= (const float*)d_in[19];
    const float* tqkm = (const float*)d_in[20];
    const float* tqkv = (const float*)d_in[21];
    const float* tqka = (const float*)d_in[22];
    const float* prW  = (const float*)d_in[23];
    const float* prb  = (const float*)d_in[24];
    const float* prg  = (const float*)d_in[25];
    const float* prbe = (const float*)d_in[26];
    const float* prm  = (const float*)d_in[27];
    const float* prv  = (const float*)d_in[28];
    const float* pra  = (const float*)d_in[29];
    float* out = (float*)d_out;

    cudaFuncSetAttribute(conv_qk_kernel,
                         cudaFuncAttributeMaxDynamicSharedMemorySize, QK_SMEM);
    cudaFuncSetAttribute(conv_v_kernel,
                         cudaFuncAttributeMaxDynamicSharedMemorySize, CV_SMEM);
    cudaFuncSetAttribute(attn_kernel<false>,
                         cudaFuncAttributeMaxDynamicSharedMemorySize, ATTN_SMEM);
    cudaFuncSetAttribute(attn_kernel<true>,
                         cudaFuncAttributeMaxDynamicSharedMemorySize, ATTN_SMEM);

    conv_qk_kernel<<<dim3(512, Bn), 256, QK_SMEM>>>(inp,
        fqkW, fqkb, fqkg, fqkbe, fqkm, fqkv, fqka,
        tqkW, tqkb, tqkg, tqkbe, tqkm, tqkv, tqka);

    conv_v_kernel<<<dim3(256, Bn), 256, CV_SMEM>>>(x,
        fvW, fvb, fvg, fvbe, fvm, fvv, fva);

    attn_kernel<false><<<dim3(256, Bn), 256, ATTN_SMEM>>>();

    attn_kernel<true><<<dim3(256, Bn), 256, ATTN_SMEM>>>();

    proj_kernel<<<dim3(512, Bn), 256>>>(x,
        prW, prb, prg, prbe, prm, prv, pra, out);
}

// round 7
// speedup vs baseline: 1.2730x; 1.1584x over previous
#include <cuda_runtime.h>
#include <cstdint>

// Problem constants
constexpr int Bn  = 4;
constexpr int Cn  = 64;
constexpr int CHn = 32;
constexpr int Fn  = 256;
constexpr int Tn  = 256;
constexpr int Sn  = Fn * Tn;
constexpr float EPSc = 1e-5f;

// -------- device scratch --------
__device__ float g_qf[Bn*Tn*Fn*CHn];
__device__ float g_kf[Bn*Tn*Fn*CHn];
__device__ float g_vf[Bn*Tn*Fn*CHn];
__device__ float g_qt[Bn*Fn*Tn*CHn];
__device__ float g_kt[Bn*Fn*Tn*CHn];
__device__ float g_fout[Bn*Fn*Tn*CHn];
__device__ float g_tout[Bn*Fn*Tn*CHn];

// dynamic-smem sizes (bytes)
constexpr int QK_SMEM   = (64*128 + 64*128 + 128 + 2) * 4;        // 66056
constexpr int CV_SMEM   = (64*32 + 64*256 + 32 + 1) * 4;          // 73860
// sK 8192 + sV 8192 + sQT 1024 + sP 256*33 (=8448) + sInv 32
constexpr int ATTN_SMEM = (8192 + 8192 + 1024 + 256*33 + 32) * 4; // 103552

// =====================================================================
// Kernel 1: fused fqk + tqk pointwise conv + BN + LeakyReLU. (unchanged)
// =====================================================================
__global__ void __launch_bounds__(256) conv_qk_kernel(
    const float* __restrict__ inp,
    const float* __restrict__ W1, const float* __restrict__ b1,
    const float* __restrict__ g1, const float* __restrict__ be1,
    const float* __restrict__ m1, const float* __restrict__ v1,
    const float* __restrict__ a1,
    const float* __restrict__ W2, const float* __restrict__ b2,
    const float* __restrict__ g2, const float* __restrict__ be2,
    const float* __restrict__ m2, const float* __restrict__ v2,
    const float* __restrict__ a2)
{
    extern __shared__ float smqk[];
    float* sW    = smqk;               // [64][128]
    float* sIn   = smqk + 64*128;      // [64][128]
    float* sBias = smqk + 2*64*128;    // [128]
    float* sAlpha= sBias + 128;        // [2]

    int tid  = threadIdx.x;
    int b    = blockIdx.y;
    int tile = blockIdx.x;
    int p0   = tile * 128;
    int f    = p0 >> 8;
    int t0   = p0 & 255;

    #pragma unroll 4
    for (int jj = 0; jj < 32; jj++) {
        int idx = tid + jj * 256;
        int k = idx >> 7;
        int o = idx & 127;
        float w;
        if (o < 64) {
            float sc = g1[o] * rsqrtf(v1[o] + EPSc);
            w = W1[o*64 + k] * sc;
        } else {
            int oo = o - 64;
            float sc = g2[oo] * rsqrtf(v2[oo] + EPSc);
            w = W2[oo*64 + k] * sc;
        }
        sW[k*128 + o] = w;
    }
    if (tid < 128) {
        int o = tid;
        float bias;
        if (o < 64) {
            float sc = g1[o] * rsqrtf(v1[o] + EPSc);
            bias = (b1[o] - m1[o]) * sc + be1[o];
        } else {
            int oo = o - 64;
            float sc = g2[oo] * rsqrtf(v2[oo] + EPSc);
            bias = (b2[oo] - m2[oo]) * sc + be2[oo];
        }
        sBias[o] = bias;
    }
    if (tid == 0) { sAlpha[0] = a1[0]; sAlpha[1] = a2[0]; }

    const float* ip = inp + (size_t)b * Cn * Sn + p0;
    #pragma unroll
    for (int jj = 0; jj < 8; jj++) {
        int idx4 = tid + jj * 256;
        int k  = idx4 >> 5;
        int pq = idx4 & 31;
        float4 val = *(const float4*)(ip + (size_t)k * Sn + pq * 4);
        *(float4*)&sIn[k*128 + pq*4] = val;
    }
    __syncthreads();

    int lane = tid & 31, w = tid >> 5;
    float acc[16][4];
    #pragma unroll
    for (int i = 0; i < 16; i++)
        #pragma unroll
        for (int j = 0; j < 4; j++) acc[i][j] = 0.f;

    #pragma unroll 2
    for (int k = 0; k < 64; k++) {
        float4 A0 = *(const float4*)&sW[k*128 + w*16 + 0];
        float4 A1 = *(const float4*)&sW[k*128 + w*16 + 4];
        float4 A2 = *(const float4*)&sW[k*128 + w*16 + 8];
        float4 A3 = *(const float4*)&sW[k*128 + w*16 + 12];
        float4 Bv = *(const float4*)&sIn[k*128 + lane*4];
        float av[16] = {A0.x,A0.y,A0.z,A0.w, A1.x,A1.y,A1.z,A1.w,
                        A2.x,A2.y,A2.z,A2.w, A3.x,A3.y,A3.z,A3.w};
        float bv[4]  = {Bv.x,Bv.y,Bv.z,Bv.w};
        #pragma unroll
        for (int i = 0; i < 16; i++)
            #pragma unroll
            for (int j = 0; j < 4; j++)
                acc[i][j] = fmaf(av[i], bv[j], acc[i][j]);
    }

    float alpha = (w < 4) ? sAlpha[0] : sAlpha[1];
    #pragma unroll
    for (int i = 0; i < 16; i++) {
        float bias = sBias[w*16 + i];
        #pragma unroll
        for (int j = 0; j < 4; j++) {
            float y = acc[i][j] + bias;
            acc[i][j] = (y > 0.f) ? y : alpha * y;
        }
    }

    int t = t0 + lane * 4;
    if (w < 4) {
        int cb = w * 8;
        #pragma unroll
        for (int j = 0; j < 4; j++) {
            size_t off = (((size_t)b*Tn + (t+j))*Fn + f)*CHn + cb;
            *(float4*)(g_qf+off)   = make_float4(acc[0][j],acc[2][j],acc[4][j],acc[6][j]);
            *(float4*)(g_qf+off+4) = make_float4(acc[8][j],acc[10][j],acc[12][j],acc[14][j]);
            *(float4*)(g_kf+off)   = make_float4(acc[1][j],acc[3][j],acc[5][j],acc[7][j]);
            *(float4*)(g_kf+off+4) = make_float4(acc[9][j],acc[11][j],acc[13][j],acc[15][j]);
        }
    } else {
        int cb = (w - 4) * 8;
        #pragma unroll
        for (int j = 0; j < 4; j++) {
            size_t off = (((size_t)b*Fn + f)*Tn + (t+j))*CHn + cb;
            *(float4*)(g_qt+off)   = make_float4(acc[0][j],acc[2][j],acc[4][j],acc[6][j]);
            *(float4*)(g_qt+off+4) = make_float4(acc[8][j],acc[10][j],acc[12][j],acc[14][j]);
            *(float4*)(g_kt+off)   = make_float4(acc[1][j],acc[3][j],acc[5][j],acc[7][j]);
            *(float4*)(g_kt+off+4) = make_float4(acc[9][j],acc[11][j],acc[13][j],acc[15][j]);
        }
    }
}

// =====================================================================
// Kernel 2: fv conv (64 -> 32) + BN + LeakyReLU. (unchanged)
// =====================================================================
__global__ void __launch_bounds__(256) conv_v_kernel(
    const float* __restrict__ xin,
    const float* __restrict__ W,  const float* __restrict__ bb,
    const float* __restrict__ gg, const float* __restrict__ be,
    const float* __restrict__ mm, const float* __restrict__ vv,
    const float* __restrict__ aa)
{
    extern __shared__ float smcv[];
    float* sW    = smcv;              // [64][32]
    float* sIn   = smcv + 64*32;      // [64][256]
    float* sBias = sIn + 64*256;      // [32]
    float* sAlpha= sBias + 32;        // [1]

    int tid = threadIdx.x;
    int f = blockIdx.x, b = blockIdx.y;

    for (int idx = tid; idx < 2048; idx += 256) {
        int k = idx >> 5, o = idx & 31;
        float sc = gg[o] * rsqrtf(vv[o] + EPSc);
        sW[k*32 + o] = W[o*64 + k] * sc;
    }
    if (tid < 32) {
        float sc = gg[tid] * rsqrtf(vv[tid] + EPSc);
        sBias[tid] = (bb[tid] - mm[tid]) * sc + be[tid];
    }
    if (tid == 0) sAlpha[0] = aa[0];

    const float* ip = xin + (size_t)b*Cn*Sn + (size_t)f*Tn;
    #pragma unroll
    for (int jj = 0; jj < 16; jj++) {
        int idx4 = tid + jj*256;
        int k = idx4 >> 6, pq = idx4 & 63;
        *(float4*)&sIn[k*256 + pq*4] = *(const float4*)(ip + (size_t)k*Sn + pq*4);
    }
    __syncthreads();

    int lane = tid & 31, w = tid >> 5;
    int cg = w & 3, ph = w >> 2;
    float acc[8][4];
    #pragma unroll
    for (int i = 0; i < 8; i++)
        #pragma unroll
        for (int j = 0; j < 4; j++) acc[i][j] = 0.f;

    #pragma unroll 2
    for (int k = 0; k < 64; k++) {
        float4 A0 = *(const float4*)&sW[k*32 + cg*8];
        float4 A1 = *(const float4*)&sW[k*32 + cg*8 + 4];
        float4 Bv = *(const float4*)&sIn[k*256 + ph*128 + lane*4];
        float av[8] = {A0.x,A0.y,A0.z,A0.w, A1.x,A1.y,A1.z,A1.w};
        float bv[4] = {Bv.x,Bv.y,Bv.z,Bv.w};
        #pragma unroll
        for (int i = 0; i < 8; i++)
            #pragma unroll
            for (int j = 0; j < 4; j++)
                acc[i][j] = fmaf(av[i], bv[j], acc[i][j]);
    }

    float alpha = sAlpha[0];
    int c = cg * 8;
    #pragma unroll
    for (int j = 0; j < 4; j++) {
        int t = ph*128 + lane*4 + j;
        float r[8];
        #pragma unroll
        for (int i = 0; i < 8; i++) {
            float y = acc[i][j] + sBias[c + i];
            r[i] = (y > 0.f) ? y : alpha * y;
        }
        size_t off = (((size_t)b*Tn + t)*Fn + f)*CHn + c;
        *(float4*)(g_vf + off)     = make_float4(r[0],r[1],r[2],r[3]);
        *(float4*)(g_vf + off + 4) = make_float4(r[4],r[5],r[6],r[7]);
    }
}

// =====================================================================
// Attention kernel — v3:
//  * score GEMM (quarters, float2 K loads) + register softmax, as v2
//  * P stored TRANSPOSED: sP[y][r], pitch 33
//      writes: scalar, 2-way conflict (cheap)
//      reads : scalar, bank-spread + 4-lane broadcast -> 1 wavefront
//  * PV split over 4 y-segments (64 threads each, 4x4 tiles):
//      per y per warp: 4 P wf + 1 V wf vs 8 FMA cycles -> compute-bound
//  * partials reduced via smem (aliases sP, which is dead by then)
// =====================================================================
template<bool CAUSAL>
__global__ void __launch_bounds__(256, 2) attn_kernel()
{
    const float* __restrict__ qg = CAUSAL ? g_qt : g_qf;
    const float* __restrict__ kg = CAUSAL ? g_kt : g_kf;
    const float* __restrict__ vg = CAUSAL ? g_fout : g_vf;
    float* __restrict__ outg     = CAUSAL ? g_tout : g_fout;

    extern __shared__ float sm[];
    float* sK    = sm;                  // [32][256]  K^T: sK[c][y]
    float* sV    = sm + 8192;           // [256][32]  V[y][c]
    float* sQT   = sm + 16384;          // [32][32]   Q chunk transposed
    float* sP    = sm + 17408;          // [256][33]  P transposed, pitch 33
    float* sPart = sm + 17408;          // alias: [4][32][32] partials
    float* sInv  = sm + 17408 + 256*33; // [32]

    int tid = threadIdx.x, lane = tid & 31, w = tid >> 5;
    int col = blockIdx.x;
    int b   = blockIdx.y;
    size_t base = ((size_t)b * 256 + col) * 256 * CHn;
    const float* qp = qg + base;
    const float* kp = kg + base;
    const float* vp = vg + base;
    size_t out_base, out_stride;
    if (CAUSAL) { out_base = base; out_stride = CHn; }
    else { out_base = ((size_t)b * Sn + col) * CHn; out_stride = (size_t)Tn * CHn; }

    // Load K (transposed) and V
    #pragma unroll
    for (int jj = 0; jj < 8; jj++) {
        int idx4 = tid + jj*256;
        int y = idx4 >> 3, cq = idx4 & 7;
        float4 kv = ((const float4*)kp)[idx4];
        sK[(cq*4+0)*256 + y] = kv.x;
        sK[(cq*4+1)*256 + y] = kv.y;
        sK[(cq*4+2)*256 + y] = kv.z;
        sK[(cq*4+3)*256 + y] = kv.w;
        ((float4*)sV)[idx4] = ((const float4*)vp)[idx4];
    }

    const float scale = 0.17677669529663687f;  // 1/sqrt(32)

    // PV decomposition indices
    const int seg = tid >> 6;          // y-segment 0..3
    const int t6  = tid & 63;
    const int rg  = t6 & 7;            // r-group: rows rg*4..rg*4+3
    const int cgp = t6 >> 3;           // c-group: cols cgp*4..cgp*4+3

    for (int ch = 0; ch < 8; ch++) {
        int r0 = ch * 32;

        // stage Q chunk transposed: sQT[c][fi]
        {
            int fi = tid >> 3, cq = tid & 7;
            float4 qv = *(const float4*)(qp + (size_t)(r0 + fi)*CHn + cq*4);
            sQT[(cq*4+0)*32 + fi] = qv.x;
            sQT[(cq*4+1)*32 + fi] = qv.y;
            sQT[(cq*4+2)*32 + fi] = qv.z;
            sQT[(cq*4+3)*32 + fi] = qv.w;
        }
        __syncthreads();   // (1) sQT ready; prev chunk's sPart reads done

        const int qmax = CAUSAL ? ((r0 + 95) >> 6) : 4;

        // ---- score GEMM: warp w -> rows w*4..w*4+3,
        //      quarter q -> cols q*64 + lane*2 + {0,1}
        float acc[4][8];
        #pragma unroll
        for (int i = 0; i < 4; i++)
            #pragma unroll
            for (int j = 0; j < 8; j++) acc[i][j] = 0.f;

        for (int q = 0; q < qmax; q++) {
            const float* kq = &sK[q*64 + lane*2];
            #pragma unroll 8
            for (int c = 0; c < 32; c++) {
                float4 A  = *(const float4*)&sQT[c*32 + w*4];
                float2 Bv = *(const float2*)&kq[c*256];
                acc[0][q*2+0] = fmaf(A.x, Bv.x, acc[0][q*2+0]);
                acc[0][q*2+1] = fmaf(A.x, Bv.y, acc[0][q*2+1]);
                acc[1][q*2+0] = fmaf(A.y, Bv.x, acc[1][q*2+0]);
                acc[1][q*2+1] = fmaf(A.y, Bv.y, acc[1][q*2+1]);
                acc[2][q*2+0] = fmaf(A.z, Bv.x, acc[2][q*2+0]);
                acc[2][q*2+1] = fmaf(A.z, Bv.y, acc[2][q*2+1]);
                acc[3][q*2+0] = fmaf(A.w, Bv.x, acc[3][q*2+0]);
                acc[3][q*2+1] = fmaf(A.w, Bv.y, acc[3][q*2+1]);
            }
        }

        // ---- register softmax; write P transposed (sP[y][r], pitch 33)
        #pragma unroll
        for (int i = 0; i < 4; i++) {
            int r  = w*4 + i;
            int tg = r0 + r;
            float mx = -1e30f;
            #pragma unroll
            for (int q = 0; q < 4; q++) {
                if (q < qmax) {
                    #pragma unroll
                    for (int v = 0; v < 2; v++) {
                        int y = q*64 + lane*2 + v;
                        float s = acc[i][q*2+v] * scale;
                        if (CAUSAL && y > tg) s = -1e30f;
                        acc[i][q*2+v] = s;
                        mx = fmaxf(mx, s);
                    }
                }
            }
            #pragma unroll
            for (int off = 16; off > 0; off >>= 1)
                mx = fmaxf(mx, __shfl_xor_sync(0xffffffffu, mx, off));

            float sum = 0.f;
            #pragma unroll
            for (int q = 0; q < 4; q++) {
                if (q < qmax) {
                    int y0 = q*64 + lane*2;
                    float e0 = __expf(acc[i][q*2+0] - mx);
                    float e1 = __expf(acc[i][q*2+1] - mx);
                    sum += e0 + e1;
                    sP[(y0+0)*33 + r] = e0;
                    sP[(y0+1)*33 + r] = e1;
                }
            }
            #pragma unroll
            for (int off = 16; off > 0; off >>= 1)
                sum += __shfl_xor_sync(0xffffffffu, sum, off);
            if (lane == 0) sInv[r] = 1.f / sum;
        }
        __syncthreads();   // (2) P ready

        // ---- PV: segment seg covers y in [seg*64, seg*64+64) clipped
        float a0x=0.f,a0y=0.f,a0z=0.f,a0w=0.f;
        float a1x=0.f,a1y=0.f,a1z=0.f,a1w=0.f;
        float a2x=0.f,a2y=0.f,a2z=0.f,a2w=0.f;
        float a3x=0.f,a3y=0.f,a3z=0.f,a3w=0.f;
        {
            int ys = seg * 64;
            int ye = CAUSAL ? min(ys + 64, r0 + 32) : (ys + 64);
            const float* pbase = &sP[rg*4];
            const float* vbase = &sV[cgp*4];
            #pragma unroll 4
            for (int y = ys; y < ye; y++) {
                const float* pr = pbase + y*33;
                float p0 = pr[0], p1 = pr[1], p2 = pr[2], p3 = pr[3];
                float4 v = *(const float4*)(vbase + y*32);
                a0x = fmaf(p0, v.x, a0x); a0y = fmaf(p0, v.y, a0y);
                a0z = fmaf(p0, v.z, a0z); a0w = fmaf(p0, v.w, a0w);
                a1x = fmaf(p1, v.x, a1x); a1y = fmaf(p1, v.y, a1y);
                a1z = fmaf(p1, v.z, a1z); a1w = fmaf(p1, v.w, a1w);
                a2x = fmaf(p2, v.x, a2x); a2y = fmaf(p2, v.y, a2y);
                a2z = fmaf(p2, v.z, a2z); a2w = fmaf(p2, v.w, a2w);
                a3x = fmaf(p3, v.x, a3x); a3y = fmaf(p3, v.y, a3y);
                a3z = fmaf(p3, v.z, a3z); a3w = fmaf(p3, v.w, a3w);
            }
        }
        __syncthreads();   // (3) all P reads done; sP reusable as sPart

        // store partials
        {
            float* pb = &sPart[seg*1024 + rg*4*32 + cgp*4];
            *(float4*)(pb + 0*32) = make_float4(a0x,a0y,a0z,a0w);
            *(float4*)(pb + 1*32) = make_float4(a1x,a1y,a1z,a1w);
            *(float4*)(pb + 2*32) = make_float4(a2x,a2y,a2z,a2w);
            *(float4*)(pb + 3*32) = make_float4(a3x,a3y,a3z,a3w);
        }
        __syncthreads();   // (4) partials ready

        // reduce 4 segments + scale + write out
        {
            int r  = tid >> 3;
            int c0 = (tid & 7) * 4;
            float4 x0 = *(const float4*)&sPart[0*1024 + r*32 + c0];
            float4 x1 = *(const float4*)&sPart[1*1024 + r*32 + c0];
            float4 x2 = *(const float4*)&sPart[2*1024 + r*32 + c0];
            float4 x3 = *(const float4*)&sPart[3*1024 + r*32 + c0];
            float inv = sInv[r];
            float ox = (x0.x + x1.x + x2.x + x3.x) * inv;
            float oy = (x0.y + x1.y + x2.y + x3.y) * inv;
            float oz = (x0.z + x1.z + x2.z + x3.z) * inv;
            float ow = (x0.w + x1.w + x2.w + x3.w) * inv;
            *(float4*)(outg + out_base + (size_t)(r0 + r)*out_stride + c0) =
                make_float4(ox, oy, oz, ow);
        }
        // next iteration's sync (1) orders these reads vs next sP writes
    }
}

// =====================================================================
// Kernel 5: proj conv (32 -> 64) + BN + LeakyReLU + residual. (unchanged)
// =====================================================================
__global__ void __launch_bounds__(256) proj_kernel(
    const float* __restrict__ xin,
    const float* __restrict__ W,  const float* __restrict__ bb,
    const float* __restrict__ gg, const float* __restrict__ be,
    const float* __restrict__ mm, const float* __restrict__ vv,
    const float* __restrict__ aa,
    float* __restrict__ outp)
{
    __shared__ float sW[32][64];
    __shared__ float sIn[32][132];
    __shared__ float sBias[64];
    __shared__ float sAlpha;

    int tid = threadIdx.x;
    int tile = blockIdx.x, b = blockIdx.y;
    int p0 = tile * 128;

    for (int idx = tid; idx < 2048; idx += 256) {
        int o = idx & 63, k = idx >> 6;
        float sc = gg[o] * rsqrtf(vv[o] + EPSc);
        sW[k][o] = W[o*32 + k] * sc;
    }
    if (tid < 64) {
        float sc = gg[tid] * rsqrtf(vv[tid] + EPSc);
        sBias[tid] = (bb[tid] - mm[tid]) * sc + be[tid];
    }
    if (tid == 0) sAlpha = aa[0];

    const float* tp = g_tout + ((size_t)b*Sn + p0) * CHn;
    #pragma unroll
    for (int jj = 0; jj < 4; jj++) {
        int idx4 = tid + jj*256;
        int p = idx4 >> 3, cq = idx4 & 7;
        float4 tv = ((const float4*)tp)[idx4];
        sIn[cq*4+0][p] = tv.x;
        sIn[cq*4+1][p] = tv.y;
        sIn[cq*4+2][p] = tv.z;
        sIn[cq*4+3][p] = tv.w;
    }
    __syncthreads();

    int lane = tid & 31, w = tid >> 5;
    float acc[8][4];
    #pragma unroll
    for (int i = 0; i < 8; i++)
        #pragma unroll
        for (int j = 0; j < 4; j++) acc[i][j] = 0.f;

    #pragma unroll 2
    for (int k = 0; k < 32; k++) {
        float4 A0 = *(const float4*)&sW[k][w*8];
        float4 A1 = *(const float4*)&sW[k][w*8 + 4];
        float4 Bv = *(const float4*)&sIn[k][lane*4];
        float av[8] = {A0.x,A0.y,A0.z,A0.w, A1.x,A1.y,A1.z,A1.w};
        float bv[4] = {Bv.x,Bv.y,Bv.z,Bv.w};
        #pragma unroll
        for (int i = 0; i < 8; i++)
            #pragma unroll
            for (int j = 0; j < 4; j++)
                acc[i][j] = fmaf(av[i], bv[j], acc[i][j]);
    }

    float alpha = sAlpha;
    const float* xb = xin + (size_t)b*Cn*Sn + p0 + lane*4;
    float*       ob = outp + (size_t)b*Cn*Sn + p0 + lane*4;
    #pragma unroll
    for (int i = 0; i < 8; i++) {
        int o = w*8 + i;
        float bias = sBias[o];
        float4 xr = *(const float4*)(xb + (size_t)o*Sn);
        float r0 = acc[i][0] + bias; r0 = (r0 > 0.f) ? r0 : alpha*r0; r0 += xr.x;
        float r1 = acc[i][1] + bias; r1 = (r1 > 0.f) ? r1 : alpha*r1; r1 += xr.y;
        float r2 = acc[i][2] + bias; r2 = (r2 > 0.f) ? r2 : alpha*r2; r2 += xr.z;
        float r3 = acc[i][3] + bias; r3 = (r3 > 0.f) ? r3 : alpha*r3; r3 += xr.w;
        *(float4*)(ob + (size_t)o*Sn) = make_float4(r0, r1, r2, r3);
    }
}

// =====================================================================
// Launch
// =====================================================================
extern "C" void kernel_launch(void* const* d_in, const int* in_sizes, int n_in,
                              void* d_out, int out_size) {
    const float* inp  = (const float*)d_in[0];
    const float* x    = (const float*)d_in[1];
    const float* fqkW = (const float*)d_in[2];
    const float* fqkb = (const float*)d_in[3];
    const float* fqkg = (const float*)d_in[4];
    const float* fqkbe= (const float*)d_in[5];
    const float* fqkm = (const float*)d_in[6];
    const float* fqkv = (const float*)d_in[7];
    const float* fqka = (const float*)d_in[8];
    const float* fvW  = (const float*)d_in[9];
    const float* fvb  = (const float*)d_in[10];
    const float* fvg  = (const float*)d_in[11];
    const float* fvbe = (const float*)d_in[12];
    const float* fvm  = (const float*)d_in[13];
    const float* fvv  = (const float*)d_in[14];
    const float* fva  = (const float*)d_in[15];
    const float* tqkW = (const float*)d_in[16];
    const float* tqkb = (const float*)d_in[17];
    const float* tqkg = (const float*)d_in[18];
    const float* tqkbe= (const float*)d_in[19];
    const float* tqkm = (const float*)d_in[20];
    const float* tqkv = (const float*)d_in[21];
    const float* tqka = (const float*)d_in[22];
    const float* prW  = (const float*)d_in[23];
    const float* prb  = (const float*)d_in[24];
    const float* prg  = (const float*)d_in[25];
    const float* prbe = (const float*)d_in[26];
    const float* prm  = (const float*)d_in[27];
    const float* prv  = (const float*)d_in[28];
    const float* pra  = (const float*)d_in[29];
    float* out = (float*)d_out;

    cudaFuncSetAttribute(conv_qk_kernel,
                         cudaFuncAttributeMaxDynamicSharedMemorySize, QK_SMEM);
    cudaFuncSetAttribute(conv_v_kernel,
                         cudaFuncAttributeMaxDynamicSharedMemorySize, CV_SMEM);
    cudaFuncSetAttribute(attn_kernel<false>,
                         cudaFuncAttributeMaxDynamicSharedMemorySize, ATTN_SMEM);
    cudaFuncSetAttribute(attn_kernel<true>,
                         cudaFuncAttributeMaxDynamicSharedMemorySize, ATTN_SMEM);

    conv_qk_kernel<<<dim3(512, Bn), 256, QK_SMEM>>>(inp,
        fqkW, fqkb, fqkg, fqkbe, fqkm, fqkv, fqka,
        tqkW, tqkb, tqkg, tqkbe, tqkm, tqkv, tqka);

    conv_v_kernel<<<dim3(256, Bn), 256, CV_SMEM>>>(x,
        fvW, fvb, fvg, fvbe, fvm, fvv, fva);

    attn_kernel<false><<<dim3(256, Bn), 256, ATTN_SMEM>>>();

    attn_kernel<true><<<dim3(256, Bn), 256, ATTN_SMEM>>>();

    proj_kernel<<<dim3(512, Bn), 256>>>(x,
        prW, prb, prg, prbe, prm, prv, pra, out);
}

// round 8
// speedup vs baseline: 1.3222x; 1.0386x over previous
#include <cuda_runtime.h>
#include <cuda_bf16.h>
#include <cstdint>

// Problem constants
constexpr int Bn  = 4;
constexpr int Cn  = 64;
constexpr int CHn = 32;
constexpr int Fn  = 256;
constexpr int Tn  = 256;
constexpr int Sn  = Fn * Tn;
constexpr float EPSc = 1e-5f;

// -------- device scratch --------
__device__ float g_qf[Bn*Tn*Fn*CHn];
__device__ float g_kf[Bn*Tn*Fn*CHn];
__device__ float g_vf[Bn*Tn*Fn*CHn];
__device__ float g_qt[Bn*Fn*Tn*CHn];
__device__ float g_kt[Bn*Fn*Tn*CHn];
__device__ float g_fout[Bn*Fn*Tn*CHn];
__device__ float g_tout[Bn*Fn*Tn*CHn];

// dynamic-smem sizes (bytes)
constexpr int QK_SMEM   = (64*128 + 64*128 + 128 + 2) * 4;        // 66056
constexpr int CV_SMEM   = (64*32 + 64*256 + 32 + 1) * 4;          // 73860
// byte layout for attn:
//   sK   (bf16) [32][256] : [0, 16384)
//   sV   (f32)  [256][32] : [16384, 49152)
//   sQT  (f32)  [32][32]  : [49152, 53248)
//   sP   (bf16) [256][33] : [53248, 70144)   (sPart f32 [4][32][32] aliases [53248, 69632))
//   sInv (f32)  [32]      : [70144, 70272)
constexpr int ATTN_SMEM = 70272;

// =====================================================================
// Kernel 1: fused fqk + tqk pointwise conv + BN + LeakyReLU. (unchanged)
// =====================================================================
__global__ void __launch_bounds__(256) conv_qk_kernel(
    const float* __restrict__ inp,
    const float* __restrict__ W1, const float* __restrict__ b1,
    const float* __restrict__ g1, const float* __restrict__ be1,
    const float* __restrict__ m1, const float* __restrict__ v1,
    const float* __restrict__ a1,
    const float* __restrict__ W2, const float* __restrict__ b2,
    const float* __restrict__ g2, const float* __restrict__ be2,
    const float* __restrict__ m2, const float* __restrict__ v2,
    const float* __restrict__ a2)
{
    extern __shared__ float smqk[];
    float* sW    = smqk;               // [64][128]
    float* sIn   = smqk + 64*128;      // [64][128]
    float* sBias = smqk + 2*64*128;    // [128]
    float* sAlpha= sBias + 128;        // [2]

    int tid  = threadIdx.x;
    int b    = blockIdx.y;
    int tile = blockIdx.x;
    int p0   = tile * 128;
    int f    = p0 >> 8;
    int t0   = p0 & 255;

    #pragma unroll 4
    for (int jj = 0; jj < 32; jj++) {
        int idx = tid + jj * 256;
        int k = idx >> 7;
        int o = idx & 127;
        float w;
        if (o < 64) {
            float sc = g1[o] * rsqrtf(v1[o] + EPSc);
            w = W1[o*64 + k] * sc;
        } else {
            int oo = o - 64;
            float sc = g2[oo] * rsqrtf(v2[oo] + EPSc);
            w = W2[oo*64 + k] * sc;
        }
        sW[k*128 + o] = w;
    }
    if (tid < 128) {
        int o = tid;
        float bias;
        if (o < 64) {
            float sc = g1[o] * rsqrtf(v1[o] + EPSc);
            bias = (b1[o] - m1[o]) * sc + be1[o];
        } else {
            int oo = o - 64;
            float sc = g2[oo] * rsqrtf(v2[oo] + EPSc);
            bias = (b2[oo] - m2[oo]) * sc + be2[oo];
        }
        sBias[o] = bias;
    }
    if (tid == 0) { sAlpha[0] = a1[0]; sAlpha[1] = a2[0]; }

    const float* ip = inp + (size_t)b * Cn * Sn + p0;
    #pragma unroll
    for (int jj = 0; jj < 8; jj++) {
        int idx4 = tid + jj * 256;
        int k  = idx4 >> 5;
        int pq = idx4 & 31;
        float4 val = *(const float4*)(ip + (size_t)k * Sn + pq * 4);
        *(float4*)&sIn[k*128 + pq*4] = val;
    }
    __syncthreads();

    int lane = tid & 31, w = tid >> 5;
    float acc[16][4];
    #pragma unroll
    for (int i = 0; i < 16; i++)
        #pragma unroll
        for (int j = 0; j < 4; j++) acc[i][j] = 0.f;

    #pragma unroll 2
    for (int k = 0; k < 64; k++) {
        float4 A0 = *(const float4*)&sW[k*128 + w*16 + 0];
        float4 A1 = *(const float4*)&sW[k*128 + w*16 + 4];
        float4 A2 = *(const float4*)&sW[k*128 + w*16 + 8];
        float4 A3 = *(const float4*)&sW[k*128 + w*16 + 12];
        float4 Bv = *(const float4*)&sIn[k*128 + lane*4];
        float av[16] = {A0.x,A0.y,A0.z,A0.w, A1.x,A1.y,A1.z,A1.w,
                        A2.x,A2.y,A2.z,A2.w, A3.x,A3.y,A3.z,A3.w};
        float bv[4]  = {Bv.x,Bv.y,Bv.z,Bv.w};
        #pragma unroll
        for (int i = 0; i < 16; i++)
            #pragma unroll
            for (int j = 0; j < 4; j++)
                acc[i][j] = fmaf(av[i], bv[j], acc[i][j]);
    }

    float alpha = (w < 4) ? sAlpha[0] : sAlpha[1];
    #pragma unroll
    for (int i = 0; i < 16; i++) {
        float bias = sBias[w*16 + i];
        #pragma unroll
        for (int j = 0; j < 4; j++) {
            float y = acc[i][j] + bias;
            acc[i][j] = (y > 0.f) ? y : alpha * y;
        }
    }

    int t = t0 + lane * 4;
    if (w < 4) {
        int cb = w * 8;
        #pragma unroll
        for (int j = 0; j < 4; j++) {
            size_t off = (((size_t)b*Tn + (t+j))*Fn + f)*CHn + cb;
            *(float4*)(g_qf+off)   = make_float4(acc[0][j],acc[2][j],acc[4][j],acc[6][j]);
            *(float4*)(g_qf+off+4) = make_float4(acc[8][j],acc[10][j],acc[12][j],acc[14][j]);
            *(float4*)(g_kf+off)   = make_float4(acc[1][j],acc[3][j],acc[5][j],acc[7][j]);
            *(float4*)(g_kf+off+4) = make_float4(acc[9][j],acc[11][j],acc[13][j],acc[15][j]);
        }
    } else {
        int cb = (w - 4) * 8;
        #pragma unroll
        for (int j = 0; j < 4; j++) {
            size_t off = (((size_t)b*Fn + f)*Tn + (t+j))*CHn + cb;
            *(float4*)(g_qt+off)   = make_float4(acc[0][j],acc[2][j],acc[4][j],acc[6][j]);
            *(float4*)(g_qt+off+4) = make_float4(acc[8][j],acc[10][j],acc[12][j],acc[14][j]);
            *(float4*)(g_kt+off)   = make_float4(acc[1][j],acc[3][j],acc[5][j],acc[7][j]);
            *(float4*)(g_kt+off+4) = make_float4(acc[9][j],acc[11][j],acc[13][j],acc[15][j]);
        }
    }
}

// =====================================================================
// Kernel 2: fv conv (64 -> 32) + BN + LeakyReLU. (unchanged)
// =====================================================================
__global__ void __launch_bounds__(256) conv_v_kernel(
    const float* __restrict__ xin,
    const float* __restrict__ W,  const float* __restrict__ bb,
    const float* __restrict__ gg, const float* __restrict__ be,
    const float* __restrict__ mm, const float* __restrict__ vv,
    const float* __restrict__ aa)
{
    extern __shared__ float smcv[];
    float* sW    = smcv;              // [64][32]
    float* sIn   = smcv + 64*32;      // [64][256]
    float* sBias = sIn + 64*256;      // [32]
    float* sAlpha= sBias + 32;        // [1]

    int tid = threadIdx.x;
    int f = blockIdx.x, b = blockIdx.y;

    for (int idx = tid; idx < 2048; idx += 256) {
        int k = idx >> 5, o = idx & 31;
        float sc = gg[o] * rsqrtf(vv[o] + EPSc);
        sW[k*32 + o] = W[o*64 + k] * sc;
    }
    if (tid < 32) {
        float sc = gg[tid] * rsqrtf(vv[tid] + EPSc);
        sBias[tid] = (bb[tid] - mm[tid]) * sc + be[tid];
    }
    if (tid == 0) sAlpha[0] = aa[0];

    const float* ip = xin + (size_t)b*Cn*Sn + (size_t)f*Tn;
    #pragma unroll
    for (int jj = 0; jj < 16; jj++) {
        int idx4 = tid + jj*256;
        int k = idx4 >> 6, pq = idx4 & 63;
        *(float4*)&sIn[k*256 + pq*4] = *(const float4*)(ip + (size_t)k*Sn + pq*4);
    }
    __syncthreads();

    int lane = tid & 31, w = tid >> 5;
    int cg = w & 3, ph = w >> 2;
    float acc[8][4];
    #pragma unroll
    for (int i = 0; i < 8; i++)
        #pragma unroll
        for (int j = 0; j < 4; j++) acc[i][j] = 0.f;

    #pragma unroll 2
    for (int k = 0; k < 64; k++) {
        float4 A0 = *(const float4*)&sW[k*32 + cg*8];
        float4 A1 = *(const float4*)&sW[k*32 + cg*8 + 4];
        float4 Bv = *(const float4*)&sIn[k*256 + ph*128 + lane*4];
        float av[8] = {A0.x,A0.y,A0.z,A0.w, A1.x,A1.y,A1.z,A1.w};
        float bv[4] = {Bv.x,Bv.y,Bv.z,Bv.w};
        #pragma unroll
        for (int i = 0; i < 8; i++)
            #pragma unroll
            for (int j = 0; j < 4; j++)
                acc[i][j] = fmaf(av[i], bv[j], acc[i][j]);
    }

    float alpha = sAlpha[0];
    int c = cg * 8;
    #pragma unroll
    for (int j = 0; j < 4; j++) {
        int t = ph*128 + lane*4 + j;
        float r[8];
        #pragma unroll
        for (int i = 0; i < 8; i++) {
            float y = acc[i][j] + sBias[c + i];
            r[i] = (y > 0.f) ? y : alpha * y;
        }
        size_t off = (((size_t)b*Tn + t)*Fn + f)*CHn + c;
        *(float4*)(g_vf + off)     = make_float4(r[0],r[1],r[2],r[3]);
        *(float4*)(g_vf + off + 4) = make_float4(r[4],r[5],r[6],r[7]);
    }
}

// =====================================================================
// Attention kernel — v4:
//  * K and P staged in bf16 (fp32 accumulate everywhere)
//      -> smem 103.5KB -> 68.6KB, score K-loads 2wf -> 1wf
//  * __launch_bounds__(256,3): 3 blocks/SM (24 warps) vs 2
//  * structure otherwise as v3 (register softmax, P transposed pitch 33,
//    split-y PV with smem partial reduction aliasing sP)
// =====================================================================
template<bool CAUSAL>
__global__ void __launch_bounds__(256, 3) attn_kernel()
{
    const float* __restrict__ qg = CAUSAL ? g_qt : g_qf;
    const float* __restrict__ kg = CAUSAL ? g_kt : g_kf;
    const float* __restrict__ vg = CAUSAL ? g_fout : g_vf;
    float* __restrict__ outg     = CAUSAL ? g_tout : g_fout;

    extern __shared__ char smb[];
    __nv_bfloat16* sK   = (__nv_bfloat16*)smb;            // [32][256]
    float*         sV   = (float*)(smb + 16384);          // [256][32]
    float*         sQT  = (float*)(smb + 49152);          // [32][32]
    __nv_bfloat16* sP   = (__nv_bfloat16*)(smb + 53248);  // [256][33]
    float*         sPart= (float*)(smb + 53248);          // [4][32][32] alias
    float*         sInv = (float*)(smb + 70144);          // [32]

    int tid = threadIdx.x, lane = tid & 31, w = tid >> 5;
    int col = blockIdx.x;
    int b   = blockIdx.y;
    size_t base = ((size_t)b * 256 + col) * 256 * CHn;
    const float* qp = qg + base;
    const float* kp = kg + base;
    const float* vp = vg + base;
    size_t out_base, out_stride;
    if (CAUSAL) { out_base = base; out_stride = CHn; }
    else { out_base = ((size_t)b * Sn + col) * CHn; out_stride = (size_t)Tn * CHn; }

    // Load K (transposed, bf16) and V (fp32)
    #pragma unroll
    for (int jj = 0; jj < 8; jj++) {
        int idx4 = tid + jj*256;
        int y = idx4 >> 3, cq = idx4 & 7;
        float4 kv = ((const float4*)kp)[idx4];
        sK[(cq*4+0)*256 + y] = __float2bfloat16(kv.x);
        sK[(cq*4+1)*256 + y] = __float2bfloat16(kv.y);
        sK[(cq*4+2)*256 + y] = __float2bfloat16(kv.z);
        sK[(cq*4+3)*256 + y] = __float2bfloat16(kv.w);
        ((float4*)sV)[idx4] = ((const float4*)vp)[idx4];
    }

    const float scale = 0.17677669529663687f;  // 1/sqrt(32)

    // PV decomposition indices
    const int seg = tid >> 6;          // y-segment 0..3
    const int t6  = tid & 63;
    const int rg  = t6 & 7;            // r-group: rows rg*4..rg*4+3
    const int cgp = t6 >> 3;           // c-group: cols cgp*4..cgp*4+3

    for (int ch = 0; ch < 8; ch++) {
        int r0 = ch * 32;

        // stage Q chunk transposed: sQT[c][fi]
        {
            int fi = tid >> 3, cq = tid & 7;
            float4 qv = *(const float4*)(qp + (size_t)(r0 + fi)*CHn + cq*4);
            sQT[(cq*4+0)*32 + fi] = qv.x;
            sQT[(cq*4+1)*32 + fi] = qv.y;
            sQT[(cq*4+2)*32 + fi] = qv.z;
            sQT[(cq*4+3)*32 + fi] = qv.w;
        }
        __syncthreads();   // (1) sQT ready; prev chunk's sPart reads done

        const int qmax = CAUSAL ? ((r0 + 95) >> 6) : 4;

        // ---- score GEMM: warp w -> rows w*4..w*4+3,
        //      quarter q -> cols q*64 + lane*2 + {0,1}
        float acc[4][8];
        #pragma unroll
        for (int i = 0; i < 4; i++)
            #pragma unroll
            for (int j = 0; j < 8; j++) acc[i][j] = 0.f;

        for (int q = 0; q < qmax; q++) {
            const __nv_bfloat162* kq =
                (const __nv_bfloat162*)&sK[q*64 + lane*2];
            #pragma unroll 8
            for (int c = 0; c < 32; c++) {
                float4 A  = *(const float4*)&sQT[c*32 + w*4];
                float2 Bv = __bfloat1622float2(kq[c*128]);  // 256 bf16 = 128 bf162 per row
                acc[0][q*2+0] = fmaf(A.x, Bv.x, acc[0][q*2+0]);
                acc[0][q*2+1] = fmaf(A.x, Bv.y, acc[0][q*2+1]);
                acc[1][q*2+0] = fmaf(A.y, Bv.x, acc[1][q*2+0]);
                acc[1][q*2+1] = fmaf(A.y, Bv.y, acc[1][q*2+1]);
                acc[2][q*2+0] = fmaf(A.z, Bv.x, acc[2][q*2+0]);
                acc[2][q*2+1] = fmaf(A.z, Bv.y, acc[2][q*2+1]);
                acc[3][q*2+0] = fmaf(A.w, Bv.x, acc[3][q*2+0]);
                acc[3][q*2+1] = fmaf(A.w, Bv.y, acc[3][q*2+1]);
            }
        }

        // ---- register softmax; write P transposed bf16 (sP[y][r], pitch 33)
        #pragma unroll
        for (int i = 0; i < 4; i++) {
            int r  = w*4 + i;
            int tg = r0 + r;
            float mx = -1e30f;
            #pragma unroll
            for (int q = 0; q < 4; q++) {
                if (q < qmax) {
                    #pragma unroll
                    for (int v = 0; v < 2; v++) {
                        int y = q*64 + lane*2 + v;
                        float s = acc[i][q*2+v] * scale;
                        if (CAUSAL && y > tg) s = -1e30f;
                        acc[i][q*2+v] = s;
                        mx = fmaxf(mx, s);
                    }
                }
            }
            #pragma unroll
            for (int off = 16; off > 0; off >>= 1)
                mx = fmaxf(mx, __shfl_xor_sync(0xffffffffu, mx, off));

            float sum = 0.f;
            #pragma unroll
            for (int q = 0; q < 4; q++) {
                if (q < qmax) {
                    int y0 = q*64 + lane*2;
                    float e0 = __expf(acc[i][q*2+0] - mx);
                    float e1 = __expf(acc[i][q*2+1] - mx);
                    sum += e0 + e1;
                    sP[(y0+0)*33 + r] = __float2bfloat16(e0);
                    sP[(y0+1)*33 + r] = __float2bfloat16(e1);
                }
            }
            #pragma unroll
            for (int off = 16; off > 0; off >>= 1)
                sum += __shfl_xor_sync(0xffffffffu, sum, off);
            if (lane == 0) sInv[r] = 1.f / sum;
        }
        __syncthreads();   // (2) P ready

        // ---- PV: segment seg covers y in [seg*64, seg*64+64) clipped
        float a0x=0.f,a0y=0.f,a0z=0.f,a0w=0.f;
        float a1x=0.f,a1y=0.f,a1z=0.f,a1w=0.f;
        float a2x=0.f,a2y=0.f,a2z=0.f,a2w=0.f;
        float a3x=0.f,a3y=0.f,a3z=0.f,a3w=0.f;
        {
            int ys = seg * 64;
            int ye = CAUSAL ? min(ys + 64, r0 + 32) : (ys + 64);
            const __nv_bfloat16* pbase = sP + rg*4;
            const float* vbase = sV + cgp*4;
            #pragma unroll 4
            for (int y = ys; y < ye; y++) {
                const __nv_bfloat16* pr = pbase + y*33;
                float p0 = __bfloat162float(pr[0]);
                float p1 = __bfloat162float(pr[1]);
                float p2 = __bfloat162float(pr[2]);
                float p3 = __bfloat162float(pr[3]);
                float4 v = *(const float4*)(vbase + y*32);
                a0x = fmaf(p0, v.x, a0x); a0y = fmaf(p0, v.y, a0y);
                a0z = fmaf(p0, v.z, a0z); a0w = fmaf(p0, v.w, a0w);
                a1x = fmaf(p1, v.x, a1x); a1y = fmaf(p1, v.y, a1y);
                a1z = fmaf(p1, v.z, a1z); a1w = fmaf(p1, v.w, a1w);
                a2x = fmaf(p2, v.x, a2x); a2y = fmaf(p2, v.y, a2y);
                a2z = fmaf(p2, v.z, a2z); a2w = fmaf(p2, v.w, a2w);
                a3x = fmaf(p3, v.x, a3x); a3y = fmaf(p3, v.y, a3y);
                a3z = fmaf(p3, v.z, a3z); a3w = fmaf(p3, v.w, a3w);
            }
        }
        __syncthreads();   // (3) all P reads done; sP reusable as sPart

        // store partials
        {
            float* pb = &sPart[seg*1024 + rg*4*32 + cgp*4];
            *(float4*)(pb + 0*32) = make_float4(a0x,a0y,a0z,a0w);
            *(float4*)(pb + 1*32) = make_float4(a1x,a1y,a1z,a1w);
            *(float4*)(pb + 2*32) = make_float4(a2x,a2y,a2z,a2w);
            *(float4*)(pb + 3*32) = make_float4(a3x,a3y,a3z,a3w);
        }
        __syncthreads();   // (4) partials ready

        // reduce 4 segments + scale + write out
        {
            int r  = tid >> 3;
            int c0 = (tid & 7) * 4;
            float4 x0 = *(const float4*)&sPart[0*1024 + r*32 + c0];
            float4 x1 = *(const float4*)&sPart[1*1024 + r*32 + c0];
            float4 x2 = *(const float4*)&sPart[2*1024 + r*32 + c0];
            float4 x3 = *(const float4*)&sPart[3*1024 + r*32 + c0];
            float inv = sInv[r];
            float ox = (x0.x + x1.x + x2.x + x3.x) * inv;
            float oy = (x0.y + x1.y + x2.y + x3.y) * inv;
            float oz = (x0.z + x1.z + x2.z + x3.z) * inv;
            float ow = (x0.w + x1.w + x2.w + x3.w) * inv;
            *(float4*)(outg + out_base + (size_t)(r0 + r)*out_stride + c0) =
                make_float4(ox, oy, oz, ow);
        }
        // next iteration's sync (1) orders these reads vs next sP writes
    }
}

// =====================================================================
// Kernel 5: proj conv (32 -> 64) + BN + LeakyReLU + residual. (unchanged)
// =====================================================================
__global__ void __launch_bounds__(256) proj_kernel(
    const float* __restrict__ xin,
    const float* __restrict__ W,  const float* __restrict__ bb,
    const float* __restrict__ gg, const float* __restrict__ be,
    const float* __restrict__ mm, const float* __restrict__ vv,
    const float* __restrict__ aa,
    float* __restrict__ outp)
{
    __shared__ float sW[32][64];
    __shared__ float sIn[32][132];
    __shared__ float sBias[64];
    __shared__ float sAlpha;

    int tid = threadIdx.x;
    int tile = blockIdx.x, b = blockIdx.y;
    int p0 = tile * 128;

    for (int idx = tid; idx < 2048; idx += 256) {
        int o = idx & 63, k = idx >> 6;
        float sc = gg[o] * rsqrtf(vv[o] + EPSc);
        sW[k][o] = W[o*32 + k] * sc;
    }
    if (tid < 64) {
        float sc = gg[tid] * rsqrtf(vv[tid] + EPSc);
        sBias[tid] = (bb[tid] - mm[tid]) * sc + be[tid];
    }
    if (tid == 0) sAlpha = aa[0];

    const float* tp = g_tout + ((size_t)b*Sn + p0) * CHn;
    #pragma unroll
    for (int jj = 0; jj < 4; jj++) {
        int idx4 = tid + jj*256;
        int p = idx4 >> 3, cq = idx4 & 7;
        float4 tv = ((const float4*)tp)[idx4];
        sIn[cq*4+0][p] = tv.x;
        sIn[cq*4+1][p] = tv.y;
        sIn[cq*4+2][p] = tv.z;
        sIn[cq*4+3][p] = tv.w;
    }
    __syncthreads();

    int lane = tid & 31, w = tid >> 5;
    float acc[8][4];
    #pragma unroll
    for (int i = 0; i < 8; i++)
        #pragma unroll
        for (int j = 0; j < 4; j++) acc[i][j] = 0.f;

    #pragma unroll 2
    for (int k = 0; k < 32; k++) {
        float4 A0 = *(const float4*)&sW[k][w*8];
        float4 A1 = *(const float4*)&sW[k][w*8 + 4];
        float4 Bv = *(const float4*)&sIn[k][lane*4];
        float av[8] = {A0.x,A0.y,A0.z,A0.w, A1.x,A1.y,A1.z,A1.w};
        float bv[4] = {Bv.x,Bv.y,Bv.z,Bv.w};
        #pragma unroll
        for (int i = 0; i < 8; i++)
            #pragma unroll
            for (int j = 0; j < 4; j++)
                acc[i][j] = fmaf(av[i], bv[j], acc[i][j]);
    }

    float alpha = sAlpha;
    const float* xb = xin + (size_t)b*Cn*Sn + p0 + lane*4;
    float*       ob = outp + (size_t)b*Cn*Sn + p0 + lane*4;
    #pragma unroll
    for (int i = 0; i < 8; i++) {
        int o = w*8 + i;
        float bias = sBias[o];
        float4 xr = *(const float4*)(xb + (size_t)o*Sn);
        float r0 = acc[i][0] + bias; r0 = (r0 > 0.f) ? r0 : alpha*r0; r0 += xr.x;
        float r1 = acc[i][1] + bias; r1 = (r1 > 0.f) ? r1 : alpha*r1; r1 += xr.y;
        float r2 = acc[i][2] + bias; r2 = (r2 > 0.f) ? r2 : alpha*r2; r2 += xr.z;
        float r3 = acc[i][3] + bias; r3 = (r3 > 0.f) ? r3 : alpha*r3; r3 += xr.w;
        *(float4*)(ob + (size_t)o*Sn) = make_float4(r0, r1, r2, r3);
    }
}

// =====================================================================
// Launch
// =====================================================================
extern "C" void kernel_launch(void* const* d_in, const int* in_sizes, int n_in,
                              void* d_out, int out_size) {
    const float* inp  = (const float*)d_in[0];
    const float* x    = (const float*)d_in[1];
    const float* fqkW = (const float*)d_in[2];
    const float* fqkb = (const float*)d_in[3];
    const float* fqkg = (const float*)d_in[4];
    const float* fqkbe= (const float*)d_in[5];
    const float* fqkm = (const float*)d_in[6];
    const float* fqkv = (const float*)d_in[7];
    const float* fqka = (const float*)d_in[8];
    const float* fvW  = (const float*)d_in[9];
    const float* fvb  = (const float*)d_in[10];
    const float* fvg  = (const float*)d_in[11];
    const float* fvbe = (const float*)d_in[12];
    const float* fvm  = (const float*)d_in[13];
    const float* fvv  = (const float*)d_in[14];
    const float* fva  = (const float*)d_in[15];
    const float* tqkW = (const float*)d_in[16];
    const float* tqkb = (const float*)d_in[17];
    const float* tqkg = (const float*)d_in[18];
    const float* tqkbe= (const float*)d_in[19];
    const float* tqkm = (const float*)d_in[20];
    const float* tqkv = (const float*)d_in[21];
    const float* tqka = (const float*)d_in[22];
    const float* prW  = (const float*)d_in[23];
    const float* prb  = (const float*)d_in[24];
    const float* prg  = (const float*)d_in[25];
    const float* prbe = (const float*)d_in[26];
    const float* prm  = (const float*)d_in[27];
    const float* prv  = (const float*)d_in[28];
    const float* pra  = (const float*)d_in[29];
    float* out = (float*)d_out;

    cudaFuncSetAttribute(conv_qk_kernel,
                         cudaFuncAttributeMaxDynamicSharedMemorySize, QK_SMEM);
    cudaFuncSetAttribute(conv_v_kernel,
                         cudaFuncAttributeMaxDynamicSharedMemorySize, CV_SMEM);
    cudaFuncSetAttribute(attn_kernel<false>,
                         cudaFuncAttributeMaxDynamicSharedMemorySize, ATTN_SMEM);
    cudaFuncSetAttribute(attn_kernel<true>,
                         cudaFuncAttributeMaxDynamicSharedMemorySize, ATTN_SMEM);

    conv_qk_kernel<<<dim3(512, Bn), 256, QK_SMEM>>>(inp,
        fqkW, fqkb, fqkg, fqkbe, fqkm, fqkv, fqka,
        tqkW, tqkb, tqkg, tqkbe, tqkm, tqkv, tqka);

    conv_v_kernel<<<dim3(256, Bn), 256, CV_SMEM>>>(x,
        fvW, fvb, fvg, fvbe, fvm, fvv, fva);

    attn_kernel<false><<<dim3(256, Bn), 256, ATTN_SMEM>>>();

    attn_kernel<true><<<dim3(256, Bn), 256, ATTN_SMEM>>>();

    proj_kernel<<<dim3(512, Bn), 256>>>(x,
        prW, prb, prg, prbe, prm, prv, pra, out);
}

// round 9
// speedup vs baseline: 1.4262x; 1.0787x over previous
#include <cuda_runtime.h>
#include <cuda_bf16.h>
#include <cstdint>

// Problem constants
constexpr int Bn  = 4;
constexpr int Cn  = 64;
constexpr int CHn = 32;
constexpr int Fn  = 256;
constexpr int Tn  = 256;
constexpr int Sn  = Fn * Tn;
constexpr float EPSc = 1e-5f;

// ---- packed fp32x2 helpers (FFMA2 path; precision identical to FFMA) ----
__device__ __forceinline__ unsigned long long pk2(float lo, float hi) {
    unsigned long long r;
    asm("mov.b64 %0, {%1, %2};" : "=l"(r) : "f"(lo), "f"(hi));
    return r;
}
__device__ __forceinline__ void upk2(unsigned long long v, float& lo, float& hi) {
    asm("mov.b64 {%0, %1}, %2;" : "=f"(lo), "=f"(hi) : "l"(v));
}
__device__ __forceinline__ unsigned long long fma2(
    unsigned long long a, unsigned long long b, unsigned long long c) {
    unsigned long long d;
    asm("fma.rn.f32x2 %0, %1, %2, %3;" : "=l"(d) : "l"(a), "l"(b), "l"(c));
    return d;
}

// -------- device scratch --------
__device__ float g_qf[Bn*Tn*Fn*CHn];
__device__ float g_kf[Bn*Tn*Fn*CHn];
__device__ float g_vf[Bn*Tn*Fn*CHn];
__device__ float g_qt[Bn*Fn*Tn*CHn];
__device__ float g_kt[Bn*Fn*Tn*CHn];
__device__ float g_fout[Bn*Fn*Tn*CHn];
__device__ float g_tout[Bn*Fn*Tn*CHn];

// dynamic-smem sizes (bytes)
constexpr int QK_SMEM   = (64*128 + 64*128 + 128 + 2) * 4;        // 66056
constexpr int CV_SMEM   = (64*32 + 64*256 + 32 + 1) * 4;          // 73860
constexpr int ATTN_SMEM = 70272;  // layout as v4 (bf16 K/P, f32 V/QT/Inv)

// =====================================================================
// Kernel 1: fused fqk + tqk pointwise conv + BN + LeakyReLU. (f32x2 GEMM)
// =====================================================================
__global__ void __launch_bounds__(256) conv_qk_kernel(
    const float* __restrict__ inp,
    const float* __restrict__ W1, const float* __restrict__ b1,
    const float* __restrict__ g1, const float* __restrict__ be1,
    const float* __restrict__ m1, const float* __restrict__ v1,
    const float* __restrict__ a1,
    const float* __restrict__ W2, const float* __restrict__ b2,
    const float* __restrict__ g2, const float* __restrict__ be2,
    const float* __restrict__ m2, const float* __restrict__ v2,
    const float* __restrict__ a2)
{
    extern __shared__ float smqk[];
    float* sW    = smqk;               // [64][128]
    float* sIn   = smqk + 64*128;      // [64][128]
    float* sBias = smqk + 2*64*128;    // [128]
    float* sAlpha= sBias + 128;        // [2]

    int tid  = threadIdx.x;
    int b    = blockIdx.y;
    int tile = blockIdx.x;
    int p0   = tile * 128;
    int f    = p0 >> 8;
    int t0   = p0 & 255;

    #pragma unroll 4
    for (int jj = 0; jj < 32; jj++) {
        int idx = tid + jj * 256;
        int k = idx >> 7;
        int o = idx & 127;
        float w;
        if (o < 64) {
            float sc = g1[o] * rsqrtf(v1[o] + EPSc);
            w = W1[o*64 + k] * sc;
        } else {
            int oo = o - 64;
            float sc = g2[oo] * rsqrtf(v2[oo] + EPSc);
            w = W2[oo*64 + k] * sc;
        }
        sW[k*128 + o] = w;
    }
    if (tid < 128) {
        int o = tid;
        float bias;
        if (o < 64) {
            float sc = g1[o] * rsqrtf(v1[o] + EPSc);
            bias = (b1[o] - m1[o]) * sc + be1[o];
        } else {
            int oo = o - 64;
            float sc = g2[oo] * rsqrtf(v2[oo] + EPSc);
            bias = (b2[oo] - m2[oo]) * sc + be2[oo];
        }
        sBias[o] = bias;
    }
    if (tid == 0) { sAlpha[0] = a1[0]; sAlpha[1] = a2[0]; }

    const float* ip = inp + (size_t)b * Cn * Sn + p0;
    #pragma unroll
    for (int jj = 0; jj < 8; jj++) {
        int idx4 = tid + jj * 256;
        int k  = idx4 >> 5;
        int pq = idx4 & 31;
        float4 val = *(const float4*)(ip + (size_t)k * Sn + pq * 4);
        *(float4*)&sIn[k*128 + pq*4] = val;
    }
    __syncthreads();

    int lane = tid & 31, w = tid >> 5;
    // accp[p][j] packs output-channel pair (2p, 2p+1) for position j
    unsigned long long accp[8][4];
    #pragma unroll
    for (int i = 0; i < 8; i++)
        #pragma unroll
        for (int j = 0; j < 4; j++) accp[i][j] = 0ull;

    #pragma unroll 2
    for (int k = 0; k < 64; k++) {
        float4 A0 = *(const float4*)&sW[k*128 + w*16 + 0];
        float4 A1 = *(const float4*)&sW[k*128 + w*16 + 4];
        float4 A2 = *(const float4*)&sW[k*128 + w*16 + 8];
        float4 A3 = *(const float4*)&sW[k*128 + w*16 + 12];
        float4 Bv = *(const float4*)&sIn[k*128 + lane*4];
        unsigned long long ap[8] = {
            pk2(A0.x,A0.y), pk2(A0.z,A0.w), pk2(A1.x,A1.y), pk2(A1.z,A1.w),
            pk2(A2.x,A2.y), pk2(A2.z,A2.w), pk2(A3.x,A3.y), pk2(A3.z,A3.w)};
        unsigned long long bd[4] = {
            pk2(Bv.x,Bv.x), pk2(Bv.y,Bv.y), pk2(Bv.z,Bv.z), pk2(Bv.w,Bv.w)};
        #pragma unroll
        for (int i = 0; i < 8; i++)
            #pragma unroll
            for (int j = 0; j < 4; j++)
                accp[i][j] = fma2(ap[i], bd[j], accp[i][j]);
    }

    // unpack
    float acc[16][4];
    #pragma unroll
    for (int i = 0; i < 8; i++)
        #pragma unroll
        for (int j = 0; j < 4; j++)
            upk2(accp[i][j], acc[2*i][j], acc[2*i+1][j]);

    float alpha = (w < 4) ? sAlpha[0] : sAlpha[1];
    #pragma unroll
    for (int i = 0; i < 16; i++) {
        float bias = sBias[w*16 + i];
        #pragma unroll
        for (int j = 0; j < 4; j++) {
            float y = acc[i][j] + bias;
            acc[i][j] = (y > 0.f) ? y : alpha * y;
        }
    }

    int t = t0 + lane * 4;
    if (w < 4) {
        int cb = w * 8;
        #pragma unroll
        for (int j = 0; j < 4; j++) {
            size_t off = (((size_t)b*Tn + (t+j))*Fn + f)*CHn + cb;
            *(float4*)(g_qf+off)   = make_float4(acc[0][j],acc[2][j],acc[4][j],acc[6][j]);
            *(float4*)(g_qf+off+4) = make_float4(acc[8][j],acc[10][j],acc[12][j],acc[14][j]);
            *(float4*)(g_kf+off)   = make_float4(acc[1][j],acc[3][j],acc[5][j],acc[7][j]);
            *(float4*)(g_kf+off+4) = make_float4(acc[9][j],acc[11][j],acc[13][j],acc[15][j]);
        }
    } else {
        int cb = (w - 4) * 8;
        #pragma unroll
        for (int j = 0; j < 4; j++) {
            size_t off = (((size_t)b*Fn + f)*Tn + (t+j))*CHn + cb;
            *(float4*)(g_qt+off)   = make_float4(acc[0][j],acc[2][j],acc[4][j],acc[6][j]);
            *(float4*)(g_qt+off+4) = make_float4(acc[8][j],acc[10][j],acc[12][j],acc[14][j]);
            *(float4*)(g_kt+off)   = make_float4(acc[1][j],acc[3][j],acc[5][j],acc[7][j]);
            *(float4*)(g_kt+off+4) = make_float4(acc[9][j],acc[11][j],acc[13][j],acc[15][j]);
        }
    }
}

// =====================================================================
// Kernel 2: fv conv (64 -> 32) + BN + LeakyReLU. (f32x2 GEMM)
// =====================================================================
__global__ void __launch_bounds__(256) conv_v_kernel(
    const float* __restrict__ xin,
    const float* __restrict__ W,  const float* __restrict__ bb,
    const float* __restrict__ gg, const float* __restrict__ be,
    const float* __restrict__ mm, const float* __restrict__ vv,
    const float* __restrict__ aa)
{
    extern __shared__ float smcv[];
    float* sW    = smcv;              // [64][32]
    float* sIn   = smcv + 64*32;      // [64][256]
    float* sBias = sIn + 64*256;      // [32]
    float* sAlpha= sBias + 32;        // [1]

    int tid = threadIdx.x;
    int f = blockIdx.x, b = blockIdx.y;

    for (int idx = tid; idx < 2048; idx += 256) {
        int k = idx >> 5, o = idx & 31;
        float sc = gg[o] * rsqrtf(vv[o] + EPSc);
        sW[k*32 + o] = W[o*64 + k] * sc;
    }
    if (tid < 32) {
        float sc = gg[tid] * rsqrtf(vv[tid] + EPSc);
        sBias[tid] = (bb[tid] - mm[tid]) * sc + be[tid];
    }
    if (tid == 0) sAlpha[0] = aa[0];

    const float* ip = xin + (size_t)b*Cn*Sn + (size_t)f*Tn;
    #pragma unroll
    for (int jj = 0; jj < 16; jj++) {
        int idx4 = tid + jj*256;
        int k = idx4 >> 6, pq = idx4 & 63;
        *(float4*)&sIn[k*256 + pq*4] = *(const float4*)(ip + (size_t)k*Sn + pq*4);
    }
    __syncthreads();

    int lane = tid & 31, w = tid >> 5;
    int cg = w & 3, ph = w >> 2;
    unsigned long long accp[4][4];   // channel pair (2p,2p+1) x position j
    #pragma unroll
    for (int i = 0; i < 4; i++)
        #pragma unroll
        for (int j = 0; j < 4; j++) accp[i][j] = 0ull;

    #pragma unroll 2
    for (int k = 0; k < 64; k++) {
        float4 A0 = *(const float4*)&sW[k*32 + cg*8];
        float4 A1 = *(const float4*)&sW[k*32 + cg*8 + 4];
        float4 Bv = *(const float4*)&sIn[k*256 + ph*128 + lane*4];
        unsigned long long ap[4] = {
            pk2(A0.x,A0.y), pk2(A0.z,A0.w), pk2(A1.x,A1.y), pk2(A1.z,A1.w)};
        unsigned long long bd[4] = {
            pk2(Bv.x,Bv.x), pk2(Bv.y,Bv.y), pk2(Bv.z,Bv.z), pk2(Bv.w,Bv.w)};
        #pragma unroll
        for (int i = 0; i < 4; i++)
            #pragma unroll
            for (int j = 0; j < 4; j++)
                accp[i][j] = fma2(ap[i], bd[j], accp[i][j]);
    }

    float acc[8][4];
    #pragma unroll
    for (int i = 0; i < 4; i++)
        #pragma unroll
        for (int j = 0; j < 4; j++)
            upk2(accp[i][j], acc[2*i][j], acc[2*i+1][j]);

    float alpha = sAlpha[0];
    int c = cg * 8;
    #pragma unroll
    for (int j = 0; j < 4; j++) {
        int t = ph*128 + lane*4 + j;
        float r[8];
        #pragma unroll
        for (int i = 0; i < 8; i++) {
            float y = acc[i][j] + sBias[c + i];
            r[i] = (y > 0.f) ? y : alpha * y;
        }
        size_t off = (((size_t)b*Tn + t)*Fn + f)*CHn + c;
        *(float4*)(g_vf + off)     = make_float4(r[0],r[1],r[2],r[3]);
        *(float4*)(g_vf + off + 4) = make_float4(r[4],r[5],r[6],r[7]);
    }
}

// =====================================================================
// Attention kernel — v5:
//  * as v4 (bf16 K/P staging, 3 blocks/SM, register softmax, split PV)
//  * score GEMM: c-outer loop (A loaded once per c, not per quarter),
//    FFMA2 packed over row pairs
//  * PV: FFMA2 packed over channel pairs
// =====================================================================
template<bool CAUSAL>
__global__ void __launch_bounds__(256, 3) attn_kernel()
{
    const float* __restrict__ qg = CAUSAL ? g_qt : g_qf;
    const float* __restrict__ kg = CAUSAL ? g_kt : g_kf;
    const float* __restrict__ vg = CAUSAL ? g_fout : g_vf;
    float* __restrict__ outg     = CAUSAL ? g_tout : g_fout;

    extern __shared__ char smb[];
    __nv_bfloat16* sK   = (__nv_bfloat16*)smb;            // [32][256]
    float*         sV   = (float*)(smb + 16384);          // [256][32]
    float*         sQT  = (float*)(smb + 49152);          // [32][32]
    __nv_bfloat16* sP   = (__nv_bfloat16*)(smb + 53248);  // [256][33]
    float*         sPart= (float*)(smb + 53248);          // [4][32][32] alias
    float*         sInv = (float*)(smb + 70144);          // [32]

    int tid = threadIdx.x, lane = tid & 31, w = tid >> 5;
    int col = blockIdx.x;
    int b   = blockIdx.y;
    size_t base = ((size_t)b * 256 + col) * 256 * CHn;
    const float* qp = qg + base;
    const float* kp = kg + base;
    const float* vp = vg + base;
    size_t out_base, out_stride;
    if (CAUSAL) { out_base = base; out_stride = CHn; }
    else { out_base = ((size_t)b * Sn + col) * CHn; out_stride = (size_t)Tn * CHn; }

    // Load K (transposed, bf16) and V (fp32)
    #pragma unroll
    for (int jj = 0; jj < 8; jj++) {
        int idx4 = tid + jj*256;
        int y = idx4 >> 3, cq = idx4 & 7;
        float4 kv = ((const float4*)kp)[idx4];
        sK[(cq*4+0)*256 + y] = __float2bfloat16(kv.x);
        sK[(cq*4+1)*256 + y] = __float2bfloat16(kv.y);
        sK[(cq*4+2)*256 + y] = __float2bfloat16(kv.z);
        sK[(cq*4+3)*256 + y] = __float2bfloat16(kv.w);
        ((float4*)sV)[idx4] = ((const float4*)vp)[idx4];
    }

    const float scale = 0.17677669529663687f;  // 1/sqrt(32)

    // PV decomposition indices
    const int seg = tid >> 6;
    const int t6  = tid & 63;
    const int rg  = t6 & 7;
    const int cgp = t6 >> 3;

    const __nv_bfloat162* sK2 = (const __nv_bfloat162*)sK;  // [c][128] bf162

    for (int ch = 0; ch < 8; ch++) {
        int r0 = ch * 32;

        // stage Q chunk transposed: sQT[c][fi]
        {
            int fi = tid >> 3, cq = tid & 7;
            float4 qv = *(const float4*)(qp + (size_t)(r0 + fi)*CHn + cq*4);
            sQT[(cq*4+0)*32 + fi] = qv.x;
            sQT[(cq*4+1)*32 + fi] = qv.y;
            sQT[(cq*4+2)*32 + fi] = qv.z;
            sQT[(cq*4+3)*32 + fi] = qv.w;
        }
        __syncthreads();   // (1)

        const int qmax = CAUSAL ? ((r0 + 95) >> 6) : 4;

        // ---- score GEMM (c-outer, FFMA2 over row pairs)
        // accp[p][q*2+v] packs rows (w*4+2p, w*4+2p+1) at col q*64+lane*2+v
        unsigned long long accp[2][8];
        #pragma unroll
        for (int p = 0; p < 2; p++)
            #pragma unroll
            for (int j = 0; j < 8; j++) accp[p][j] = 0ull;

        #pragma unroll 4
        for (int c = 0; c < 32; c++) {
            float4 A = *(const float4*)&sQT[c*32 + w*4];
            unsigned long long a01 = pk2(A.x, A.y);
            unsigned long long a23 = pk2(A.z, A.w);
            #pragma unroll
            for (int q = 0; q < 4; q++) {
                if (q < qmax) {
                    float2 Bv = __bfloat1622float2(sK2[c*128 + q*32 + lane]);
                    unsigned long long b0 = pk2(Bv.x, Bv.x);
                    unsigned long long b1 = pk2(Bv.y, Bv.y);
                    accp[0][q*2+0] = fma2(a01, b0, accp[0][q*2+0]);
                    accp[1][q*2+0] = fma2(a23, b0, accp[1][q*2+0]);
                    accp[0][q*2+1] = fma2(a01, b1, accp[0][q*2+1]);
                    accp[1][q*2+1] = fma2(a23, b1, accp[1][q*2+1]);
                }
            }
        }

        float acc[4][8];
        #pragma unroll
        for (int p = 0; p < 2; p++)
            #pragma unroll
            for (int j = 0; j < 8; j++)
                upk2(accp[p][j], acc[2*p][j], acc[2*p+1][j]);

        // ---- register softmax; write P transposed bf16 (pitch 33)
        #pragma unroll
        for (int i = 0; i < 4; i++) {
            int r  = w*4 + i;
            int tg = r0 + r;
            float mx = -1e30f;
            #pragma unroll
            for (int q = 0; q < 4; q++) {
                if (q < qmax) {
                    #pragma unroll
                    for (int v = 0; v < 2; v++) {
                        int y = q*64 + lane*2 + v;
                        float s = acc[i][q*2+v] * scale;
                        if (CAUSAL && y > tg) s = -1e30f;
                        acc[i][q*2+v] = s;
                        mx = fmaxf(mx, s);
                    }
                }
            }
            #pragma unroll
            for (int off = 16; off > 0; off >>= 1)
                mx = fmaxf(mx, __shfl_xor_sync(0xffffffffu, mx, off));

            float sum = 0.f;
            #pragma unroll
            for (int q = 0; q < 4; q++) {
                if (q < qmax) {
                    int y0 = q*64 + lane*2;
                    float e0 = __expf(acc[i][q*2+0] - mx);
                    float e1 = __expf(acc[i][q*2+1] - mx);
                    sum += e0 + e1;
                    sP[(y0+0)*33 + r] = __float2bfloat16(e0);
                    sP[(y0+1)*33 + r] = __float2bfloat16(e1);
                }
            }
            #pragma unroll
            for (int off = 16; off > 0; off >>= 1)
                sum += __shfl_xor_sync(0xffffffffu, sum, off);
            if (lane == 0) sInv[r] = 1.f / sum;
        }
        __syncthreads();   // (2) P ready

        // ---- PV (FFMA2 over channel pairs)
        unsigned long long plo[4] = {0ull,0ull,0ull,0ull}; // rows x cols (c0,c0+1)
        unsigned long long phi[4] = {0ull,0ull,0ull,0ull}; // rows x cols (c0+2,c0+3)
        {
            int ys = seg * 64;
            int ye = CAUSAL ? min(ys + 64, r0 + 32) : (ys + 64);
            const __nv_bfloat16* pbase = sP + rg*4;
            const float* vbase = sV + cgp*4;
            #pragma unroll 4
            for (int y = ys; y < ye; y++) {
                const __nv_bfloat16* pr = pbase + y*33;
                float p0 = __bfloat162float(pr[0]);
                float p1 = __bfloat162float(pr[1]);
                float p2 = __bfloat162float(pr[2]);
                float p3 = __bfloat162float(pr[3]);
                float4 v = *(const float4*)(vbase + y*32);
                unsigned long long vlo = pk2(v.x, v.y);
                unsigned long long vhi = pk2(v.z, v.w);
                unsigned long long d0 = pk2(p0, p0);
                unsigned long long d1 = pk2(p1, p1);
                unsigned long long d2 = pk2(p2, p2);
                unsigned long long d3 = pk2(p3, p3);
                plo[0] = fma2(d0, vlo, plo[0]); phi[0] = fma2(d0, vhi, phi[0]);
                plo[1] = fma2(d1, vlo, plo[1]); phi[1] = fma2(d1, vhi, phi[1]);
                plo[2] = fma2(d2, vlo, plo[2]); phi[2] = fma2(d2, vhi, phi[2]);
                plo[3] = fma2(d3, vlo, plo[3]); phi[3] = fma2(d3, vhi, phi[3]);
            }
        }
        __syncthreads();   // (3) P reads done; sP reusable as sPart

        // store partials
        {
            float* pb = &sPart[seg*1024 + rg*4*32 + cgp*4];
            #pragma unroll
            for (int i = 0; i < 4; i++) {
                float x0, x1, x2, x3;
                upk2(plo[i], x0, x1);
                upk2(phi[i], x2, x3);
                *(float4*)(pb + i*32) = make_float4(x0, x1, x2, x3);
            }
        }
        __syncthreads();   // (4) partials ready

        // reduce 4 segments + scale + write out
        {
            int r  = tid >> 3;
            int c0 = (tid & 7) * 4;
            float4 x0 = *(const float4*)&sPart[0*1024 + r*32 + c0];
            float4 x1 = *(const float4*)&sPart[1*1024 + r*32 + c0];
            float4 x2 = *(const float4*)&sPart[2*1024 + r*32 + c0];
            float4 x3 = *(const float4*)&sPart[3*1024 + r*32 + c0];
            float inv = sInv[r];
            float ox = (x0.x + x1.x + x2.x + x3.x) * inv;
            float oy = (x0.y + x1.y + x2.y + x3.y) * inv;
            float oz = (x0.z + x1.z + x2.z + x3.z) * inv;
            float ow = (x0.w + x1.w + x2.w + x3.w) * inv;
            *(float4*)(outg + out_base + (size_t)(r0 + r)*out_stride + c0) =
                make_float4(ox, oy, oz, ow);
        }
    }
}

// =====================================================================
// Kernel 5: proj conv (32 -> 64) + BN + LeakyReLU + residual. (f32x2)
// =====================================================================
__global__ void __launch_bounds__(256) proj_kernel(
    const float* __restrict__ xin,
    const float* __restrict__ W,  const float* __restrict__ bb,
    const float* __restrict__ gg, const float* __restrict__ be,
    const float* __restrict__ mm, const float* __restrict__ vv,
    const float* __restrict__ aa,
    float* __restrict__ outp)
{
    __shared__ float sW[32][64];
    __shared__ float sIn[32][132];
    __shared__ float sBias[64];
    __shared__ float sAlpha;

    int tid = threadIdx.x;
    int tile = blockIdx.x, b = blockIdx.y;
    int p0 = tile * 128;

    for (int idx = tid; idx < 2048; idx += 256) {
        int o = idx & 63, k = idx >> 6;
        float sc = gg[o] * rsqrtf(vv[o] + EPSc);
        sW[k][o] = W[o*32 + k] * sc;
    }
    if (tid < 64) {
        float sc = gg[tid] * rsqrtf(vv[tid] + EPSc);
        sBias[tid] = (bb[tid] - mm[tid]) * sc + be[tid];
    }
    if (tid == 0) sAlpha = aa[0];

    const float* tp = g_tout + ((size_t)b*Sn + p0) * CHn;
    #pragma unroll
    for (int jj = 0; jj < 4; jj++) {
        int idx4 = tid + jj*256;
        int p = idx4 >> 3, cq = idx4 & 7;
        float4 tv = ((const float4*)tp)[idx4];
        sIn[cq*4+0][p] = tv.x;
        sIn[cq*4+1][p] = tv.y;
        sIn[cq*4+2][p] = tv.z;
        sIn[cq*4+3][p] = tv.w;
    }
    __syncthreads();

    int lane = tid & 31, w = tid >> 5;
    unsigned long long accp[4][4];   // channel pair x position
    #pragma unroll
    for (int i = 0; i < 4; i++)
        #pragma unroll
        for (int j = 0; j < 4; j++) accp[i][j] = 0ull;

    #pragma unroll 2
    for (int k = 0; k < 32; k++) {
        float4 A0 = *(const float4*)&sW[k][w*8];
        float4 A1 = *(const float4*)&sW[k][w*8 + 4];
        float4 Bv = *(const float4*)&sIn[k][lane*4];
        unsigned long long ap[4] = {
            pk2(A0.x,A0.y), pk2(A0.z,A0.w), pk2(A1.x,A1.y), pk2(A1.z,A1.w)};
        unsigned long long bd[4] = {
            pk2(Bv.x,Bv.x), pk2(Bv.y,Bv.y), pk2(Bv.z,Bv.z), pk2(Bv.w,Bv.w)};
        #pragma unroll
        for (int i = 0; i < 4; i++)
            #pragma unroll
            for (int j = 0; j < 4; j++)
                accp[i][j] = fma2(ap[i], bd[j], accp[i][j]);
    }

    float acc[8][4];
    #pragma unroll
    for (int i = 0; i < 4; i++)
        #pragma unroll
        for (int j = 0; j < 4; j++)
            upk2(accp[i][j], acc[2*i][j], acc[2*i+1][j]);

    float alpha = sAlpha;
    const float* xb = xin + (size_t)b*Cn*Sn + p0 + lane*4;
    float*       ob = outp + (size_t)b*Cn*Sn + p0 + lane*4;
    #pragma unroll
    for (int i = 0; i < 8; i++) {
        int o = w*8 + i;
        float bias = sBias[o];
        float4 xr = *(const float4*)(xb + (size_t)o*Sn);
        float r0 = acc[i][0] + bias; r0 = (r0 > 0.f) ? r0 : alpha*r0; r0 += xr.x;
        float r1 = acc[i][1] + bias; r1 = (r1 > 0.f) ? r1 : alpha*r1; r1 += xr.y;
        float r2 = acc[i][2] + bias; r2 = (r2 > 0.f) ? r2 : alpha*r2; r2 += xr.z;
        float r3 = acc[i][3] + bias; r3 = (r3 > 0.f) ? r3 : alpha*r3; r3 += xr.w;
        *(float4*)(ob + (size_t)o*Sn) = make_float4(r0, r1, r2, r3);
    }
}

// =====================================================================
// Launch
// =====================================================================
extern "C" void kernel_launch(void* const* d_in, const int* in_sizes, int n_in,
                              void* d_out, int out_size) {
    const float* inp  = (const float*)d_in[0];
    const float* x    = (const float*)d_in[1];
    const float* fqkW = (const float*)d_in[2];
    const float* fqkb = (const float*)d_in[3];
    const float* fqkg = (const float*)d_in[4];
    const float* fqkbe= (const float*)d_in[5];
    const float* fqkm = (const float*)d_in[6];
    const float* fqkv = (const float*)d_in[7];
    const float* fqka = (const float*)d_in[8];
    const float* fvW  = (const float*)d_in[9];
    const float* fvb  = (const float*)d_in[10];
    const float* fvg  = (const float*)d_in[11];
    const float* fvbe = (const float*)d_in[12];
    const float* fvm  = (const float*)d_in[13];
    const float* fvv  = (const float*)d_in[14];
    const float* fva  = (const float*)d_in[15];
    const float* tqkW = (const float*)d_in[16];
    const float* tqkb = (const float*)d_in[17];
    const float* tqkg = (const float*)d_in[18];
    const float* tqkbe= (const float*)d_in[19];
    const float* tqkm = (const float*)d_in[20];
    const float* tqkv = (const float*)d_in[21];
    const float* tqka = (const float*)d_in[22];
    const float* prW  = (const float*)d_in[23];
    const float* prb  = (const float*)d_in[24];
    const float* prg  = (const float*)d_in[25];
    const float* prbe = (const float*)d_in[26];
    const float* prm  = (const float*)d_in[27];
    const float* prv  = (const float*)d_in[28];
    const float* pra  = (const float*)d_in[29];
    float* out = (float*)d_out;

    cudaFuncSetAttribute(conv_qk_kernel,
                         cudaFuncAttributeMaxDynamicSharedMemorySize, QK_SMEM);
    cudaFuncSetAttribute(conv_v_kernel,
                         cudaFuncAttributeMaxDynamicSharedMemorySize, CV_SMEM);
    cudaFuncSetAttribute(attn_kernel<false>,
                         cudaFuncAttributeMaxDynamicSharedMemorySize, ATTN_SMEM);
    cudaFuncSetAttribute(attn_kernel<true>,
                         cudaFuncAttributeMaxDynamicSharedMemorySize, ATTN_SMEM);

    conv_qk_kernel<<<dim3(512, Bn), 256, QK_SMEM>>>(inp,
        fqkW, fqkb, fqkg, fqkbe, fqkm, fqkv, fqka,
        tqkW, tqkb, tqkg, tqkbe, tqkm, tqkv, tqka);

    conv_v_kernel<<<dim3(256, Bn), 256, CV_SMEM>>>(x,
        fvW, fvb, fvg, fvbe, fvm, fvv, fva);

    attn_kernel<false><<<dim3(256, Bn), 256, ATTN_SMEM>>>();

    attn_kernel<true><<<dim3(256, Bn), 256, ATTN_SMEM>>>();

    proj_kernel<<<dim3(512, Bn), 256>>>(x,
        prW, prb, prg, prbe, prm, prv, pra, out);
}

// round 10
// speedup vs baseline: 2.5181x; 1.7655x over previous
#include <cuda_runtime.h>
#include <cuda_bf16.h>
#include <cstdint>

// Problem constants
constexpr int Bn  = 4;
constexpr int Cn  = 64;
constexpr int CHn = 32;
constexpr int Fn  = 256;
constexpr int Tn  = 256;
constexpr int Sn  = Fn * Tn;
constexpr float EPSc = 1e-5f;

// ---- packed fp32x2 helpers (FFMA2) ----
__device__ __forceinline__ unsigned long long pk2(float lo, float hi) {
    unsigned long long r;
    asm("mov.b64 %0, {%1, %2};" : "=l"(r) : "f"(lo), "f"(hi));
    return r;
}
__device__ __forceinline__ void upk2(unsigned long long v, float& lo, float& hi) {
    asm("mov.b64 {%0, %1}, %2;" : "=f"(lo), "=f"(hi) : "l"(v));
}
__device__ __forceinline__ unsigned long long fma2(
    unsigned long long a, unsigned long long b, unsigned long long c) {
    unsigned long long d;
    asm("fma.rn.f32x2 %0, %1, %2, %3;" : "=l"(d) : "l"(a), "l"(b), "l"(c));
    return d;
}

// ---- tensor-core helpers ----
__device__ __forceinline__ void ldsm4(uint32_t* r, uint32_t addr) {
    asm volatile("ldmatrix.sync.aligned.m8n8.x4.shared.b16 {%0,%1,%2,%3}, [%4];\n"
        : "=r"(r[0]), "=r"(r[1]), "=r"(r[2]), "=r"(r[3]) : "r"(addr));
}
__device__ __forceinline__ void mma_bf16(float* d, const uint32_t* a, const uint32_t* b) {
    asm volatile(
        "mma.sync.aligned.m16n8k16.row.col.f32.bf16.bf16.f32 "
        "{%0,%1,%2,%3}, {%4,%5,%6,%7}, {%8,%9}, {%0,%1,%2,%3};\n"
        : "+f"(d[0]), "+f"(d[1]), "+f"(d[2]), "+f"(d[3])
        : "r"(a[0]), "r"(a[1]), "r"(a[2]), "r"(a[3]), "r"(b[0]), "r"(b[1]));
}

// -------- device scratch --------
__device__ float g_qf[Bn*Tn*Fn*CHn];
__device__ float g_kf[Bn*Tn*Fn*CHn];
__device__ float g_vf[Bn*Tn*Fn*CHn];
__device__ float g_qt[Bn*Fn*Tn*CHn];
__device__ float g_kt[Bn*Fn*Tn*CHn];
__device__ float g_fout[Bn*Fn*Tn*CHn];
__device__ float g_tout[Bn*Fn*Tn*CHn];

// dynamic-smem sizes (bytes)
constexpr int QK_SMEM   = (64*128 + 64*128 + 128 + 2) * 4;        // 66056
constexpr int CV_SMEM   = (64*32 + 64*256 + 32 + 1) * 4;          // 73860
// attn smem byte layout:
//   sK  bf16 [256][40]  : [0, 20480)
//   sVT bf16 [32][264]  : [20480, 37376)   (V transposed: [c][y])
//   sQ  bf16 [32][40]   : [37376, 39936)
//   sP  bf16 [32][264]  : [39936, 56832)
//   sMaxP f32 [8][32]   : [56832, 57856)
//   sSumP f32 [8][32]   : [57856, 58880)
//   sPartO f32 [2][32][32] : [58880, 67072)
constexpr int ATTN_SMEM = 67072;

// =====================================================================
// Kernel 1: fused fqk + tqk pointwise conv + BN + LeakyReLU. (f32x2)
// =====================================================================
__global__ void __launch_bounds__(256) conv_qk_kernel(
    const float* __restrict__ inp,
    const float* __restrict__ W1, const float* __restrict__ b1,
    const float* __restrict__ g1, const float* __restrict__ be1,
    const float* __restrict__ m1, const float* __restrict__ v1,
    const float* __restrict__ a1,
    const float* __restrict__ W2, const float* __restrict__ b2,
    const float* __restrict__ g2, const float* __restrict__ be2,
    const float* __restrict__ m2, const float* __restrict__ v2,
    const float* __restrict__ a2)
{
    extern __shared__ float smqk[];
    float* sW    = smqk;               // [64][128]
    float* sIn   = smqk + 64*128;      // [64][128]
    float* sBias = smqk + 2*64*128;    // [128]
    float* sAlpha= sBias + 128;        // [2]

    int tid  = threadIdx.x;
    int b    = blockIdx.y;
    int tile = blockIdx.x;
    int p0   = tile * 128;
    int f    = p0 >> 8;
    int t0   = p0 & 255;

    #pragma unroll 4
    for (int jj = 0; jj < 32; jj++) {
        int idx = tid + jj * 256;
        int k = idx >> 7;
        int o = idx & 127;
        float w;
        if (o < 64) {
            float sc = g1[o] * rsqrtf(v1[o] + EPSc);
            w = W1[o*64 + k] * sc;
        } else {
            int oo = o - 64;
            float sc = g2[oo] * rsqrtf(v2[oo] + EPSc);
            w = W2[oo*64 + k] * sc;
        }
        sW[k*128 + o] = w;
    }
    if (tid < 128) {
        int o = tid;
        float bias;
        if (o < 64) {
            float sc = g1[o] * rsqrtf(v1[o] + EPSc);
            bias = (b1[o] - m1[o]) * sc + be1[o];
        } else {
            int oo = o - 64;
            float sc = g2[oo] * rsqrtf(v2[oo] + EPSc);
            bias = (b2[oo] - m2[oo]) * sc + be2[oo];
        }
        sBias[o] = bias;
    }
    if (tid == 0) { sAlpha[0] = a1[0]; sAlpha[1] = a2[0]; }

    const float* ip = inp + (size_t)b * Cn * Sn + p0;
    #pragma unroll
    for (int jj = 0; jj < 8; jj++) {
        int idx4 = tid + jj * 256;
        int k  = idx4 >> 5;
        int pq = idx4 & 31;
        float4 val = *(const float4*)(ip + (size_t)k * Sn + pq * 4);
        *(float4*)&sIn[k*128 + pq*4] = val;
    }
    __syncthreads();

    int lane = tid & 31, w = tid >> 5;
    unsigned long long accp[8][4];
    #pragma unroll
    for (int i = 0; i < 8; i++)
        #pragma unroll
        for (int j = 0; j < 4; j++) accp[i][j] = 0ull;

    #pragma unroll 2
    for (int k = 0; k < 64; k++) {
        float4 A0 = *(const float4*)&sW[k*128 + w*16 + 0];
        float4 A1 = *(const float4*)&sW[k*128 + w*16 + 4];
        float4 A2 = *(const float4*)&sW[k*128 + w*16 + 8];
        float4 A3 = *(const float4*)&sW[k*128 + w*16 + 12];
        float4 Bv = *(const float4*)&sIn[k*128 + lane*4];
        unsigned long long ap[8] = {
            pk2(A0.x,A0.y), pk2(A0.z,A0.w), pk2(A1.x,A1.y), pk2(A1.z,A1.w),
            pk2(A2.x,A2.y), pk2(A2.z,A2.w), pk2(A3.x,A3.y), pk2(A3.z,A3.w)};
        unsigned long long bd[4] = {
            pk2(Bv.x,Bv.x), pk2(Bv.y,Bv.y), pk2(Bv.z,Bv.z), pk2(Bv.w,Bv.w)};
        #pragma unroll
        for (int i = 0; i < 8; i++)
            #pragma unroll
            for (int j = 0; j < 4; j++)
                accp[i][j] = fma2(ap[i], bd[j], accp[i][j]);
    }

    float acc[16][4];
    #pragma unroll
    for (int i = 0; i < 8; i++)
        #pragma unroll
        for (int j = 0; j < 4; j++)
            upk2(accp[i][j], acc[2*i][j], acc[2*i+1][j]);

    float alpha = (w < 4) ? sAlpha[0] : sAlpha[1];
    #pragma unroll
    for (int i = 0; i < 16; i++) {
        float bias = sBias[w*16 + i];
        #pragma unroll
        for (int j = 0; j < 4; j++) {
            float y = acc[i][j] + bias;
            acc[i][j] = (y > 0.f) ? y : alpha * y;
        }
    }

    int t = t0 + lane * 4;
    if (w < 4) {
        int cb = w * 8;
        #pragma unroll
        for (int j = 0; j < 4; j++) {
            size_t off = (((size_t)b*Tn + (t+j))*Fn + f)*CHn + cb;
            *(float4*)(g_qf+off)   = make_float4(acc[0][j],acc[2][j],acc[4][j],acc[6][j]);
            *(float4*)(g_qf+off+4) = make_float4(acc[8][j],acc[10][j],acc[12][j],acc[14][j]);
            *(float4*)(g_kf+off)   = make_float4(acc[1][j],acc[3][j],acc[5][j],acc[7][j]);
            *(float4*)(g_kf+off+4) = make_float4(acc[9][j],acc[11][j],acc[13][j],acc[15][j]);
        }
    } else {
        int cb = (w - 4) * 8;
        #pragma unroll
        for (int j = 0; j < 4; j++) {
            size_t off = (((size_t)b*Fn + f)*Tn + (t+j))*CHn + cb;
            *(float4*)(g_qt+off)   = make_float4(acc[0][j],acc[2][j],acc[4][j],acc[6][j]);
            *(float4*)(g_qt+off+4) = make_float4(acc[8][j],acc[10][j],acc[12][j],acc[14][j]);
            *(float4*)(g_kt+off)   = make_float4(acc[1][j],acc[3][j],acc[5][j],acc[7][j]);
            *(float4*)(g_kt+off+4) = make_float4(acc[9][j],acc[11][j],acc[13][j],acc[15][j]);
        }
    }
}

// =====================================================================
// Kernel 2: fv conv (64 -> 32) + BN + LeakyReLU. (f32x2)
// =====================================================================
__global__ void __launch_bounds__(256) conv_v_kernel(
    const float* __restrict__ xin,
    const float* __restrict__ W,  const float* __restrict__ bb,
    const float* __restrict__ gg, const float* __restrict__ be,
    const float* __restrict__ mm, const float* __restrict__ vv,
    const float* __restrict__ aa)
{
    extern __shared__ float smcv[];
    float* sW    = smcv;              // [64][32]
    float* sIn   = smcv + 64*32;      // [64][256]
    float* sBias = sIn + 64*256;      // [32]
    float* sAlpha= sBias + 32;        // [1]

    int tid = threadIdx.x;
    int f = blockIdx.x, b = blockIdx.y;

    for (int idx = tid; idx < 2048; idx += 256) {
        int k = idx >> 5, o = idx & 31;
        float sc = gg[o] * rsqrtf(vv[o] + EPSc);
        sW[k*32 + o] = W[o*64 + k] * sc;
    }
    if (tid < 32) {
        float sc = gg[tid] * rsqrtf(vv[tid] + EPSc);
        sBias[tid] = (bb[tid] - mm[tid]) * sc + be[tid];
    }
    if (tid == 0) sAlpha[0] = aa[0];

    const float* ip = xin + (size_t)b*Cn*Sn + (size_t)f*Tn;
    #pragma unroll
    for (int jj = 0; jj < 16; jj++) {
        int idx4 = tid + jj*256;
        int k = idx4 >> 6, pq = idx4 & 63;
        *(float4*)&sIn[k*256 + pq*4] = *(const float4*)(ip + (size_t)k*Sn + pq*4);
    }
    __syncthreads();

    int lane = tid & 31, w = tid >> 5;
    int cg = w & 3, ph = w >> 2;
    unsigned long long accp[4][4];
    #pragma unroll
    for (int i = 0; i < 4; i++)
        #pragma unroll
        for (int j = 0; j < 4; j++) accp[i][j] = 0ull;

    #pragma unroll 2
    for (int k = 0; k < 64; k++) {
        float4 A0 = *(const float4*)&sW[k*32 + cg*8];
        float4 A1 = *(const float4*)&sW[k*32 + cg*8 + 4];
        float4 Bv = *(const float4*)&sIn[k*256 + ph*128 + lane*4];
        unsigned long long ap[4] = {
            pk2(A0.x,A0.y), pk2(A0.z,A0.w), pk2(A1.x,A1.y), pk2(A1.z,A1.w)};
        unsigned long long bd[4] = {
            pk2(Bv.x,Bv.x), pk2(Bv.y,Bv.y), pk2(Bv.z,Bv.z), pk2(Bv.w,Bv.w)};
        #pragma unroll
        for (int i = 0; i < 4; i++)
            #pragma unroll
            for (int j = 0; j < 4; j++)
                accp[i][j] = fma2(ap[i], bd[j], accp[i][j]);
    }

    float acc[8][4];
    #pragma unroll
    for (int i = 0; i < 4; i++)
        #pragma unroll
        for (int j = 0; j < 4; j++)
            upk2(accp[i][j], acc[2*i][j], acc[2*i+1][j]);

    float alpha = sAlpha[0];
    int c = cg * 8;
    #pragma unroll
    for (int j = 0; j < 4; j++) {
        int t = ph*128 + lane*4 + j;
        float r[8];
        #pragma unroll
        for (int i = 0; i < 8; i++) {
            float y = acc[i][j] + sBias[c + i];
            r[i] = (y > 0.f) ? y : alpha * y;
        }
        size_t off = (((size_t)b*Tn + t)*Fn + f)*CHn + c;
        *(float4*)(g_vf + off)     = make_float4(r[0],r[1],r[2],r[3]);
        *(float4*)(g_vf + off + 4) = make_float4(r[4],r[5],r[6],r[7]);
    }
}

// =====================================================================
// Attention kernel — v6 (tensor cores, mma.sync bf16):
//  scores: mma m16n8k16, A=Q[32][40]bf16 (row-major), B=K[256][40]bf16
//          (natural [y][c] = col-major for row.col mma). Warp w owns
//          cols w*32..w*32+31, all 32 rows; 16 mmas/warp/chunk.
//  softmax: per-warp partial max/sum (2 shfl), cross-warp via smem.
//  P -> smem bf16 [32][264]; PV: A=P via ldmatrix, B=V^T[32][264]bf16;
//          warps split (k-half x 4 col-tiles); 2-way smem reduction.
//  causal: score warps w>ch skipped; PV k-half 1 skipped for ch<4.
//  Pitches 40/264 make every ldmatrix conflict-free.
// =====================================================================
template<bool CAUSAL>
__global__ void __launch_bounds__(256, 3) attn_kernel()
{
    const float* __restrict__ qg = CAUSAL ? g_qt : g_qf;
    const float* __restrict__ kg = CAUSAL ? g_kt : g_kf;
    const float* __restrict__ vg = CAUSAL ? g_fout : g_vf;
    float* __restrict__ outg     = CAUSAL ? g_tout : g_fout;

    extern __shared__ char smb[];
    constexpr int KOFF = 0, VOFF = 20480, QOFF = 37376, POFF = 39936,
                  MAXOFF = 56832, SUMOFF = 57856, PARTOFF = 58880;
    __nv_bfloat16* sK  = (__nv_bfloat16*)(smb + KOFF);   // [256][40]
    __nv_bfloat16* sVT = (__nv_bfloat16*)(smb + VOFF);   // [32][264]
    __nv_bfloat16* sQ  = (__nv_bfloat16*)(smb + QOFF);   // [32][40]
    __nv_bfloat16* sP  = (__nv_bfloat16*)(smb + POFF);   // [32][264]
    float* sMaxP  = (float*)(smb + MAXOFF);              // [8][32]
    float* sSumP  = (float*)(smb + SUMOFF);              // [8][32]
    float* sPartO = (float*)(smb + PARTOFF);             // [2][32][32]
    uint32_t sb = (uint32_t)__cvta_generic_to_shared(smb);

    int tid = threadIdx.x, lane = tid & 31, w = tid >> 5;
    int g = lane >> 2, t2 = (lane & 3) * 2;
    int col = blockIdx.x;
    int b   = blockIdx.y;
    size_t base = ((size_t)b * 256 + col) * 256 * CHn;
    const float* qp = qg + base;
    const float* kp = kg + base;
    const float* vp = vg + base;
    size_t out_base, out_stride;
    if (CAUSAL) { out_base = base; out_stride = CHn; }
    else { out_base = ((size_t)b * Sn + col) * CHn; out_stride = (size_t)Tn * CHn; }

    const float scale = 0.17677669529663687f;  // 1/sqrt(32)

    // ---- stage K (bf16 [y][40]) and V^T (bf16 [c][264]) ----
    #pragma unroll
    for (int jj = 0; jj < 8; jj++) {
        int idx4 = tid + jj*256;         // 0..2047
        int y = idx4 >> 3, cq = idx4 & 7;
        float4 kv = ((const float4*)kp)[idx4];
        *(__nv_bfloat162*)&sK[y*40 + cq*4]     = __float22bfloat162_rn(make_float2(kv.x, kv.y));
        *(__nv_bfloat162*)&sK[y*40 + cq*4 + 2] = __float22bfloat162_rn(make_float2(kv.z, kv.w));
        float4 vv = ((const float4*)vp)[idx4];
        sVT[(cq*4+0)*264 + y] = __float2bfloat16(vv.x);
        sVT[(cq*4+1)*264 + y] = __float2bfloat16(vv.y);
        sVT[(cq*4+2)*264 + y] = __float2bfloat16(vv.z);
        sVT[(cq*4+3)*264 + y] = __float2bfloat16(vv.w);
    }

    for (int ch = 0; ch < 8; ch++) {
        int r0 = ch * 32;

        // ---- stage Q chunk, scaled, bf16 [r][40]
        {
            int row = tid >> 3, cq = tid & 7;
            float4 qv = *(const float4*)(qp + (size_t)(r0 + row)*CHn + cq*4);
            *(__nv_bfloat162*)&sQ[row*40 + cq*4] =
                __float22bfloat162_rn(make_float2(qv.x*scale, qv.y*scale));
            *(__nv_bfloat162*)&sQ[row*40 + cq*4 + 2] =
                __float22bfloat162_rn(make_float2(qv.z*scale, qv.w*scale));
        }
        __syncthreads();   // (1) Q/K ready

        const bool act = !CAUSAL || (w <= ch);
        const int nact = CAUSAL ? (ch + 1) : 8;

        // ---- score mmas
        float D[2][4][4];
        #pragma unroll
        for (int mt = 0; mt < 2; mt++)
            #pragma unroll
            for (int nt = 0; nt < 4; nt++)
                #pragma unroll
                for (int j = 0; j < 4; j++) D[mt][nt][j] = 0.f;

        if (act) {
            uint32_t qa[2][2][4];
            #pragma unroll
            for (int mt = 0; mt < 2; mt++)
                #pragma unroll
                for (int ks = 0; ks < 2; ks++) {
                    int row = mt*16 + (lane & 15);
                    int cc  = ks*16 + (lane >> 4) * 8;
                    ldsm4(qa[mt][ks], sb + QOFF + (uint32_t)(row*40 + cc)*2);
                }
            uint32_t kb[4][4];
            #pragma unroll
            for (int nt = 0; nt < 4; nt++) {
                int y = w*32 + nt*8 + (lane & 7);
                int k = (lane >> 3) * 8;
                ldsm4(kb[nt], sb + KOFF + (uint32_t)(y*40 + k)*2);
            }
            #pragma unroll
            for (int mt = 0; mt < 2; mt++)
                #pragma unroll
                for (int nt = 0; nt < 4; nt++) {
                    mma_bf16(D[mt][nt], qa[mt][0], &kb[nt][0]);
                    mma_bf16(D[mt][nt], qa[mt][1], &kb[nt][2]);
                }

            // diagonal-warp causal mask
            if (CAUSAL && w == ch) {
                #pragma unroll
                for (int mt = 0; mt < 2; mt++)
                    #pragma unroll
                    for (int nt = 0; nt < 4; nt++) {
                        int y0 = w*32 + nt*8 + t2;
                        int rA = r0 + mt*16 + g;
                        int rB = rA + 8;
                        if (y0     > rA) D[mt][nt][0] = -1e30f;
                        if (y0 + 1 > rA) D[mt][nt][1] = -1e30f;
                        if (y0     > rB) D[mt][nt][2] = -1e30f;
                        if (y0 + 1 > rB) D[mt][nt][3] = -1e30f;
                    }
            }

            // per-warp row max (rows live in lane quads)
            float mx[2][2];
            #pragma unroll
            for (int mt = 0; mt < 2; mt++) {
                mx[mt][0] = -1e30f; mx[mt][1] = -1e30f;
                #pragma unroll
                for (int nt = 0; nt < 4; nt++) {
                    mx[mt][0] = fmaxf(mx[mt][0], fmaxf(D[mt][nt][0], D[mt][nt][1]));
                    mx[mt][1] = fmaxf(mx[mt][1], fmaxf(D[mt][nt][2], D[mt][nt][3]));
                }
                #pragma unroll
                for (int dlt = 1; dlt <= 2; dlt <<= 1) {
                    mx[mt][0] = fmaxf(mx[mt][0], __shfl_xor_sync(0xffffffffu, mx[mt][0], dlt));
                    mx[mt][1] = fmaxf(mx[mt][1], __shfl_xor_sync(0xffffffffu, mx[mt][1], dlt));
                }
            }
            if ((lane & 3) == 0) {
                #pragma unroll
                for (int mt = 0; mt < 2; mt++) {
                    sMaxP[w*32 + mt*16 + g]     = mx[mt][0];
                    sMaxP[w*32 + mt*16 + g + 8] = mx[mt][1];
                }
            }
        }
        __syncthreads();   // (2) max partials ready

        // ---- global max, exp, P write (bf16), sum partials
        float gmx[2][2];
        #pragma unroll
        for (int mt = 0; mt < 2; mt++)
            #pragma unroll
            for (int h = 0; h < 2; h++) {
                int r = mt*16 + g + h*8;
                float m = -1e30f;
                for (int wi = 0; wi < nact; wi++)
                    m = fmaxf(m, sMaxP[wi*32 + r]);
                gmx[mt][h] = m;
            }

        float sum[2][2] = {{0.f,0.f},{0.f,0.f}};
        #pragma unroll
        for (int mt = 0; mt < 2; mt++)
            #pragma unroll
            for (int nt = 0; nt < 4; nt++) {
                float e0 = act ? __expf(D[mt][nt][0] - gmx[mt][0]) : 0.f;
                float e1 = act ? __expf(D[mt][nt][1] - gmx[mt][0]) : 0.f;
                float e2 = act ? __expf(D[mt][nt][2] - gmx[mt][1]) : 0.f;
                float e3 = act ? __expf(D[mt][nt][3] - gmx[mt][1]) : 0.f;
                sum[mt][0] += e0 + e1;
                sum[mt][1] += e2 + e3;
                int yy = w*32 + nt*8 + t2;
                *(__nv_bfloat162*)&sP[(mt*16+g)*264 + yy] =
                    __float22bfloat162_rn(make_float2(e0, e1));
                *(__nv_bfloat162*)&sP[(mt*16+g+8)*264 + yy] =
                    __float22bfloat162_rn(make_float2(e2, e3));
            }
        if (act) {
            #pragma unroll
            for (int mt = 0; mt < 2; mt++) {
                #pragma unroll
                for (int dlt = 1; dlt <= 2; dlt <<= 1) {
                    sum[mt][0] += __shfl_xor_sync(0xffffffffu, sum[mt][0], dlt);
                    sum[mt][1] += __shfl_xor_sync(0xffffffffu, sum[mt][1], dlt);
                }
            }
            if ((lane & 3) == 0) {
                #pragma unroll
                for (int mt = 0; mt < 2; mt++) {
                    sSumP[w*32 + mt*16 + g]     = sum[mt][0];
                    sSumP[w*32 + mt*16 + g + 8] = sum[mt][1];
                }
            }
        }
        __syncthreads();   // (3) P + sums ready

        // ---- PV mmas: warp -> (k-half kh, V col-tile ntc)
        const int kh  = w >> 2;
        const int ntc = w & 3;
        const bool use_kh1 = !CAUSAL || (ch >= 4);
        if (kh == 0 || use_kh1) {
            float O[2][4];
            #pragma unroll
            for (int mt = 0; mt < 2; mt++)
                #pragma unroll
                for (int j = 0; j < 4; j++) O[mt][j] = 0.f;

            #pragma unroll
            for (int kc = 0; kc < 4; kc++) {       // 32-wide k chunks
                uint32_t vb[4];
                {
                    int c = ntc*8 + (lane & 7);
                    int y = kh*128 + kc*32 + (lane >> 3) * 8;
                    ldsm4(vb, sb + VOFF + (uint32_t)(c*264 + y)*2);
                }
                #pragma unroll
                for (int mt = 0; mt < 2; mt++) {
                    uint32_t pa0[4], pa1[4];
                    int row = mt*16 + (lane & 15);
                    int cb2 = kh*128 + kc*32 + (lane >> 4) * 8;
                    ldsm4(pa0, sb + POFF + (uint32_t)(row*264 + cb2)*2);
                    ldsm4(pa1, sb + POFF + (uint32_t)(row*264 + cb2 + 16)*2);
                    mma_bf16(O[mt], pa0, &vb[0]);
                    mma_bf16(O[mt], pa1, &vb[2]);
                }
            }
            #pragma unroll
            for (int mt = 0; mt < 2; mt++) {
                *(float2*)&sPartO[kh*1024 + (mt*16+g)*32   + ntc*8 + t2] =
                    make_float2(O[mt][0], O[mt][1]);
                *(float2*)&sPartO[kh*1024 + (mt*16+g+8)*32 + ntc*8 + t2] =
                    make_float2(O[mt][2], O[mt][3]);
            }
        }
        __syncthreads();   // (4) partials ready

        // ---- reduce + normalize + write out
        {
            int r  = tid >> 3;
            int c0 = (tid & 7) * 4;
            float s = 0.f;
            for (int wi = 0; wi < nact; wi++) s += sSumP[wi*32 + r];
            float inv = 1.f / s;
            float4 x = *(float4*)&sPartO[r*32 + c0];
            if (use_kh1) {
                float4 y4 = *(float4*)&sPartO[1024 + r*32 + c0];
                x.x += y4.x; x.y += y4.y; x.z += y4.z; x.w += y4.w;
            }
            *(float4*)(outg + out_base + (size_t)(r0 + r)*out_stride + c0) =
                make_float4(x.x*inv, x.y*inv, x.z*inv, x.w*inv);
        }
        // next iteration's syncs order reuse of sQ/sMaxP/sSumP/sP/sPartO
    }
}

// =====================================================================
// Kernel 5: proj conv (32 -> 64) + BN + LeakyReLU + residual. (f32x2)
// =====================================================================
__global__ void __launch_bounds__(256) proj_kernel(
    const float* __restrict__ xin,
    const float* __restrict__ W,  const float* __restrict__ bb,
    const float* __restrict__ gg, const float* __restrict__ be,
    const float* __restrict__ mm, const float* __restrict__ vv,
    const float* __restrict__ aa,
    float* __restrict__ outp)
{
    __shared__ float sW[32][64];
    __shared__ float sIn[32][132];
    __shared__ float sBias[64];
    __shared__ float sAlpha;

    int tid = threadIdx.x;
    int tile = blockIdx.x, b = blockIdx.y;
    int p0 = tile * 128;

    for (int idx = tid; idx < 2048; idx += 256) {
        int o = idx & 63, k = idx >> 6;
        float sc = gg[o] * rsqrtf(vv[o] + EPSc);
        sW[k][o] = W[o*32 + k] * sc;
    }
    if (tid < 64) {
        float sc = gg[tid] * rsqrtf(vv[tid] + EPSc);
        sBias[tid] = (bb[tid] - mm[tid]) * sc + be[tid];
    }
    if (tid == 0) sAlpha = aa[0];

    const float* tp = g_tout + ((size_t)b*Sn + p0) * CHn;
    #pragma unroll
    for (int jj = 0; jj < 4; jj++) {
        int idx4 = tid + jj*256;
        int p = idx4 >> 3, cq = idx4 & 7;
        float4 tv = ((const float4*)tp)[idx4];
        sIn[cq*4+0][p] = tv.x;
        sIn[cq*4+1][p] = tv.y;
        sIn[cq*4+2][p] = tv.z;
        sIn[cq*4+3][p] = tv.w;
    }
    __syncthreads();

    int lane = tid & 31, w = tid >> 5;
    unsigned long long accp[4][4];
    #pragma unroll
    for (int i = 0; i < 4; i++)
        #pragma unroll
        for (int j = 0; j < 4; j++) accp[i][j] = 0ull;

    #pragma unroll 2
    for (int k = 0; k < 32; k++) {
        float4 A0 = *(const float4*)&sW[k][w*8];
        float4 A1 = *(const float4*)&sW[k][w*8 + 4];
        float4 Bv = *(const float4*)&sIn[k][lane*4];
        unsigned long long ap[4] = {
            pk2(A0.x,A0.y), pk2(A0.z,A0.w), pk2(A1.x,A1.y), pk2(A1.z,A1.w)};
        unsigned long long bd[4] = {
            pk2(Bv.x,Bv.x), pk2(Bv.y,Bv.y), pk2(Bv.z,Bv.z), pk2(Bv.w,Bv.w)};
        #pragma unroll
        for (int i = 0; i < 4; i++)
            #pragma unroll
            for (int j = 0; j < 4; j++)
                accp[i][j] = fma2(ap[i], bd[j], accp[i][j]);
    }

    float acc[8][4];
    #pragma unroll
    for (int i = 0; i < 4; i++)
        #pragma unroll
        for (int j = 0; j < 4; j++)
            upk2(accp[i][j], acc[2*i][j], acc[2*i+1][j]);

    float alpha = sAlpha;
    const float* xb = xin + (size_t)b*Cn*Sn + p0 + lane*4;
    float*       ob = outp + (size_t)b*Cn*Sn + p0 + lane*4;
    #pragma unroll
    for (int i = 0; i < 8; i++) {
        int o = w*8 + i;
        float bias = sBias[o];
        float4 xr = *(const float4*)(xb + (size_t)o*Sn);
        float r0 = acc[i][0] + bias; r0 = (r0 > 0.f) ? r0 : alpha*r0; r0 += xr.x;
        float r1 = acc[i][1] + bias; r1 = (r1 > 0.f) ? r1 : alpha*r1; r1 += xr.y;
        float r2 = acc[i][2] + bias; r2 = (r2 > 0.f) ? r2 : alpha*r2; r2 += xr.z;
        float r3 = acc[i][3] + bias; r3 = (r3 > 0.f) ? r3 : alpha*r3; r3 += xr.w;
        *(float4*)(ob + (size_t)o*Sn) = make_float4(r0, r1, r2, r3);
    }
}

// =====================================================================
// Launch
// =====================================================================
extern "C" void kernel_launch(void* const* d_in, const int* in_sizes, int n_in,
                              void* d_out, int out_size) {
    const float* inp  = (const float*)d_in[0];
    const float* x    = (const float*)d_in[1];
    const float* fqkW = (const float*)d_in[2];
    const float* fqkb = (const float*)d_in[3];
    const float* fqkg = (const float*)d_in[4];
    const float* fqkbe= (const float*)d_in[5];
    const float* fqkm = (const float*)d_in[6];
    const float* fqkv = (const float*)d_in[7];
    const float* fqka = (const float*)d_in[8];
    const float* fvW  = (const float*)d_in[9];
    const float* fvb  = (const float*)d_in[10];
    const float* fvg  = (const float*)d_in[11];
    const float* fvbe = (const float*)d_in[12];
    const float* fvm  = (const float*)d_in[13];
    const float* fvv  = (const float*)d_in[14];
    const float* fva  = (const float*)d_in[15];
    const float* tqkW = (const float*)d_in[16];
    const float* tqkb = (const float*)d_in[17];
    const float* tqkg = (const float*)d_in[18];
    const float* tqkbe= (const float*)d_in[19];
    const float* tqkm = (const float*)d_in[20];
    const float* tqkv = (const float*)d_in[21];
    const float* tqka = (const float*)d_in[22];
    const float* prW  = (const float*)d_in[23];
    const float* prb  = (const float*)d_in[24];
    const float* prg  = (const float*)d_in[25];
    const float* prbe = (const float*)d_in[26];
    const float* prm  = (const float*)d_in[27];
    const float* prv  = (const float*)d_in[28];
    const float* pra  = (const float*)d_in[29];
    float* out = (float*)d_out;

    cudaFuncSetAttribute(conv_qk_kernel,
                         cudaFuncAttributeMaxDynamicSharedMemorySize, QK_SMEM);
    cudaFuncSetAttribute(conv_v_kernel,
                         cudaFuncAttributeMaxDynamicSharedMemorySize, CV_SMEM);
    cudaFuncSetAttribute(attn_kernel<false>,
                         cudaFuncAttributeMaxDynamicSharedMemorySize, ATTN_SMEM);
    cudaFuncSetAttribute(attn_kernel<true>,
                         cudaFuncAttributeMaxDynamicSharedMemorySize, ATTN_SMEM);

    conv_qk_kernel<<<dim3(512, Bn), 256, QK_SMEM>>>(inp,
        fqkW, fqkb, fqkg, fqkbe, fqkm, fqkv, fqka,
        tqkW, tqkb, tqkg, tqkbe, tqkm, tqkv, tqka);

    conv_v_kernel<<<dim3(256, Bn), 256, CV_SMEM>>>(x,
        fvW, fvb, fvg, fvbe, fvm, fvv, fva);

    attn_kernel<false><<<dim3(256, Bn), 256, ATTN_SMEM>>>();

    attn_kernel<true><<<dim3(256, Bn), 256, ATTN_SMEM>>>();

    proj_kernel<<<dim3(512, Bn), 256>>>(x,
        prW, prb, prg, prbe, prm, prv, pra, out);
}

// round 11
// speedup vs baseline: 3.3319x; 1.3232x over previous
#include <cuda_runtime.h>
#include <cuda_bf16.h>
#include <cstdint>

// Problem constants
constexpr int Bn  = 4;
constexpr int Cn  = 64;
constexpr int CHn = 32;
constexpr int Fn  = 256;
constexpr int Tn  = 256;
constexpr int Sn  = Fn * Tn;
constexpr float EPSc = 1e-5f;
constexpr float QSCALE = 0.17677669529663687f;  // 1/sqrt(32)

// ---- packed fp32x2 helpers (FFMA2) ----
__device__ __forceinline__ unsigned long long pk2(float lo, float hi) {
    unsigned long long r;
    asm("mov.b64 %0, {%1, %2};" : "=l"(r) : "f"(lo), "f"(hi));
    return r;
}
__device__ __forceinline__ void upk2(unsigned long long v, float& lo, float& hi) {
    asm("mov.b64 {%0, %1}, %2;" : "=f"(lo), "=f"(hi) : "l"(v));
}
__device__ __forceinline__ unsigned long long fma2(
    unsigned long long a, unsigned long long b, unsigned long long c) {
    unsigned long long d;
    asm("fma.rn.f32x2 %0, %1, %2, %3;" : "=l"(d) : "l"(a), "l"(b), "l"(c));
    return d;
}
__device__ __forceinline__ uint32_t pkbf2(float lo, float hi) {
    __nv_bfloat162 h = __float22bfloat162_rn(make_float2(lo, hi));
    return *(uint32_t*)&h;
}

// ---- tensor-core helpers ----
__device__ __forceinline__ void ldsm4(uint32_t* r, uint32_t addr) {
    asm volatile("ldmatrix.sync.aligned.m8n8.x4.shared.b16 {%0,%1,%2,%3}, [%4];\n"
        : "=r"(r[0]), "=r"(r[1]), "=r"(r[2]), "=r"(r[3]) : "r"(addr));
}
__device__ __forceinline__ void mma_bf16(float* d, const uint32_t* a, const uint32_t* b) {
    asm volatile(
        "mma.sync.aligned.m16n8k16.row.col.f32.bf16.bf16.f32 "
        "{%0,%1,%2,%3}, {%4,%5,%6,%7}, {%8,%9}, {%0,%1,%2,%3};\n"
        : "+f"(d[0]), "+f"(d[1]), "+f"(d[2]), "+f"(d[3])
        : "r"(a[0]), "r"(a[1]), "r"(a[2]), "r"(a[3]), "r"(b[0]), "r"(b[1]));
}

// -------- device scratch (bf16 intermediates; tout fp32 for proj) --------
__device__ __nv_bfloat16 g_qf[Bn*Tn*Fn*CHn];
__device__ __nv_bfloat16 g_kf[Bn*Tn*Fn*CHn];
__device__ __nv_bfloat16 g_vf[Bn*Tn*Fn*CHn];
__device__ __nv_bfloat16 g_qt[Bn*Fn*Tn*CHn];
__device__ __nv_bfloat16 g_kt[Bn*Fn*Tn*CHn];
__device__ __nv_bfloat16 g_fout[Bn*Fn*Tn*CHn];
__device__ float g_tout[Bn*Fn*Tn*CHn];

// -------- folded conv parameters (written once by fold_kernel) --------
__device__ float w_qk[64*128];   // [k][o], BN-scaled, q-channels pre-scaled
__device__ float b_qk[128];
__device__ float w_v [64*32];    // [k][o]
__device__ float b_v [32];
__device__ float w_pr[32*64];    // [k][o]
__device__ float b_pr[64];

// dynamic-smem sizes (bytes)
constexpr int QK_SMEM   = (64*128 + 64*128 + 128 + 2) * 4;        // 66056
constexpr int CV_SMEM   = (64*32 + 64*256 + 32 + 1) * 4;          // 73860
constexpr int ATTN_SMEM = 67072;   // same layout as v6 (all bf16 stages)

// =====================================================================
// Kernel 0: fold BN into weights/biases once.
// =====================================================================
__global__ void fold_kernel(
    const float* __restrict__ W1, const float* __restrict__ b1,
    const float* __restrict__ g1, const float* __restrict__ be1,
    const float* __restrict__ m1, const float* __restrict__ v1,
    const float* __restrict__ W2, const float* __restrict__ b2,
    const float* __restrict__ g2, const float* __restrict__ be2,
    const float* __restrict__ m2, const float* __restrict__ v2,
    const float* __restrict__ Wv, const float* __restrict__ bv,
    const float* __restrict__ gv, const float* __restrict__ bev,
    const float* __restrict__ mv, const float* __restrict__ vvv,
    const float* __restrict__ Wp, const float* __restrict__ bp,
    const float* __restrict__ gp, const float* __restrict__ bep,
    const float* __restrict__ mp, const float* __restrict__ vp)
{
    int tid = threadIdx.x;
    // fqk + tqk fused (o<64: fqk, o>=64: tqk); q channels (even) pre-scaled
    for (int idx = tid; idx < 8192; idx += 256) {
        int k = idx >> 7, o = idx & 127;
        float wv_;
        bool isq;
        if (o < 64) {
            float sc = g1[o] * rsqrtf(v1[o] + EPSc);
            wv_ = W1[o*64 + k] * sc;
            isq = ((o & 1) == 0);
        } else {
            int oo = o - 64;
            float sc = g2[oo] * rsqrtf(v2[oo] + EPSc);
            wv_ = W2[oo*64 + k] * sc;
            isq = ((oo & 1) == 0);
        }
        if (isq) wv_ *= QSCALE;
        w_qk[k*128 + o] = wv_;
    }
    if (tid < 128) {
        int o = tid;
        float bias; bool isq;
        if (o < 64) {
            float sc = g1[o] * rsqrtf(v1[o] + EPSc);
            bias = (b1[o] - m1[o]) * sc + be1[o];
            isq = ((o & 1) == 0);
        } else {
            int oo = o - 64;
            float sc = g2[oo] * rsqrtf(v2[oo] + EPSc);
            bias = (b2[oo] - m2[oo]) * sc + be2[oo];
            isq = ((oo & 1) == 0);
        }
        if (isq) bias *= QSCALE;
        b_qk[o] = bias;
    }
    // fv
    for (int idx = tid; idx < 2048; idx += 256) {
        int k = idx >> 5, o = idx & 31;
        float sc = gv[o] * rsqrtf(vvv[o] + EPSc);
        w_v[k*32 + o] = Wv[o*64 + k] * sc;
    }
    if (tid < 32) {
        float sc = gv[tid] * rsqrtf(vvv[tid] + EPSc);
        b_v[tid] = (bv[tid] - mv[tid]) * sc + bev[tid];
    }
    // proj
    for (int idx = tid; idx < 2048; idx += 256) {
        int k = idx >> 6, o = idx & 63;
        float sc = gp[o] * rsqrtf(vp[o] + EPSc);
        w_pr[k*64 + o] = Wp[o*32 + k] * sc;
    }
    if (tid < 64) {
        float sc = gp[tid] * rsqrtf(vp[tid] + EPSc);
        b_pr[tid] = (bp[tid] - mp[tid]) * sc + bep[tid];
    }
}

// =====================================================================
// Kernel 1: fused fqk + tqk conv (folded params), bf16 outputs. (f32x2)
// =====================================================================
__global__ void __launch_bounds__(256) conv_qk_kernel(
    const float* __restrict__ inp,
    const float* __restrict__ a1, const float* __restrict__ a2)
{
    extern __shared__ float smqk[];
    float* sW    = smqk;               // [64][128]
    float* sIn   = smqk + 64*128;      // [64][128]
    float* sBias = smqk + 2*64*128;    // [128]
    float* sAlpha= sBias + 128;        // [2]

    int tid  = threadIdx.x;
    int b    = blockIdx.y;
    int tile = blockIdx.x;
    int p0   = tile * 128;
    int f    = p0 >> 8;
    int t0   = p0 & 255;

    #pragma unroll
    for (int jj = 0; jj < 8; jj++) {
        int idx4 = tid + jj * 256;            // 0..2047 float4s
        *(float4*)&sW[idx4*4] = *(const float4*)&w_qk[idx4*4];
    }
    if (tid < 128) sBias[tid] = b_qk[tid];
    if (tid == 0) { sAlpha[0] = a1[0]; sAlpha[1] = a2[0]; }

    const float* ip = inp + (size_t)b * Cn * Sn + p0;
    #pragma unroll
    for (int jj = 0; jj < 8; jj++) {
        int idx4 = tid + jj * 256;
        int k  = idx4 >> 5;
        int pq = idx4 & 31;
        float4 val = *(const float4*)(ip + (size_t)k * Sn + pq * 4);
        *(float4*)&sIn[k*128 + pq*4] = val;
    }
    __syncthreads();

    int lane = tid & 31, w = tid >> 5;
    unsigned long long accp[8][4];
    #pragma unroll
    for (int i = 0; i < 8; i++)
        #pragma unroll
        for (int j = 0; j < 4; j++) accp[i][j] = 0ull;

    #pragma unroll 2
    for (int k = 0; k < 64; k++) {
        float4 A0 = *(const float4*)&sW[k*128 + w*16 + 0];
        float4 A1 = *(const float4*)&sW[k*128 + w*16 + 4];
        float4 A2 = *(const float4*)&sW[k*128 + w*16 + 8];
        float4 A3 = *(const float4*)&sW[k*128 + w*16 + 12];
        float4 Bv = *(const float4*)&sIn[k*128 + lane*4];
        unsigned long long ap[8] = {
            pk2(A0.x,A0.y), pk2(A0.z,A0.w), pk2(A1.x,A1.y), pk2(A1.z,A1.w),
            pk2(A2.x,A2.y), pk2(A2.z,A2.w), pk2(A3.x,A3.y), pk2(A3.z,A3.w)};
        unsigned long long bd[4] = {
            pk2(Bv.x,Bv.x), pk2(Bv.y,Bv.y), pk2(Bv.z,Bv.z), pk2(Bv.w,Bv.w)};
        #pragma unroll
        for (int i = 0; i < 8; i++)
            #pragma unroll
            for (int j = 0; j < 4; j++)
                accp[i][j] = fma2(ap[i], bd[j], accp[i][j]);
    }

    float acc[16][4];
    #pragma unroll
    for (int i = 0; i < 8; i++)
        #pragma unroll
        for (int j = 0; j < 4; j++)
            upk2(accp[i][j], acc[2*i][j], acc[2*i+1][j]);

    float alpha = (w < 4) ? sAlpha[0] : sAlpha[1];
    #pragma unroll
    for (int i = 0; i < 16; i++) {
        float bias = sBias[w*16 + i];
        #pragma unroll
        for (int j = 0; j < 4; j++) {
            float y = acc[i][j] + bias;
            acc[i][j] = (y > 0.f) ? y : alpha * y;
        }
    }

    int t = t0 + lane * 4;
    if (w < 4) {
        int cb = w * 8;
        #pragma unroll
        for (int j = 0; j < 4; j++) {
            size_t off = (((size_t)b*Tn + (t+j))*Fn + f)*CHn + cb;
            uint4 qu, ku;
            qu.x = pkbf2(acc[0][j],  acc[2][j]);
            qu.y = pkbf2(acc[4][j],  acc[6][j]);
            qu.z = pkbf2(acc[8][j],  acc[10][j]);
            qu.w = pkbf2(acc[12][j], acc[14][j]);
            ku.x = pkbf2(acc[1][j],  acc[3][j]);
            ku.y = pkbf2(acc[5][j],  acc[7][j]);
            ku.z = pkbf2(acc[9][j],  acc[11][j]);
            ku.w = pkbf2(acc[13][j], acc[15][j]);
            *(uint4*)(g_qf + off) = qu;
            *(uint4*)(g_kf + off) = ku;
        }
    } else {
        int cb = (w - 4) * 8;
        #pragma unroll
        for (int j = 0; j < 4; j++) {
            size_t off = (((size_t)b*Fn + f)*Tn + (t+j))*CHn + cb;
            uint4 qu, ku;
            qu.x = pkbf2(acc[0][j],  acc[2][j]);
            qu.y = pkbf2(acc[4][j],  acc[6][j]);
            qu.z = pkbf2(acc[8][j],  acc[10][j]);
            qu.w = pkbf2(acc[12][j], acc[14][j]);
            ku.x = pkbf2(acc[1][j],  acc[3][j]);
            ku.y = pkbf2(acc[5][j],  acc[7][j]);
            ku.z = pkbf2(acc[9][j],  acc[11][j]);
            ku.w = pkbf2(acc[13][j], acc[15][j]);
            *(uint4*)(g_qt + off) = qu;
            *(uint4*)(g_kt + off) = ku;
        }
    }
}

// =====================================================================
// Kernel 2: fv conv (folded params), bf16 output. (f32x2)
// =====================================================================
__global__ void __launch_bounds__(256) conv_v_kernel(
    const float* __restrict__ xin, const float* __restrict__ aa)
{
    extern __shared__ float smcv[];
    float* sW    = smcv;              // [64][32]
    float* sIn   = smcv + 64*32;      // [64][256]
    float* sBias = sIn + 64*256;      // [32]
    float* sAlpha= sBias + 32;        // [1]

    int tid = threadIdx.x;
    int f = blockIdx.x, b = blockIdx.y;

    #pragma unroll
    for (int jj = 0; jj < 2; jj++) {
        int idx4 = tid + jj*256;          // 0..511 float4s
        *(float4*)&sW[idx4*4] = *(const float4*)&w_v[idx4*4];
    }
    if (tid < 32) sBias[tid] = b_v[tid];
    if (tid == 0) sAlpha[0] = aa[0];

    const float* ip = xin + (size_t)b*Cn*Sn + (size_t)f*Tn;
    #pragma unroll
    for (int jj = 0; jj < 16; jj++) {
        int idx4 = tid + jj*256;
        int k = idx4 >> 6, pq = idx4 & 63;
        *(float4*)&sIn[k*256 + pq*4] = *(const float4*)(ip + (size_t)k*Sn + pq*4);
    }
    __syncthreads();

    int lane = tid & 31, w = tid >> 5;
    int cg = w & 3, ph = w >> 2;
    unsigned long long accp[4][4];
    #pragma unroll
    for (int i = 0; i < 4; i++)
        #pragma unroll
        for (int j = 0; j < 4; j++) accp[i][j] = 0ull;

    #pragma unroll 2
    for (int k = 0; k < 64; k++) {
        float4 A0 = *(const float4*)&sW[k*32 + cg*8];
        float4 A1 = *(const float4*)&sW[k*32 + cg*8 + 4];
        float4 Bv = *(const float4*)&sIn[k*256 + ph*128 + lane*4];
        unsigned long long ap[4] = {
            pk2(A0.x,A0.y), pk2(A0.z,A0.w), pk2(A1.x,A1.y), pk2(A1.z,A1.w)};
        unsigned long long bd[4] = {
            pk2(Bv.x,Bv.x), pk2(Bv.y,Bv.y), pk2(Bv.z,Bv.z), pk2(Bv.w,Bv.w)};
        #pragma unroll
        for (int i = 0; i < 4; i++)
            #pragma unroll
            for (int j = 0; j < 4; j++)
                accp[i][j] = fma2(ap[i], bd[j], accp[i][j]);
    }

    float acc[8][4];
    #pragma unroll
    for (int i = 0; i < 4; i++)
        #pragma unroll
        for (int j = 0; j < 4; j++)
            upk2(accp[i][j], acc[2*i][j], acc[2*i+1][j]);

    float alpha = sAlpha[0];
    int c = cg * 8;
    #pragma unroll
    for (int j = 0; j < 4; j++) {
        int t = ph*128 + lane*4 + j;
        float r[8];
        #pragma unroll
        for (int i = 0; i < 8; i++) {
            float y = acc[i][j] + sBias[c + i];
            r[i] = (y > 0.f) ? y : alpha * y;
        }
        size_t off = (((size_t)b*Tn + t)*Fn + f)*CHn + c;
        uint4 u;
        u.x = pkbf2(r[0], r[1]); u.y = pkbf2(r[2], r[3]);
        u.z = pkbf2(r[4], r[5]); u.w = pkbf2(r[6], r[7]);
        *(uint4*)(g_vf + off) = u;
    }
}

// =====================================================================
// Attention kernel — v7: bf16 inputs (q pre-scaled), tensor-core mmas.
// Non-causal writes bf16 fout; causal writes fp32 tout.
// =====================================================================
template<bool CAUSAL>
__global__ void __launch_bounds__(256, 3) attn_kernel()
{
    const __nv_bfloat16* __restrict__ qg = CAUSAL ? g_qt : g_qf;
    const __nv_bfloat16* __restrict__ kg = CAUSAL ? g_kt : g_kf;
    const __nv_bfloat16* __restrict__ vg = CAUSAL ? g_fout : g_vf;

    extern __shared__ char smb[];
    constexpr int KOFF = 0, VOFF = 20480, QOFF = 37376, POFF = 39936,
                  MAXOFF = 56832, SUMOFF = 57856, PARTOFF = 58880;
    __nv_bfloat16* sK  = (__nv_bfloat16*)(smb + KOFF);   // [256][40]
    __nv_bfloat16* sVT = (__nv_bfloat16*)(smb + VOFF);   // [32][264]
    __nv_bfloat16* sQ  = (__nv_bfloat16*)(smb + QOFF);   // [32][40]
    __nv_bfloat16* sP  = (__nv_bfloat16*)(smb + POFF);   // [32][264]
    float* sMaxP  = (float*)(smb + MAXOFF);              // [8][32]
    float* sSumP  = (float*)(smb + SUMOFF);              // [8][32]
    float* sPartO = (float*)(smb + PARTOFF);             // [2][32][32]
    uint32_t sb = (uint32_t)__cvta_generic_to_shared(smb);

    int tid = threadIdx.x, lane = tid & 31, w = tid >> 5;
    int g = lane >> 2, t2 = (lane & 3) * 2;
    int col = blockIdx.x;
    int b   = blockIdx.y;
    size_t base = ((size_t)b * 256 + col) * 256 * CHn;
    const __nv_bfloat16* qp = qg + base;
    const __nv_bfloat16* kp = kg + base;
    const __nv_bfloat16* vp = vg + base;
    size_t out_base, out_stride;
    if (CAUSAL) { out_base = base; out_stride = CHn; }
    else { out_base = ((size_t)b * Sn + col) * CHn; out_stride = (size_t)Tn * CHn; }

    // ---- stage K [y][40] and V^T [c][264] (both bf16 copies) ----
    #pragma unroll
    for (int jj = 0; jj < 4; jj++) {
        int idx = tid + jj*256;              // 0..1023 (uint4 = 8 bf16)
        int y = idx >> 2, q4 = idx & 3;
        *(uint4*)&sK[y*40 + q4*8] = *(const uint4*)(kp + y*32 + q4*8);
        union { uint4 u; __nv_bfloat16 h[8]; } vv;
        vv.u = *(const uint4*)(vp + y*32 + q4*8);
        #pragma unroll
        for (int c8 = 0; c8 < 8; c8++)
            sVT[(q4*8 + c8)*264 + y] = vv.h[c8];
    }

    for (int ch = 0; ch < 8; ch++) {
        int r0 = ch * 32;

        // ---- stage Q chunk (already scaled at conv)
        if (tid < 128) {
            int row = tid >> 2, q4 = tid & 3;
            *(uint4*)&sQ[row*40 + q4*8] =
                *(const uint4*)(qp + (size_t)(r0 + row)*CHn + q4*8);
        }
        __syncthreads();   // (1) Q/K ready

        const bool act = !CAUSAL || (w <= ch);
        const int nact = CAUSAL ? (ch + 1) : 8;

        // ---- score mmas
        float D[2][4][4];
        #pragma unroll
        for (int mt = 0; mt < 2; mt++)
            #pragma unroll
            for (int nt = 0; nt < 4; nt++)
                #pragma unroll
                for (int j = 0; j < 4; j++) D[mt][nt][j] = 0.f;

        if (act) {
            uint32_t qa[2][2][4];
            #pragma unroll
            for (int mt = 0; mt < 2; mt++)
                #pragma unroll
                for (int ks = 0; ks < 2; ks++) {
                    int row = mt*16 + (lane & 15);
                    int cc  = ks*16 + (lane >> 4) * 8;
                    ldsm4(qa[mt][ks], sb + QOFF + (uint32_t)(row*40 + cc)*2);
                }
            uint32_t kb[4][4];
            #pragma unroll
            for (int nt = 0; nt < 4; nt++) {
                int y = w*32 + nt*8 + (lane & 7);
                int k = (lane >> 3) * 8;
                ldsm4(kb[nt], sb + KOFF + (uint32_t)(y*40 + k)*2);
            }
            #pragma unroll
            for (int mt = 0; mt < 2; mt++)
                #pragma unroll
                for (int nt = 0; nt < 4; nt++) {
                    mma_bf16(D[mt][nt], qa[mt][0], &kb[nt][0]);
                    mma_bf16(D[mt][nt], qa[mt][1], &kb[nt][2]);
                }

            if (CAUSAL && w == ch) {
                #pragma unroll
                for (int mt = 0; mt < 2; mt++)
                    #pragma unroll
                    for (int nt = 0; nt < 4; nt++) {
                        int y0 = w*32 + nt*8 + t2;
                        int rA = r0 + mt*16 + g;
                        int rB = rA + 8;
                        if (y0     > rA) D[mt][nt][0] = -1e30f;
                        if (y0 + 1 > rA) D[mt][nt][1] = -1e30f;
                        if (y0     > rB) D[mt][nt][2] = -1e30f;
                        if (y0 + 1 > rB) D[mt][nt][3] = -1e30f;
                    }
            }

            float mx[2][2];
            #pragma unroll
            for (int mt = 0; mt < 2; mt++) {
                mx[mt][0] = -1e30f; mx[mt][1] = -1e30f;
                #pragma unroll
                for (int nt = 0; nt < 4; nt++) {
                    mx[mt][0] = fmaxf(mx[mt][0], fmaxf(D[mt][nt][0], D[mt][nt][1]));
                    mx[mt][1] = fmaxf(mx[mt][1], fmaxf(D[mt][nt][2], D[mt][nt][3]));
                }
                #pragma unroll
                for (int dlt = 1; dlt <= 2; dlt <<= 1) {
                    mx[mt][0] = fmaxf(mx[mt][0], __shfl_xor_sync(0xffffffffu, mx[mt][0], dlt));
                    mx[mt][1] = fmaxf(mx[mt][1], __shfl_xor_sync(0xffffffffu, mx[mt][1], dlt));
                }
            }
            if ((lane & 3) == 0) {
                #pragma unroll
                for (int mt = 0; mt < 2; mt++) {
                    sMaxP[w*32 + mt*16 + g]     = mx[mt][0];
                    sMaxP[w*32 + mt*16 + g + 8] = mx[mt][1];
                }
            }
        }
        __syncthreads();   // (2) max partials

        float gmx[2][2];
        #pragma unroll
        for (int mt = 0; mt < 2; mt++)
            #pragma unroll
            for (int h = 0; h < 2; h++) {
                int r = mt*16 + g + h*8;
                float m = -1e30f;
                for (int wi = 0; wi < nact; wi++)
                    m = fmaxf(m, sMaxP[wi*32 + r]);
                gmx[mt][h] = m;
            }

        float sum[2][2] = {{0.f,0.f},{0.f,0.f}};
        #pragma unroll
        for (int mt = 0; mt < 2; mt++)
            #pragma unroll
            for (int nt = 0; nt < 4; nt++) {
                float e0 = act ? __expf(D[mt][nt][0] - gmx[mt][0]) : 0.f;
                float e1 = act ? __expf(D[mt][nt][1] - gmx[mt][0]) : 0.f;
                float e2 = act ? __expf(D[mt][nt][2] - gmx[mt][1]) : 0.f;
                float e3 = act ? __expf(D[mt][nt][3] - gmx[mt][1]) : 0.f;
                sum[mt][0] += e0 + e1;
                sum[mt][1] += e2 + e3;
                int yy = w*32 + nt*8 + t2;
                *(__nv_bfloat162*)&sP[(mt*16+g)*264 + yy] =
                    __float22bfloat162_rn(make_float2(e0, e1));
                *(__nv_bfloat162*)&sP[(mt*16+g+8)*264 + yy] =
                    __float22bfloat162_rn(make_float2(e2, e3));
            }
        if (act) {
            #pragma unroll
            for (int mt = 0; mt < 2; mt++) {
                #pragma unroll
                for (int dlt = 1; dlt <= 2; dlt <<= 1) {
                    sum[mt][0] += __shfl_xor_sync(0xffffffffu, sum[mt][0], dlt);
                    sum[mt][1] += __shfl_xor_sync(0xffffffffu, sum[mt][1], dlt);
                }
            }
            if ((lane & 3) == 0) {
                #pragma unroll
                for (int mt = 0; mt < 2; mt++) {
                    sSumP[w*32 + mt*16 + g]     = sum[mt][0];
                    sSumP[w*32 + mt*16 + g + 8] = sum[mt][1];
                }
            }
        }
        __syncthreads();   // (3) P + sums ready

        const int kh  = w >> 2;
        const int ntc = w & 3;
        const bool use_kh1 = !CAUSAL || (ch >= 4);
        if (kh == 0 || use_kh1) {
            float O[2][4];
            #pragma unroll
            for (int mt = 0; mt < 2; mt++)
                #pragma unroll
                for (int j = 0; j < 4; j++) O[mt][j] = 0.f;

            #pragma unroll
            for (int kc = 0; kc < 4; kc++) {
                uint32_t vb[4];
                {
                    int c = ntc*8 + (lane & 7);
                    int y = kh*128 + kc*32 + (lane >> 3) * 8;
                    ldsm4(vb, sb + VOFF + (uint32_t)(c*264 + y)*2);
                }
                #pragma unroll
                for (int mt = 0; mt < 2; mt++) {
                    uint32_t pa0[4], pa1[4];
                    int row = mt*16 + (lane & 15);
                    int cb2 = kh*128 + kc*32 + (lane >> 4) * 8;
                    ldsm4(pa0, sb + POFF + (uint32_t)(row*264 + cb2)*2);
                    ldsm4(pa1, sb + POFF + (uint32_t)(row*264 + cb2 + 16)*2);
                    mma_bf16(O[mt], pa0, &vb[0]);
                    mma_bf16(O[mt], pa1, &vb[2]);
                }
            }
            #pragma unroll
            for (int mt = 0; mt < 2; mt++) {
                *(float2*)&sPartO[kh*1024 + (mt*16+g)*32   + ntc*8 + t2] =
                    make_float2(O[mt][0], O[mt][1]);
                *(float2*)&sPartO[kh*1024 + (mt*16+g+8)*32 + ntc*8 + t2] =
                    make_float2(O[mt][2], O[mt][3]);
            }
        }
        __syncthreads();   // (4) partials ready

        // ---- reduce + normalize + write out
        {
            int r  = tid >> 3;
            int c0 = (tid & 7) * 4;
            float s = 0.f;
            for (int wi = 0; wi < nact; wi++) s += sSumP[wi*32 + r];
            float inv = 1.f / s;
            float4 x = *(float4*)&sPartO[r*32 + c0];
            if (use_kh1) {
                float4 y4 = *(float4*)&sPartO[1024 + r*32 + c0];
                x.x += y4.x; x.y += y4.y; x.z += y4.z; x.w += y4.w;
            }
            if (CAUSAL) {
                *(float4*)(g_tout + out_base + (size_t)(r0 + r)*out_stride + c0) =
                    make_float4(x.x*inv, x.y*inv, x.z*inv, x.w*inv);
            } else {
                uint2 u;
                u.x = pkbf2(x.x*inv, x.y*inv);
                u.y = pkbf2(x.z*inv, x.w*inv);
                *(uint2*)(g_fout + out_base + (size_t)(r0 + r)*out_stride + c0) = u;
            }
        }
    }
}

// =====================================================================
// Kernel 5: proj conv (folded params) + residual -> fp32 out. (f32x2)
// =====================================================================
__global__ void __launch_bounds__(256) proj_kernel(
    const float* __restrict__ xin, const float* __restrict__ aa,
    float* __restrict__ outp)
{
    __shared__ float sW[32][64];
    __shared__ float sIn[32][132];
    __shared__ float sBias[64];
    __shared__ float sAlpha;

    int tid = threadIdx.x;
    int tile = blockIdx.x, b = blockIdx.y;
    int p0 = tile * 128;

    #pragma unroll
    for (int jj = 0; jj < 2; jj++) {
        int idx4 = tid + jj*256;
        *(float4*)&((float*)sW)[idx4*4] = *(const float4*)&w_pr[idx4*4];
    }
    if (tid < 64) sBias[tid] = b_pr[tid];
    if (tid == 0) sAlpha = aa[0];

    const float* tp = g_tout + ((size_t)b*Sn + p0) * CHn;
    #pragma unroll
    for (int jj = 0; jj < 4; jj++) {
        int idx4 = tid + jj*256;
        int p = idx4 >> 3, cq = idx4 & 7;
        float4 tv = ((const float4*)tp)[idx4];
        sIn[cq*4+0][p] = tv.x;
        sIn[cq*4+1][p] = tv.y;
        sIn[cq*4+2][p] = tv.z;
        sIn[cq*4+3][p] = tv.w;
    }
    __syncthreads();

    int lane = tid & 31, w = tid >> 5;
    unsigned long long accp[4][4];
    #pragma unroll
    for (int i = 0; i < 4; i++)
        #pragma unroll
        for (int j = 0; j < 4; j++) accp[i][j] = 0ull;

    #pragma unroll 2
    for (int k = 0; k < 32; k++) {
        float4 A0 = *(const float4*)&sW[k][w*8];
        float4 A1 = *(const float4*)&sW[k][w*8 + 4];
        float4 Bv = *(const float4*)&sIn[k][lane*4];
        unsigned long long ap[4] = {
            pk2(A0.x,A0.y), pk2(A0.z,A0.w), pk2(A1.x,A1.y), pk2(A1.z,A1.w)};
        unsigned long long bd[4] = {
            pk2(Bv.x,Bv.x), pk2(Bv.y,Bv.y), pk2(Bv.z,Bv.z), pk2(Bv.w,Bv.w)};
        #pragma unroll
        for (int i = 0; i < 4; i++)
            #pragma unroll
            for (int j = 0; j < 4; j++)
                accp[i][j] = fma2(ap[i], bd[j], accp[i][j]);
    }

    float acc[8][4];
    #pragma unroll
    for (int i = 0; i < 4; i++)
        #pragma unroll
        for (int j = 0; j < 4; j++)
            upk2(accp[i][j], acc[2*i][j], acc[2*i+1][j]);

    float alpha = sAlpha;
    const float* xb = xin + (size_t)b*Cn*Sn + p0 + lane*4;
    float*       ob = outp + (size_t)b*Cn*Sn + p0 + lane*4;
    #pragma unroll
    for (int i = 0; i < 8; i++) {
        int o = w*8 + i;
        float bias = sBias[o];
        float4 xr = *(const float4*)(xb + (size_t)o*Sn);
        float r0 = acc[i][0] + bias; r0 = (r0 > 0.f) ? r0 : alpha*r0; r0 += xr.x;
        float r1 = acc[i][1] + bias; r1 = (r1 > 0.f) ? r1 : alpha*r1; r1 += xr.y;
        float r2 = acc[i][2] + bias; r2 = (r2 > 0.f) ? r2 : alpha*r2; r2 += xr.z;
        float r3 = acc[i][3] + bias; r3 = (r3 > 0.f) ? r3 : alpha*r3; r3 += xr.w;
        *(float4*)(ob + (size_t)o*Sn) = make_float4(r0, r1, r2, r3);
    }
}

// =====================================================================
// Launch
// =====================================================================
extern "C" void kernel_launch(void* const* d_in, const int* in_sizes, int n_in,
                              void* d_out, int out_size) {
    const float* inp  = (const float*)d_in[0];
    const float* x    = (const float*)d_in[1];
    const float* fqkW = (const float*)d_in[2];
    const float* fqkb = (const float*)d_in[3];
    const float* fqkg = (const float*)d_in[4];
    const float* fqkbe= (const float*)d_in[5];
    const float* fqkm = (const float*)d_in[6];
    const float* fqkv = (const float*)d_in[7];
    const float* fqka = (const float*)d_in[8];
    const float* fvW  = (const float*)d_in[9];
    const float* fvb  = (const float*)d_in[10];
    const float* fvg  = (const float*)d_in[11];
    const float* fvbe = (const float*)d_in[12];
    const float* fvm  = (const float*)d_in[13];
    const float* fvv  = (const float*)d_in[14];
    const float* fva  = (const float*)d_in[15];
    const float* tqkW = (const float*)d_in[16];
    const float* tqkb = (const float*)d_in[17];
    const float* tqkg = (const float*)d_in[18];
    const float* tqkbe= (const float*)d_in[19];
    const float* tqkm = (const float*)d_in[20];
    const float* tqkv = (const float*)d_in[21];
    const float* tqka = (const float*)d_in[22];
    const float* prW  = (const float*)d_in[23];
    const float* prb  = (const float*)d_in[24];
    const float* prg  = (const float*)d_in[25];
    const float* prbe = (const float*)d_in[26];
    const float* prm  = (const float*)d_in[27];
    const float* prv  = (const float*)d_in[28];
    const float* pra  = (const float*)d_in[29];
    float* out = (float*)d_out;

    cudaFuncSetAttribute(conv_qk_kernel,
                         cudaFuncAttributeMaxDynamicSharedMemorySize, QK_SMEM);
    cudaFuncSetAttribute(conv_v_kernel,
                         cudaFuncAttributeMaxDynamicSharedMemorySize, CV_SMEM);
    cudaFuncSetAttribute(attn_kernel<false>,
                         cudaFuncAttributeMaxDynamicSharedMemorySize, ATTN_SMEM);
    cudaFuncSetAttribute(attn_kernel<true>,
                         cudaFuncAttributeMaxDynamicSharedMemorySize, ATTN_SMEM);

    fold_kernel<<<1, 256>>>(
        fqkW, fqkb, fqkg, fqkbe, fqkm, fqkv,
        tqkW, tqkb, tqkg, tqkbe, tqkm, tqkv,
        fvW,  fvb,  fvg,  fvbe,  fvm,  fvv,
        prW,  prb,  prg,  prbe,  prm,  prv);

    conv_qk_kernel<<<dim3(512, Bn), 256, QK_SMEM>>>(inp, fqka, tqka);

    conv_v_kernel<<<dim3(256, Bn), 256, CV_SMEM>>>(x, fva);

    attn_kernel<false><<<dim3(256, Bn), 256, ATTN_SMEM>>>();

    attn_kernel<true><<<dim3(256, Bn), 256, ATTN_SMEM>>>();

    proj_kernel<<<dim3(512, Bn), 256>>>(x, pra, out);
}

// round 12
// speedup vs baseline: 4.3461x; 1.3044x over previous
#include <cuda_runtime.h>
#include <cuda_bf16.h>
#include <cstdint>

// Problem constants
constexpr int Bn  = 4;
constexpr int Cn  = 64;
constexpr int CHn = 32;
constexpr int Fn  = 256;
constexpr int Tn  = 256;
constexpr int Sn  = Fn * Tn;
constexpr float EPSc = 1e-5f;
constexpr float QSCALE = 0.17677669529663687f;  // 1/sqrt(32)

// ---- packed fp32x2 helpers (FFMA2) ----
__device__ __forceinline__ unsigned long long pk2(float lo, float hi) {
    unsigned long long r;
    asm("mov.b64 %0, {%1, %2};" : "=l"(r) : "f"(lo), "f"(hi));
    return r;
}
__device__ __forceinline__ void upk2(unsigned long long v, float& lo, float& hi) {
    asm("mov.b64 {%0, %1}, %2;" : "=f"(lo), "=f"(hi) : "l"(v));
}
__device__ __forceinline__ unsigned long long fma2(
    unsigned long long a, unsigned long long b, unsigned long long c) {
    unsigned long long d;
    asm("fma.rn.f32x2 %0, %1, %2, %3;" : "=l"(d) : "l"(a), "l"(b), "l"(c));
    return d;
}
__device__ __forceinline__ uint32_t pkbf2(float lo, float hi) {
    __nv_bfloat162 h = __float22bfloat162_rn(make_float2(lo, hi));
    return *(uint32_t*)&h;
}

// ---- tensor-core helpers ----
__device__ __forceinline__ void ldsm4(uint32_t* r, uint32_t addr) {
    asm volatile("ldmatrix.sync.aligned.m8n8.x4.shared.b16 {%0,%1,%2,%3}, [%4];\n"
        : "=r"(r[0]), "=r"(r[1]), "=r"(r[2]), "=r"(r[3]) : "r"(addr));
}
__device__ __forceinline__ void mma_bf16(float* d, const uint32_t* a, const uint32_t* b) {
    asm volatile(
        "mma.sync.aligned.m16n8k16.row.col.f32.bf16.bf16.f32 "
        "{%0,%1,%2,%3}, {%4,%5,%6,%7}, {%8,%9}, {%0,%1,%2,%3};\n"
        : "+f"(d[0]), "+f"(d[1]), "+f"(d[2]), "+f"(d[3])
        : "r"(a[0]), "r"(a[1]), "r"(a[2]), "r"(a[3]), "r"(b[0]), "r"(b[1]));
}

// -------- device scratch (bf16 intermediates; tout fp32 for proj) --------
__device__ __nv_bfloat16 g_qf[Bn*Tn*Fn*CHn];
__device__ __nv_bfloat16 g_kf[Bn*Tn*Fn*CHn];
__device__ __nv_bfloat16 g_vf[Bn*Tn*Fn*CHn];
__device__ __nv_bfloat16 g_qt[Bn*Fn*Tn*CHn];
__device__ __nv_bfloat16 g_kt[Bn*Fn*Tn*CHn];
__device__ __nv_bfloat16 g_fout[Bn*Fn*Tn*CHn];
__device__ float g_tout[Bn*Fn*Tn*CHn];

// -------- folded conv parameters --------
__device__ float w_qk[64*128];
__device__ float b_qk[128];
__device__ float w_v [64*32];
__device__ float b_v [32];
__device__ float w_pr[32*64];
__device__ float b_pr[64];

// dynamic-smem sizes (bytes)
constexpr int QK_SMEM   = (64*128 + 64*128 + 128 + 2) * 4;        // 66056
constexpr int CV_SMEM   = (64*32 + 64*256 + 32 + 1) * 4;          // 73860
// attn: sK bf16 [256][40] @0 (20480) | sVT bf16 [32][264] @20480 (16896)
//       sQ bf16 [256][40] @37376 (20480)  -> total 57856
constexpr int ATTN_SMEM = 57856;

// =====================================================================
// Kernel 0: fold BN into weights/biases once.
// =====================================================================
__global__ void fold_kernel(
    const float* __restrict__ W1, const float* __restrict__ b1,
    const float* __restrict__ g1, const float* __restrict__ be1,
    const float* __restrict__ m1, const float* __restrict__ v1,
    const float* __restrict__ W2, const float* __restrict__ b2,
    const float* __restrict__ g2, const float* __restrict__ be2,
    const float* __restrict__ m2, const float* __restrict__ v2,
    const float* __restrict__ Wv, const float* __restrict__ bv,
    const float* __restrict__ gv, const float* __restrict__ bev,
    const float* __restrict__ mv, const float* __restrict__ vvv,
    const float* __restrict__ Wp, const float* __restrict__ bp,
    const float* __restrict__ gp, const float* __restrict__ bep,
    const float* __restrict__ mp, const float* __restrict__ vp)
{
    int tid = threadIdx.x;
    for (int idx = tid; idx < 8192; idx += 256) {
        int k = idx >> 7, o = idx & 127;
        float wv_; bool isq;
        if (o < 64) {
            float sc = g1[o] * rsqrtf(v1[o] + EPSc);
            wv_ = W1[o*64 + k] * sc; isq = ((o & 1) == 0);
        } else {
            int oo = o - 64;
            float sc = g2[oo] * rsqrtf(v2[oo] + EPSc);
            wv_ = W2[oo*64 + k] * sc; isq = ((oo & 1) == 0);
        }
        if (isq) wv_ *= QSCALE;
        w_qk[k*128 + o] = wv_;
    }
    if (tid < 128) {
        int o = tid;
        float bias; bool isq;
        if (o < 64) {
            float sc = g1[o] * rsqrtf(v1[o] + EPSc);
            bias = (b1[o] - m1[o]) * sc + be1[o]; isq = ((o & 1) == 0);
        } else {
            int oo = o - 64;
            float sc = g2[oo] * rsqrtf(v2[oo] + EPSc);
            bias = (b2[oo] - m2[oo]) * sc + be2[oo]; isq = ((oo & 1) == 0);
        }
        if (isq) bias *= QSCALE;
        b_qk[o] = bias;
    }
    for (int idx = tid; idx < 2048; idx += 256) {
        int k = idx >> 5, o = idx & 31;
        float sc = gv[o] * rsqrtf(vvv[o] + EPSc);
        w_v[k*32 + o] = Wv[o*64 + k] * sc;
    }
    if (tid < 32) {
        float sc = gv[tid] * rsqrtf(vvv[tid] + EPSc);
        b_v[tid] = (bv[tid] - mv[tid]) * sc + bev[tid];
    }
    for (int idx = tid; idx < 2048; idx += 256) {
        int k = idx >> 6, o = idx & 63;
        float sc = gp[o] * rsqrtf(vp[o] + EPSc);
        w_pr[k*64 + o] = Wp[o*32 + k] * sc;
    }
    if (tid < 64) {
        float sc = gp[tid] * rsqrtf(vp[tid] + EPSc);
        b_pr[tid] = (bp[tid] - mp[tid]) * sc + bep[tid];
    }
}

// =====================================================================
// Kernel 1: fused fqk + tqk conv (folded), bf16 outputs. (f32x2)
// =====================================================================
__global__ void __launch_bounds__(256) conv_qk_kernel(
    const float* __restrict__ inp,
    const float* __restrict__ a1, const float* __restrict__ a2)
{
    extern __shared__ float smqk[];
    float* sW    = smqk;               // [64][128]
    float* sIn   = smqk + 64*128;      // [64][128]
    float* sBias = smqk + 2*64*128;    // [128]
    float* sAlpha= sBias + 128;        // [2]

    int tid  = threadIdx.x;
    int b    = blockIdx.y;
    int tile = blockIdx.x;
    int p0   = tile * 128;
    int f    = p0 >> 8;
    int t0   = p0 & 255;

    #pragma unroll
    for (int jj = 0; jj < 8; jj++) {
        int idx4 = tid + jj * 256;
        *(float4*)&sW[idx4*4] = *(const float4*)&w_qk[idx4*4];
    }
    if (tid < 128) sBias[tid] = b_qk[tid];
    if (tid == 0) { sAlpha[0] = a1[0]; sAlpha[1] = a2[0]; }

    const float* ip = inp + (size_t)b * Cn * Sn + p0;
    #pragma unroll
    for (int jj = 0; jj < 8; jj++) {
        int idx4 = tid + jj * 256;
        int k  = idx4 >> 5;
        int pq = idx4 & 31;
        float4 val = *(const float4*)(ip + (size_t)k * Sn + pq * 4);
        *(float4*)&sIn[k*128 + pq*4] = val;
    }
    __syncthreads();

    int lane = tid & 31, w = tid >> 5;
    unsigned long long accp[8][4];
    #pragma unroll
    for (int i = 0; i < 8; i++)
        #pragma unroll
        for (int j = 0; j < 4; j++) accp[i][j] = 0ull;

    #pragma unroll 2
    for (int k = 0; k < 64; k++) {
        float4 A0 = *(const float4*)&sW[k*128 + w*16 + 0];
        float4 A1 = *(const float4*)&sW[k*128 + w*16 + 4];
        float4 A2 = *(const float4*)&sW[k*128 + w*16 + 8];
        float4 A3 = *(const float4*)&sW[k*128 + w*16 + 12];
        float4 Bv = *(const float4*)&sIn[k*128 + lane*4];
        unsigned long long ap[8] = {
            pk2(A0.x,A0.y), pk2(A0.z,A0.w), pk2(A1.x,A1.y), pk2(A1.z,A1.w),
            pk2(A2.x,A2.y), pk2(A2.z,A2.w), pk2(A3.x,A3.y), pk2(A3.z,A3.w)};
        unsigned long long bd[4] = {
            pk2(Bv.x,Bv.x), pk2(Bv.y,Bv.y), pk2(Bv.z,Bv.z), pk2(Bv.w,Bv.w)};
        #pragma unroll
        for (int i = 0; i < 8; i++)
            #pragma unroll
            for (int j = 0; j < 4; j++)
                accp[i][j] = fma2(ap[i], bd[j], accp[i][j]);
    }

    float acc[16][4];
    #pragma unroll
    for (int i = 0; i < 8; i++)
        #pragma unroll
        for (int j = 0; j < 4; j++)
            upk2(accp[i][j], acc[2*i][j], acc[2*i+1][j]);

    float alpha = (w < 4) ? sAlpha[0] : sAlpha[1];
    #pragma unroll
    for (int i = 0; i < 16; i++) {
        float bias = sBias[w*16 + i];
        #pragma unroll
        for (int j = 0; j < 4; j++) {
            float y = acc[i][j] + bias;
            acc[i][j] = (y > 0.f) ? y : alpha * y;
        }
    }

    int t = t0 + lane * 4;
    if (w < 4) {
        int cb = w * 8;
        #pragma unroll
        for (int j = 0; j < 4; j++) {
            size_t off = (((size_t)b*Tn + (t+j))*Fn + f)*CHn + cb;
            uint4 qu, ku;
            qu.x = pkbf2(acc[0][j],  acc[2][j]);
            qu.y = pkbf2(acc[4][j],  acc[6][j]);
            qu.z = pkbf2(acc[8][j],  acc[10][j]);
            qu.w = pkbf2(acc[12][j], acc[14][j]);
            ku.x = pkbf2(acc[1][j],  acc[3][j]);
            ku.y = pkbf2(acc[5][j],  acc[7][j]);
            ku.z = pkbf2(acc[9][j],  acc[11][j]);
            ku.w = pkbf2(acc[13][j], acc[15][j]);
            *(uint4*)(g_qf + off) = qu;
            *(uint4*)(g_kf + off) = ku;
        }
    } else {
        int cb = (w - 4) * 8;
        #pragma unroll
        for (int j = 0; j < 4; j++) {
            size_t off = (((size_t)b*Fn + f)*Tn + (t+j))*CHn + cb;
            uint4 qu, ku;
            qu.x = pkbf2(acc[0][j],  acc[2][j]);
            qu.y = pkbf2(acc[4][j],  acc[6][j]);
            qu.z = pkbf2(acc[8][j],  acc[10][j]);
            qu.w = pkbf2(acc[12][j], acc[14][j]);
            ku.x = pkbf2(acc[1][j],  acc[3][j]);
            ku.y = pkbf2(acc[5][j],  acc[7][j]);
            ku.z = pkbf2(acc[9][j],  acc[11][j]);
            ku.w = pkbf2(acc[13][j], acc[15][j]);
            *(uint4*)(g_qt + off) = qu;
            *(uint4*)(g_kt + off) = ku;
        }
    }
}

// =====================================================================
// Kernel 2: fv conv (folded), bf16 output. (f32x2)
// =====================================================================
__global__ void __launch_bounds__(256) conv_v_kernel(
    const float* __restrict__ xin, const float* __restrict__ aa)
{
    extern __shared__ float smcv[];
    float* sW    = smcv;              // [64][32]
    float* sIn   = smcv + 64*32;      // [64][256]
    float* sBias = sIn + 64*256;      // [32]
    float* sAlpha= sBias + 32;        // [1]

    int tid = threadIdx.x;
    int f = blockIdx.x, b = blockIdx.y;

    #pragma unroll
    for (int jj = 0; jj < 2; jj++) {
        int idx4 = tid + jj*256;
        *(float4*)&sW[idx4*4] = *(const float4*)&w_v[idx4*4];
    }
    if (tid < 32) sBias[tid] = b_v[tid];
    if (tid == 0) sAlpha[0] = aa[0];

    const float* ip = xin + (size_t)b*Cn*Sn + (size_t)f*Tn;
    #pragma unroll
    for (int jj = 0; jj < 16; jj++) {
        int idx4 = tid + jj*256;
        int k = idx4 >> 6, pq = idx4 & 63;
        *(float4*)&sIn[k*256 + pq*4] = *(const float4*)(ip + (size_t)k*Sn + pq*4);
    }
    __syncthreads();

    int lane = tid & 31, w = tid >> 5;
    int cg = w & 3, ph = w >> 2;
    unsigned long long accp[4][4];
    #pragma unroll
    for (int i = 0; i < 4; i++)
        #pragma unroll
        for (int j = 0; j < 4; j++) accp[i][j] = 0ull;

    #pragma unroll 2
    for (int k = 0; k < 64; k++) {
        float4 A0 = *(const float4*)&sW[k*32 + cg*8];
        float4 A1 = *(const float4*)&sW[k*32 + cg*8 + 4];
        float4 Bv = *(const float4*)&sIn[k*256 + ph*128 + lane*4];
        unsigned long long ap[4] = {
            pk2(A0.x,A0.y), pk2(A0.z,A0.w), pk2(A1.x,A1.y), pk2(A1.z,A1.w)};
        unsigned long long bd[4] = {
            pk2(Bv.x,Bv.x), pk2(Bv.y,Bv.y), pk2(Bv.z,Bv.z), pk2(Bv.w,Bv.w)};
        #pragma unroll
        for (int i = 0; i < 4; i++)
            #pragma unroll
            for (int j = 0; j < 4; j++)
                accp[i][j] = fma2(ap[i], bd[j], accp[i][j]);
    }

    float acc[8][4];
    #pragma unroll
    for (int i = 0; i < 4; i++)
        #pragma unroll
        for (int j = 0; j < 4; j++)
            upk2(accp[i][j], acc[2*i][j], acc[2*i+1][j]);

    float alpha = sAlpha[0];
    int c = cg * 8;
    #pragma unroll
    for (int j = 0; j < 4; j++) {
        int t = ph*128 + lane*4 + j;
        float r[8];
        #pragma unroll
        for (int i = 0; i < 8; i++) {
            float y = acc[i][j] + sBias[c + i];
            r[i] = (y > 0.f) ? y : alpha * y;
        }
        size_t off = (((size_t)b*Tn + t)*Fn + f)*CHn + c;
        uint4 u;
        u.x = pkbf2(r[0], r[1]); u.y = pkbf2(r[2], r[3]);
        u.z = pkbf2(r[4], r[5]); u.w = pkbf2(r[6], r[7]);
        *(uint4*)(g_vf + off) = u;
    }
}

// =====================================================================
// Attention kernel — v8 (FlashAttention-2 warp tiling):
//  * one barrier per block (K, V^T, Q all staged up-front)
//  * warp owns 16 full rows; online softmax over 64-col quarters
//  * P reused directly as mma A-fragments (C->A register repack)
//  * O in registers; direct gmem writes
//  * causal: quarter skip + k-tile skip + diagonal mask
// =====================================================================
template<bool CAUSAL>
__global__ void __launch_bounds__(256, 2) attn_kernel()
{
    const __nv_bfloat16* __restrict__ qg = CAUSAL ? g_qt : g_qf;
    const __nv_bfloat16* __restrict__ kg = CAUSAL ? g_kt : g_kf;
    const __nv_bfloat16* __restrict__ vg = CAUSAL ? g_fout : g_vf;

    extern __shared__ char smb[];
    constexpr int KOFF = 0, VOFF = 20480, QOFF = 37376;
    __nv_bfloat16* sK  = (__nv_bfloat16*)(smb + KOFF);   // [256][40]
    __nv_bfloat16* sVT = (__nv_bfloat16*)(smb + VOFF);   // [32][264]
    __nv_bfloat16* sQ  = (__nv_bfloat16*)(smb + QOFF);   // [256][40]
    uint32_t sb = (uint32_t)__cvta_generic_to_shared(smb);

    int tid = threadIdx.x, lane = tid & 31, w = tid >> 5;
    int g = lane >> 2, t2 = (lane & 3) * 2;
    int col = blockIdx.x;
    int b   = blockIdx.y;
    size_t base = ((size_t)b * 256 + col) * 256 * CHn;
    const __nv_bfloat16* qp = qg + base;
    const __nv_bfloat16* kp = kg + base;
    const __nv_bfloat16* vp = vg + base;
    size_t out_base, out_stride;
    if (CAUSAL) { out_base = base; out_stride = CHn; }
    else { out_base = ((size_t)b * Sn + col) * CHn; out_stride = (size_t)Tn * CHn; }

    // ---- stage K [y][40], Q [r][40], V^T [c][264] ----
    #pragma unroll
    for (int jj = 0; jj < 4; jj++) {
        int idx = tid + jj*256;              // 0..1023 (uint4 = 8 bf16)
        int y = idx >> 2, q4 = idx & 3;
        *(uint4*)&sK[y*40 + q4*8] = *(const uint4*)(kp + y*32 + q4*8);
        *(uint4*)&sQ[y*40 + q4*8] = *(const uint4*)(qp + y*32 + q4*8);
        union { uint4 u; __nv_bfloat16 h[8]; } vv;
        vv.u = *(const uint4*)(vp + y*32 + q4*8);
        #pragma unroll
        for (int c8 = 0; c8 < 8; c8++)
            sVT[(q4*8 + c8)*264 + y] = vv.h[c8];
    }
    __syncthreads();   // the only barrier

    #pragma unroll
    for (int it = 0; it < 2; it++) {
        const int wr0 = it*128 + w*16;

        // Q A-fragments for this warp's 16 rows (k = 32)
        uint32_t qa[2][4];
        #pragma unroll
        for (int ks = 0; ks < 2; ks++) {
            int row = wr0 + (lane & 15);
            int cc  = ks*16 + (lane >> 4) * 8;
            ldsm4(qa[ks], sb + QOFF + (uint32_t)(row*40 + cc)*2);
        }

        float O[4][4];
        #pragma unroll
        for (int i = 0; i < 4; i++)
            #pragma unroll
            for (int j = 0; j < 4; j++) O[i][j] = 0.f;
        float mA = -1e30f, mB = -1e30f, lA = 0.f, lB = 0.f;

        const int qmax = CAUSAL ? ((wr0 >> 6) + 1) : 4;

        for (int q = 0; q < qmax; q++) {
            // ---- score: D[nt] = Q(16x32) * K^T slice (cols q*64+nt*8..+7)
            float D[8][4];
            #pragma unroll
            for (int nt = 0; nt < 8; nt++)
                #pragma unroll
                for (int j = 0; j < 4; j++) D[nt][j] = 0.f;

            #pragma unroll
            for (int nt = 0; nt < 8; nt++) {
                if (!CAUSAL || (q*64 + nt*8 <= wr0 + 15)) {
                    uint32_t kb[4];
                    int y = q*64 + nt*8 + (lane & 7);
                    int k = (lane >> 3) * 8;
                    ldsm4(kb, sb + KOFF + (uint32_t)(y*40 + k)*2);
                    mma_bf16(D[nt], qa[0], &kb[0]);
                    mma_bf16(D[nt], qa[1], &kb[2]);
                }
            }
            if (CAUSAL) {
                #pragma unroll
                for (int nt = 0; nt < 8; nt++) {
                    int y0 = q*64 + nt*8 + t2;
                    int rA = wr0 + g, rB = rA + 8;
                    if (y0     > rA) D[nt][0] = -1e30f;
                    if (y0 + 1 > rA) D[nt][1] = -1e30f;
                    if (y0     > rB) D[nt][2] = -1e30f;
                    if (y0 + 1 > rB) D[nt][3] = -1e30f;
                }
            }

            // ---- online softmax update
            float mqA = -1e30f, mqB = -1e30f;
            #pragma unroll
            for (int nt = 0; nt < 8; nt++) {
                mqA = fmaxf(mqA, fmaxf(D[nt][0], D[nt][1]));
                mqB = fmaxf(mqB, fmaxf(D[nt][2], D[nt][3]));
            }
            #pragma unroll
            for (int dlt = 1; dlt <= 2; dlt <<= 1) {
                mqA = fmaxf(mqA, __shfl_xor_sync(0xffffffffu, mqA, dlt));
                mqB = fmaxf(mqB, __shfl_xor_sync(0xffffffffu, mqB, dlt));
            }
            float mnA = fmaxf(mA, mqA), mnB = fmaxf(mB, mqB);
            float corrA = __expf(mA - mnA), corrB = __expf(mB - mnB);
            mA = mnA; mB = mnB;
            #pragma unroll
            for (int i = 0; i < 4; i++) {
                O[i][0] *= corrA; O[i][1] *= corrA;
                O[i][2] *= corrB; O[i][3] *= corrB;
            }

            uint32_t P[8][2];
            float sqA = 0.f, sqB = 0.f;
            #pragma unroll
            for (int nt = 0; nt < 8; nt++) {
                float e0 = __expf(D[nt][0] - mA);
                float e1 = __expf(D[nt][1] - mA);
                float e2 = __expf(D[nt][2] - mB);
                float e3 = __expf(D[nt][3] - mB);
                sqA += e0 + e1; sqB += e2 + e3;
                P[nt][0] = pkbf2(e0, e1);
                P[nt][1] = pkbf2(e2, e3);
            }
            #pragma unroll
            for (int dlt = 1; dlt <= 2; dlt <<= 1) {
                sqA += __shfl_xor_sync(0xffffffffu, sqA, dlt);
                sqB += __shfl_xor_sync(0xffffffffu, sqB, dlt);
            }
            lA = lA * corrA + sqA;
            lB = lB * corrB + sqB;

            // ---- PV: O += P(16 x 64) * V slice (64 x 32)
            #pragma unroll
            for (int kc2 = 0; kc2 < 2; kc2++) {
                if (CAUSAL && (q*64 + kc2*32 > wr0 + 15)) continue;
                uint32_t aF0[4] = {P[kc2*4+0][0], P[kc2*4+0][1],
                                   P[kc2*4+1][0], P[kc2*4+1][1]};
                uint32_t aF1[4] = {P[kc2*4+2][0], P[kc2*4+2][1],
                                   P[kc2*4+3][0], P[kc2*4+3][1]};
                #pragma unroll
                for (int ntv = 0; ntv < 4; ntv++) {
                    uint32_t vb[4];
                    int c = ntv*8 + (lane & 7);
                    int y = q*64 + kc2*32 + (lane >> 3) * 8;
                    ldsm4(vb, sb + VOFF + (uint32_t)(c*264 + y)*2);
                    mma_bf16(O[ntv], aF0, &vb[0]);
                    mma_bf16(O[ntv], aF1, &vb[2]);
                }
            }
        }

        // ---- normalize + write out
        float invA = 1.f / lA, invB = 1.f / lB;
        int rA = wr0 + g, rB = rA + 8;
        #pragma unroll
        for (int ntv = 0; ntv < 4; ntv++) {
            int c = ntv*8 + t2;
            if (CAUSAL) {
                *(float2*)(g_tout + out_base + (size_t)rA*out_stride + c) =
                    make_float2(O[ntv][0]*invA, O[ntv][1]*invA);
                *(float2*)(g_tout + out_base + (size_t)rB*out_stride + c) =
                    make_float2(O[ntv][2]*invB, O[ntv][3]*invB);
            } else {
                *(uint32_t*)(g_fout + out_base + (size_t)rA*out_stride + c) =
                    pkbf2(O[ntv][0]*invA, O[ntv][1]*invA);
                *(uint32_t*)(g_fout + out_base + (size_t)rB*out_stride + c) =
                    pkbf2(O[ntv][2]*invB, O[ntv][3]*invB);
            }
        }
    }
}

// =====================================================================
// Kernel 5: proj conv (folded) + residual -> fp32 out. (f32x2)
// =====================================================================
__global__ void __launch_bounds__(256) proj_kernel(
    const float* __restrict__ xin, const float* __restrict__ aa,
    float* __restrict__ outp)
{
    __shared__ float sW[32][64];
    __shared__ float sIn[32][132];
    __shared__ float sBias[64];
    __shared__ float sAlpha;

    int tid = threadIdx.x;
    int tile = blockIdx.x, b = blockIdx.y;
    int p0 = tile * 128;

    #pragma unroll
    for (int jj = 0; jj < 2; jj++) {
        int idx4 = tid + jj*256;
        *(float4*)&((float*)sW)[idx4*4] = *(const float4*)&w_pr[idx4*4];
    }
    if (tid < 64) sBias[tid] = b_pr[tid];
    if (tid == 0) sAlpha = aa[0];

    const float* tp = g_tout + ((size_t)b*Sn + p0) * CHn;
    #pragma unroll
    for (int jj = 0; jj < 4; jj++) {
        int idx4 = tid + jj*256;
        int p = idx4 >> 3, cq = idx4 & 7;
        float4 tv = ((const float4*)tp)[idx4];
        sIn[cq*4+0][p] = tv.x;
        sIn[cq*4+1][p] = tv.y;
        sIn[cq*4+2][p] = tv.z;
        sIn[cq*4+3][p] = tv.w;
    }
    __syncthreads();

    int lane = tid & 31, w = tid >> 5;
    unsigned long long accp[4][4];
    #pragma unroll
    for (int i = 0; i < 4; i++)
        #pragma unroll
        for (int j = 0; j < 4; j++) accp[i][j] = 0ull;

    #pragma unroll 2
    for (int k = 0; k < 32; k++) {
        float4 A0 = *(const float4*)&sW[k][w*8];
        float4 A1 = *(const float4*)&sW[k][w*8 + 4];
        float4 Bv = *(const float4*)&sIn[k][lane*4];
        unsigned long long ap[4] = {
            pk2(A0.x,A0.y), pk2(A0.z,A0.w), pk2(A1.x,A1.y), pk2(A1.z,A1.w)};
        unsigned long long bd[4] = {
            pk2(Bv.x,Bv.x), pk2(Bv.y,Bv.y), pk2(Bv.z,Bv.z), pk2(Bv.w,Bv.w)};
        #pragma unroll
        for (int i = 0; i < 4; i++)
            #pragma unroll
            for (int j = 0; j < 4; j++)
                accp[i][j] = fma2(ap[i], bd[j], accp[i][j]);
    }

    float acc[8][4];
    #pragma unroll
    for (int i = 0; i < 4; i++)
        #pragma unroll
        for (int j = 0; j < 4; j++)
            upk2(accp[i][j], acc[2*i][j], acc[2*i+1][j]);

    float alpha = sAlpha;
    const float* xb = xin + (size_t)b*Cn*Sn + p0 + lane*4;
    float*       ob = outp + (size_t)b*Cn*Sn + p0 + lane*4;
    #pragma unroll
    for (int i = 0; i < 8; i++) {
        int o = w*8 + i;
        float bias = sBias[o];
        float4 xr = *(const float4*)(xb + (size_t)o*Sn);
        float r0 = acc[i][0] + bias; r0 = (r0 > 0.f) ? r0 : alpha*r0; r0 += xr.x;
        float r1 = acc[i][1] + bias; r1 = (r1 > 0.f) ? r1 : alpha*r1; r1 += xr.y;
        float r2 = acc[i][2] + bias; r2 = (r2 > 0.f) ? r2 : alpha*r2; r2 += xr.z;
        float r3 = acc[i][3] + bias; r3 = (r3 > 0.f) ? r3 : alpha*r3; r3 += xr.w;
        *(float4*)(ob + (size_t)o*Sn) = make_float4(r0, r1, r2, r3);
    }
}

// =====================================================================
// Launch
// =====================================================================
extern "C" void kernel_launch(void* const* d_in, const int* in_sizes, int n_in,
                              void* d_out, int out_size) {
    const float* inp  = (const float*)d_in[0];
    const float* x    = (const float*)d_in[1];
    const float* fqkW = (const float*)d_in[2];
    const float* fqkb = (const float*)d_in[3];
    const float* fqkg = (const float*)d_in[4];
    const float* fqkbe= (const float*)d_in[5];
    const float* fqkm = (const float*)d_in[6];
    const float* fqkv = (const float*)d_in[7];
    const float* fqka = (const float*)d_in[8];
    const float* fvW  = (const float*)d_in[9];
    const float* fvb  = (const float*)d_in[10];
    const float* fvg  = (const float*)d_in[11];
    const float* fvbe = (const float*)d_in[12];
    const float* fvm  = (const float*)d_in[13];
    const float* fvv  = (const float*)d_in[14];
    const float* fva  = (const float*)d_in[15];
    const float* tqkW = (const float*)d_in[16];
    const float* tqkb = (const float*)d_in[17];
    const float* tqkg = (const float*)d_in[18];
    const float* tqkbe= (const float*)d_in[19];
    const float* tqkm = (const float*)d_in[20];
    const float* tqkv = (const float*)d_in[21];
    const float* tqka = (const float*)d_in[22];
    const float* prW  = (const float*)d_in[23];
    const float* prb  = (const float*)d_in[24];
    const float* prg  = (const float*)d_in[25];
    const float* prbe = (const float*)d_in[26];
    const float* prm  = (const float*)d_in[27];
    const float* prv  = (const float*)d_in[28];
    const float* pra  = (const float*)d_in[29];
    float* out = (float*)d_out;

    cudaFuncSetAttribute(conv_qk_kernel,
                         cudaFuncAttributeMaxDynamicSharedMemorySize, QK_SMEM);
    cudaFuncSetAttribute(conv_v_kernel,
                         cudaFuncAttributeMaxDynamicSharedMemorySize, CV_SMEM);
    cudaFuncSetAttribute(attn_kernel<false>,
                         cudaFuncAttributeMaxDynamicSharedMemorySize, ATTN_SMEM);
    cudaFuncSetAttribute(attn_kernel<true>,
                         cudaFuncAttributeMaxDynamicSharedMemorySize, ATTN_SMEM);

    fold_kernel<<<1, 256>>>(
        fqkW, fqkb, fqkg, fqkbe, fqkm, fqkv,
        tqkW, tqkb, tqkg, tqkbe, tqkm, tqkv,
        fvW,  fvb,  fvg,  fvbe,  fvm,  fvv,
        prW,  prb,  prg,  prbe,  prm,  prv);

    conv_qk_kernel<<<dim3(512, Bn), 256, QK_SMEM>>>(inp, fqka, tqka);

    conv_v_kernel<<<dim3(256, Bn), 256, CV_SMEM>>>(x, fva);

    attn_kernel<false><<<dim3(256, Bn), 256, ATTN_SMEM>>>();

    attn_kernel<true><<<dim3(256, Bn), 256, ATTN_SMEM>>>();

    proj_kernel<<<dim3(512, Bn), 256>>>(x, pra, out);
}

// round 13
// speedup vs baseline: 5.6521x; 1.3005x over previous
#include <cuda_runtime.h>
#include <cuda_bf16.h>
#include <cstdint>

// Problem constants
constexpr int Bn  = 4;
constexpr int Cn  = 64;
constexpr int CHn = 32;
constexpr int Fn  = 256;
constexpr int Tn  = 256;
constexpr int Sn  = Fn * Tn;
constexpr float EPSc = 1e-5f;
constexpr float QSCALE = 0.17677669529663687f;  // 1/sqrt(32)

__device__ __forceinline__ uint32_t pkbf2(float lo, float hi) {
    __nv_bfloat162 h = __float22bfloat162_rn(make_float2(lo, hi));
    return *(uint32_t*)&h;
}

// ---- tensor-core helpers ----
__device__ __forceinline__ void ldsm4(uint32_t* r, uint32_t addr) {
    asm volatile("ldmatrix.sync.aligned.m8n8.x4.shared.b16 {%0,%1,%2,%3}, [%4];\n"
        : "=r"(r[0]), "=r"(r[1]), "=r"(r[2]), "=r"(r[3]) : "r"(addr));
}
__device__ __forceinline__ void ldsm4t(uint32_t* r, uint32_t addr) {
    asm volatile("ldmatrix.sync.aligned.m8n8.x4.trans.shared.b16 {%0,%1,%2,%3}, [%4];\n"
        : "=r"(r[0]), "=r"(r[1]), "=r"(r[2]), "=r"(r[3]) : "r"(addr));
}
__device__ __forceinline__ void mma_bf16(float* d, const uint32_t* a, const uint32_t* b) {
    asm volatile(
        "mma.sync.aligned.m16n8k16.row.col.f32.bf16.bf16.f32 "
        "{%0,%1,%2,%3}, {%4,%5,%6,%7}, {%8,%9}, {%0,%1,%2,%3};\n"
        : "+f"(d[0]), "+f"(d[1]), "+f"(d[2]), "+f"(d[3])
        : "r"(a[0]), "r"(a[1]), "r"(a[2]), "r"(a[3]), "r"(b[0]), "r"(b[1]));
}

// -------- device scratch (all intermediates bf16) --------
__device__ __nv_bfloat16 g_qf[Bn*Tn*Fn*CHn];
__device__ __nv_bfloat16 g_kf[Bn*Tn*Fn*CHn];
__device__ __nv_bfloat16 g_vf[Bn*Tn*Fn*CHn];
__device__ __nv_bfloat16 g_qt[Bn*Fn*Tn*CHn];
__device__ __nv_bfloat16 g_kt[Bn*Fn*Tn*CHn];
__device__ __nv_bfloat16 g_fout[Bn*Fn*Tn*CHn];
__device__ __nv_bfloat16 g_tout[Bn*Fn*Tn*CHn];

// -------- folded bf16 weights [o][k] + fp32 biases --------
// wqk_bf rows permuted: 0..31 fqk-q, 32..63 fqk-k, 64..95 tqk-q, 96..127 tqk-k
__device__ __nv_bfloat16 wqk_bf[128*72];
__device__ float b_qk[128];
__device__ __nv_bfloat16 wv_bf[32*72];
__device__ float b_v[32];
__device__ __nv_bfloat16 wpr_bf[64*40];
__device__ float b_pr[64];

// dynamic-smem sizes (bytes)
constexpr int CQK_SMEM  = 17408 + 18432 + 34816 + 512 + 8;   // 71176
constexpr int CV_SMEM   = 33792 + 4608 + 20480 + 128 + 4;    // 59012
constexpr int PR_SMEM   = 10240 + 5120 + 33792 + 256 + 4;    // 49412
constexpr int ATTN_SMEM = 57856;  // sK[256][40] | sVT[32][264] | sQ[256][40]

// =====================================================================
// Kernel 0: fold BN into bf16 weights / fp32 biases once.
// =====================================================================
__global__ void fold_kernel(
    const float* __restrict__ W1, const float* __restrict__ b1,
    const float* __restrict__ g1, const float* __restrict__ be1,
    const float* __restrict__ m1, const float* __restrict__ v1,
    const float* __restrict__ W2, const float* __restrict__ b2,
    const float* __restrict__ g2, const float* __restrict__ be2,
    const float* __restrict__ m2, const float* __restrict__ v2,
    const float* __restrict__ Wv, const float* __restrict__ bv,
    const float* __restrict__ gv, const float* __restrict__ bev,
    const float* __restrict__ mv, const float* __restrict__ vvv,
    const float* __restrict__ Wp, const float* __restrict__ bp,
    const float* __restrict__ gp, const float* __restrict__ bep,
    const float* __restrict__ mp, const float* __restrict__ vp)
{
    int tid = threadIdx.x;
    // fqk + tqk fused, rows de-interleaved (q first, then k per group)
    for (int idx = tid; idx < 8192; idx += 256) {
        int o = idx >> 6, k = idx & 63;
        float wv_; int grp, oo;
        if (o < 64) {
            grp = 0; oo = o;
            float sc = g1[o] * rsqrtf(v1[o] + EPSc);
            wv_ = W1[o*64 + k] * sc;
        } else {
            grp = 1; oo = o - 64;
            float sc = g2[oo] * rsqrtf(v2[oo] + EPSc);
            wv_ = W2[oo*64 + k] * sc;
        }
        bool isq = ((oo & 1) == 0);
        if (isq) wv_ *= QSCALE;
        int op = grp*64 + (isq ? 0 : 32) + (oo >> 1);
        wqk_bf[op*72 + k] = __float2bfloat16(wv_);
    }
    if (tid < 128) {
        int o = tid;
        float bias; int grp, oo;
        if (o < 64) {
            grp = 0; oo = o;
            float sc = g1[o] * rsqrtf(v1[o] + EPSc);
            bias = (b1[o] - m1[o]) * sc + be1[o];
        } else {
            grp = 1; oo = o - 64;
            float sc = g2[oo] * rsqrtf(v2[oo] + EPSc);
            bias = (b2[oo] - m2[oo]) * sc + be2[oo];
        }
        bool isq = ((oo & 1) == 0);
        if (isq) bias *= QSCALE;
        int op = grp*64 + (isq ? 0 : 32) + (oo >> 1);
        b_qk[op] = bias;
    }
    // fv
    for (int idx = tid; idx < 2048; idx += 256) {
        int o = idx >> 6, k = idx & 63;
        float sc = gv[o] * rsqrtf(vvv[o] + EPSc);
        wv_bf[o*72 + k] = __float2bfloat16(Wv[o*64 + k] * sc);
    }
    if (tid < 32) {
        float sc = gv[tid] * rsqrtf(vvv[tid] + EPSc);
        b_v[tid] = (bv[tid] - mv[tid]) * sc + bev[tid];
    }
    // proj
    for (int idx = tid; idx < 2048; idx += 256) {
        int o = idx >> 5, k = idx & 31;
        float sc = gp[o] * rsqrtf(vp[o] + EPSc);
        wpr_bf[o*40 + k] = __float2bfloat16(Wp[o*32 + k] * sc);
    }
    if (tid < 64) {
        float sc = gp[tid] * rsqrtf(vp[tid] + EPSc);
        b_pr[tid] = (bp[tid] - mp[tid]) * sc + bep[tid];
    }
}

// =====================================================================
// Kernel 1: fused fqk+tqk conv, tensor cores.
// Block: 128 positions x 128 outputs, K=64. A via ldmatrix.trans.
// smem: sIn[64][136] @0 | sW[128][72] @17408 | sOut[128][136] @35840
//       bias @70656 | alpha @71168
// =====================================================================
__global__ void __launch_bounds__(256) conv_qk_kernel(
    const float* __restrict__ inp,
    const float* __restrict__ a1, const float* __restrict__ a2)
{
    extern __shared__ char smc[];
    __nv_bfloat16* sIn = (__nv_bfloat16*)smc;
    __nv_bfloat16* sW  = (__nv_bfloat16*)(smc + 17408);
    __nv_bfloat16* sOut= (__nv_bfloat16*)(smc + 35840);
    float* sBias = (float*)(smc + 70656);
    float* sAl   = (float*)(smc + 71168);
    uint32_t sb = (uint32_t)__cvta_generic_to_shared(smc);

    int tid = threadIdx.x, b = blockIdx.y, tile = blockIdx.x;
    int p0 = tile*128, f = p0 >> 8, t0 = p0 & 255;

    #pragma unroll
    for (int i = tid; i < 1152; i += 256)
        ((uint4*)sW)[i] = ((const uint4*)wqk_bf)[i];
    if (tid < 128) sBias[tid] = b_qk[tid];
    if (tid == 0) { sAl[0] = a1[0]; sAl[1] = a2[0]; }

    const float* ip = inp + (size_t)b*Cn*Sn + p0;
    #pragma unroll
    for (int jj = 0; jj < 8; jj++) {
        int idx4 = tid + jj*256;
        int k = idx4 >> 5, p4 = (idx4 & 31)*4;
        float4 v = *(const float4*)(ip + (size_t)k*Sn + p4);
        *(uint32_t*)&sIn[k*136 + p4]     = pkbf2(v.x, v.y);
        *(uint32_t*)&sIn[k*136 + p4 + 2] = pkbf2(v.z, v.w);
    }
    __syncthreads();

    int lane = tid & 31, w = tid >> 5;
    int g = lane >> 2, t2 = (lane & 3)*2;

    // A frags (positions w*16..+15, all k) via trans ldsm
    uint32_t qa[4][4];
    {
        int krow = (lane & 7) + ((lane >> 4) << 3);
        int col  = w*16 + ((lane >> 3) & 1)*8;
        #pragma unroll
        for (int ks = 0; ks < 4; ks++)
            ldsm4t(qa[ks], sb + (uint32_t)((ks*16 + krow)*136 + col)*2);
    }

    float alF = sAl[0], alT = sAl[1];
    #pragma unroll
    for (int nt = 0; nt < 16; nt++) {
        uint32_t kb0[4], kb1[4];
        uint32_t baddr = sb + 17408 +
            (uint32_t)((nt*8 + (lane & 7))*72 + (lane >> 3)*8)*2;
        ldsm4(kb0, baddr);
        ldsm4(kb1, baddr + 64);
        float D[4] = {0.f, 0.f, 0.f, 0.f};
        mma_bf16(D, qa[0], kb0 + 0);
        mma_bf16(D, qa[1], kb0 + 2);
        mma_bf16(D, qa[2], kb1 + 0);
        mma_bf16(D, qa[3], kb1 + 2);
        float al = (nt < 8) ? alF : alT;
        float b0 = sBias[nt*8 + t2], b1 = sBias[nt*8 + t2 + 1];
        float v0 = D[0] + b0; v0 = (v0 > 0.f) ? v0 : al*v0;
        float v1 = D[1] + b1; v1 = (v1 > 0.f) ? v1 : al*v1;
        float v2 = D[2] + b0; v2 = (v2 > 0.f) ? v2 : al*v2;
        float v3 = D[3] + b1; v3 = (v3 > 0.f) ? v3 : al*v3;
        int p = w*16 + g;
        *(uint32_t*)&sOut[p*136 + nt*8 + t2]       = pkbf2(v0, v1);
        *(uint32_t*)&sOut[(p+8)*136 + nt*8 + t2]   = pkbf2(v2, v3);
    }
    __syncthreads();

    // copy out: 2048 uint4; arr uniform per (warp, j)
    #pragma unroll
    for (int j = 0; j < 8; j++) {
        int idx = tid + j*256;
        int arr = idx >> 9;
        int pos = (idx >> 2) & 127;
        int c   = (idx & 3)*8;
        uint4 v = *(const uint4*)&sOut[pos*136 + arr*32 + c];
        int t = t0 + pos;
        if (arr == 0)
            *(uint4*)(g_qf + (((size_t)b*Tn + t)*Fn + f)*CHn + c) = v;
        else if (arr == 1)
            *(uint4*)(g_kf + (((size_t)b*Tn + t)*Fn + f)*CHn + c) = v;
        else if (arr == 2)
            *(uint4*)(g_qt + (((size_t)b*Fn + f)*Tn + t)*CHn + c) = v;
        else
            *(uint4*)(g_kt + (((size_t)b*Fn + f)*Tn + t)*CHn + c) = v;
    }
}

// =====================================================================
// Kernel 2: fv conv, tensor cores. Block: 256 positions (one f row) x 32.
// smem: sIn[64][264] @0 | sW[32][72] @33792 | sOut[256][40] @38400
//       bias @58880 | alpha @59008
// =====================================================================
__global__ void __launch_bounds__(256) conv_v_kernel(
    const float* __restrict__ xin, const float* __restrict__ aa)
{
    extern __shared__ char smc[];
    __nv_bfloat16* sIn = (__nv_bfloat16*)smc;
    __nv_bfloat16* sW  = (__nv_bfloat16*)(smc + 33792);
    __nv_bfloat16* sOut= (__nv_bfloat16*)(smc + 38400);
    float* sBias = (float*)(smc + 58880);
    float* sAl   = (float*)(smc + 59008);
    uint32_t sb = (uint32_t)__cvta_generic_to_shared(smc);

    int tid = threadIdx.x, f = blockIdx.x, b = blockIdx.y;

    #pragma unroll
    for (int i = tid; i < 288; i += 256)
        ((uint4*)sW)[i] = ((const uint4*)wv_bf)[i];
    if (tid < 32) sBias[tid] = b_v[tid];
    if (tid == 0) sAl[0] = aa[0];

    const float* ip = xin + (size_t)b*Cn*Sn + (size_t)f*Tn;
    #pragma unroll
    for (int jj = 0; jj < 16; jj++) {
        int idx4 = tid + jj*256;
        int k = idx4 >> 6, t4 = (idx4 & 63)*4;
        float4 v = *(const float4*)(ip + (size_t)k*Sn + t4);
        *(uint32_t*)&sIn[k*264 + t4]     = pkbf2(v.x, v.y);
        *(uint32_t*)&sIn[k*264 + t4 + 2] = pkbf2(v.z, v.w);
    }
    __syncthreads();

    int lane = tid & 31, w = tid >> 5;
    int g = lane >> 2, t2 = (lane & 3)*2;

    uint32_t qa[2][4][4];
    {
        int krow = (lane & 7) + ((lane >> 4) << 3);
        #pragma unroll
        for (int mt = 0; mt < 2; mt++) {
            int col = w*32 + mt*16 + ((lane >> 3) & 1)*8;
            #pragma unroll
            for (int ks = 0; ks < 4; ks++)
                ldsm4t(qa[mt][ks], sb + (uint32_t)((ks*16 + krow)*264 + col)*2);
        }
    }

    float al = sAl[0];
    #pragma unroll
    for (int nt = 0; nt < 4; nt++) {
        uint32_t kb0[4], kb1[4];
        uint32_t baddr = sb + 33792 +
            (uint32_t)((nt*8 + (lane & 7))*72 + (lane >> 3)*8)*2;
        ldsm4(kb0, baddr);
        ldsm4(kb1, baddr + 64);
        float b0 = sBias[nt*8 + t2], b1 = sBias[nt*8 + t2 + 1];
        #pragma unroll
        for (int mt = 0; mt < 2; mt++) {
            float D[4] = {0.f, 0.f, 0.f, 0.f};
            mma_bf16(D, qa[mt][0], kb0 + 0);
            mma_bf16(D, qa[mt][1], kb0 + 2);
            mma_bf16(D, qa[mt][2], kb1 + 0);
            mma_bf16(D, qa[mt][3], kb1 + 2);
            float v0 = D[0] + b0; v0 = (v0 > 0.f) ? v0 : al*v0;
            float v1 = D[1] + b1; v1 = (v1 > 0.f) ? v1 : al*v1;
            float v2 = D[2] + b0; v2 = (v2 > 0.f) ? v2 : al*v2;
            float v3 = D[3] + b1; v3 = (v3 > 0.f) ? v3 : al*v3;
            int p = w*32 + mt*16 + g;
            *(uint32_t*)&sOut[p*40 + nt*8 + t2]     = pkbf2(v0, v1);
            *(uint32_t*)&sOut[(p+8)*40 + nt*8 + t2] = pkbf2(v2, v3);
        }
    }
    __syncthreads();

    #pragma unroll
    for (int j = 0; j < 4; j++) {
        int idx = tid + j*256;
        int pos = idx >> 2;
        int c   = (idx & 3)*8;
        uint4 v = *(const uint4*)&sOut[pos*40 + c];
        *(uint4*)(g_vf + (((size_t)b*Tn + pos)*Fn + f)*CHn + c) = v;
    }
}

// =====================================================================
// Attention kernel — v8 (FA2 warp tiling), bf16 in/out.
// =====================================================================
template<bool CAUSAL>
__global__ void __launch_bounds__(256, 2) attn_kernel()
{
    const __nv_bfloat16* __restrict__ qg = CAUSAL ? g_qt : g_qf;
    const __nv_bfloat16* __restrict__ kg = CAUSAL ? g_kt : g_kf;
    const __nv_bfloat16* __restrict__ vg = CAUSAL ? g_fout : g_vf;
    __nv_bfloat16* __restrict__ outg     = CAUSAL ? g_tout : g_fout;

    extern __shared__ char smb[];
    constexpr int KOFF = 0, VOFF = 20480, QOFF = 37376;
    __nv_bfloat16* sK  = (__nv_bfloat16*)(smb + KOFF);   // [256][40]
    __nv_bfloat16* sVT = (__nv_bfloat16*)(smb + VOFF);   // [32][264]
    __nv_bfloat16* sQ  = (__nv_bfloat16*)(smb + QOFF);   // [256][40]
    uint32_t sb = (uint32_t)__cvta_generic_to_shared(smb);

    int tid = threadIdx.x, lane = tid & 31, w = tid >> 5;
    int g = lane >> 2, t2 = (lane & 3)*2;
    int col = blockIdx.x;
    int b   = blockIdx.y;
    size_t base = ((size_t)b*256 + col)*256*CHn;
    const __nv_bfloat16* qp = qg + base;
    const __nv_bfloat16* kp = kg + base;
    const __nv_bfloat16* vp = vg + base;
    size_t out_base, out_stride;
    if (CAUSAL) { out_base = base; out_stride = CHn; }
    else { out_base = ((size_t)b*Sn + col)*CHn; out_stride = (size_t)Tn*CHn; }

    #pragma unroll
    for (int jj = 0; jj < 4; jj++) {
        int idx = tid + jj*256;
        int y = idx >> 2, q4 = idx & 3;
        *(uint4*)&sK[y*40 + q4*8] = *(const uint4*)(kp + y*32 + q4*8);
        *(uint4*)&sQ[y*40 + q4*8] = *(const uint4*)(qp + y*32 + q4*8);
        union { uint4 u; __nv_bfloat16 h[8]; } vv;
        vv.u = *(const uint4*)(vp + y*32 + q4*8);
        #pragma unroll
        for (int c8 = 0; c8 < 8; c8++)
            sVT[(q4*8 + c8)*264 + y] = vv.h[c8];
    }
    __syncthreads();

    #pragma unroll
    for (int it = 0; it < 2; it++) {
        const int wr0 = it*128 + w*16;

        uint32_t qa[2][4];
        #pragma unroll
        for (int ks = 0; ks < 2; ks++) {
            int row = wr0 + (lane & 15);
            int cc  = ks*16 + (lane >> 4)*8;
            ldsm4(qa[ks], sb + QOFF + (uint32_t)(row*40 + cc)*2);
        }

        float O[4][4];
        #pragma unroll
        for (int i = 0; i < 4; i++)
            #pragma unroll
            for (int j = 0; j < 4; j++) O[i][j] = 0.f;
        float mA = -1e30f, mB = -1e30f, lA = 0.f, lB = 0.f;

        const int qmax = CAUSAL ? ((wr0 >> 6) + 1) : 4;

        for (int q = 0; q < qmax; q++) {
            float D[8][4];
            #pragma unroll
            for (int nt = 0; nt < 8; nt++)
                #pragma unroll
                for (int j = 0; j < 4; j++) D[nt][j] = 0.f;

            #pragma unroll
            for (int nt = 0; nt < 8; nt++) {
                if (!CAUSAL || (q*64 + nt*8 <= wr0 + 15)) {
                    uint32_t kb[4];
                    int y = q*64 + nt*8 + (lane & 7);
                    int k = (lane >> 3)*8;
                    ldsm4(kb, sb + KOFF + (uint32_t)(y*40 + k)*2);
                    mma_bf16(D[nt], qa[0], &kb[0]);
                    mma_bf16(D[nt], qa[1], &kb[2]);
                }
            }
            if (CAUSAL) {
                #pragma unroll
                for (int nt = 0; nt < 8; nt++) {
                    int y0 = q*64 + nt*8 + t2;
                    int rA = wr0 + g, rB = rA + 8;
                    if (y0     > rA) D[nt][0] = -1e30f;
                    if (y0 + 1 > rA) D[nt][1] = -1e30f;
                    if (y0     > rB) D[nt][2] = -1e30f;
                    if (y0 + 1 > rB) D[nt][3] = -1e30f;
                }
            }

            float mqA = -1e30f, mqB = -1e30f;
            #pragma unroll
            for (int nt = 0; nt < 8; nt++) {
                mqA = fmaxf(mqA, fmaxf(D[nt][0], D[nt][1]));
                mqB = fmaxf(mqB, fmaxf(D[nt][2], D[nt][3]));
            }
            #pragma unroll
            for (int dlt = 1; dlt <= 2; dlt <<= 1) {
                mqA = fmaxf(mqA, __shfl_xor_sync(0xffffffffu, mqA, dlt));
                mqB = fmaxf(mqB, __shfl_xor_sync(0xffffffffu, mqB, dlt));
            }
            float mnA = fmaxf(mA, mqA), mnB = fmaxf(mB, mqB);
            float corrA = __expf(mA - mnA), corrB = __expf(mB - mnB);
            mA = mnA; mB = mnB;
            #pragma unroll
            for (int i = 0; i < 4; i++) {
                O[i][0] *= corrA; O[i][1] *= corrA;
                O[i][2] *= corrB; O[i][3] *= corrB;
            }

            uint32_t P[8][2];
            float sqA = 0.f, sqB = 0.f;
            #pragma unroll
            for (int nt = 0; nt < 8; nt++) {
                float e0 = __expf(D[nt][0] - mA);
                float e1 = __expf(D[nt][1] - mA);
                float e2 = __expf(D[nt][2] - mB);
                float e3 = __expf(D[nt][3] - mB);
                sqA += e0 + e1; sqB += e2 + e3;
                P[nt][0] = pkbf2(e0, e1);
                P[nt][1] = pkbf2(e2, e3);
            }
            #pragma unroll
            for (int dlt = 1; dlt <= 2; dlt <<= 1) {
                sqA += __shfl_xor_sync(0xffffffffu, sqA, dlt);
                sqB += __shfl_xor_sync(0xffffffffu, sqB, dlt);
            }
            lA = lA*corrA + sqA;
            lB = lB*corrB + sqB;

            #pragma unroll
            for (int kc2 = 0; kc2 < 2; kc2++) {
                if (CAUSAL && (q*64 + kc2*32 > wr0 + 15)) continue;
                uint32_t aF0[4] = {P[kc2*4+0][0], P[kc2*4+0][1],
                                   P[kc2*4+1][0], P[kc2*4+1][1]};
                uint32_t aF1[4] = {P[kc2*4+2][0], P[kc2*4+2][1],
                                   P[kc2*4+3][0], P[kc2*4+3][1]};
                #pragma unroll
                for (int ntv = 0; ntv < 4; ntv++) {
                    uint32_t vb[4];
                    int c = ntv*8 + (lane & 7);
                    int y = q*64 + kc2*32 + (lane >> 3)*8;
                    ldsm4(vb, sb + VOFF + (uint32_t)(c*264 + y)*2);
                    mma_bf16(O[ntv], aF0, &vb[0]);
                    mma_bf16(O[ntv], aF1, &vb[2]);
                }
            }
        }

        float invA = 1.f / lA, invB = 1.f / lB;
        int rA = wr0 + g, rB = rA + 8;
        #pragma unroll
        for (int ntv = 0; ntv < 4; ntv++) {
            int c = ntv*8 + t2;
            *(uint32_t*)(outg + out_base + (size_t)rA*out_stride + c) =
                pkbf2(O[ntv][0]*invA, O[ntv][1]*invA);
            *(uint32_t*)(outg + out_base + (size_t)rB*out_stride + c) =
                pkbf2(O[ntv][2]*invB, O[ntv][3]*invB);
        }
    }
}

// =====================================================================
// Kernel 5: proj conv, tensor cores, + residual -> fp32 out.
// Block: 128 positions x 64 outputs, K=32.
// smem: sIn[128][40] @0 | sW[64][40] @10240 | sOutF f32 [64][132] @15360
//       bias @49152 | alpha @49408
// =====================================================================
__global__ void __launch_bounds__(256) proj_kernel(
    const float* __restrict__ xin, const float* __restrict__ aa,
    float* __restrict__ outp)
{
    extern __shared__ char smc[];
    __nv_bfloat16* sIn  = (__nv_bfloat16*)smc;
    __nv_bfloat16* sW   = (__nv_bfloat16*)(smc + 10240);
    float*         sOutF= (float*)(smc + 15360);
    float* sBias = (float*)(smc + 49152);
    float* sAl   = (float*)(smc + 49408);
    uint32_t sb = (uint32_t)__cvta_generic_to_shared(smc);

    int tid = threadIdx.x, tile = blockIdx.x, b = blockIdx.y;
    int p0 = tile*128;

    #pragma unroll
    for (int i = tid; i < 320; i += 256)
        if (i < 320) ((uint4*)sW)[i] = ((const uint4*)wpr_bf)[i];
    if (tid < 64) sBias[tid] = b_pr[tid];
    if (tid == 0) sAl[0] = aa[0];

    const __nv_bfloat16* tp = g_tout + ((size_t)b*Sn + p0)*CHn;
    #pragma unroll
    for (int j = 0; j < 2; j++) {
        int idx = tid + j*256;
        int p = idx >> 2, q4 = idx & 3;
        *(uint4*)&sIn[p*40 + q4*8] = *(const uint4*)(tp + p*32 + q4*8);
    }
    __syncthreads();

    int lane = tid & 31, w = tid >> 5;
    int g = lane >> 2, t2 = (lane & 3)*2;

    uint32_t qa[2][4];
    #pragma unroll
    for (int ks = 0; ks < 2; ks++) {
        int row = w*16 + (lane & 15);
        int cc  = ks*16 + (lane >> 4)*8;
        ldsm4(qa[ks], sb + (uint32_t)(row*40 + cc)*2);
    }

    float al = sAl[0];
    #pragma unroll
    for (int nt = 0; nt < 8; nt++) {
        uint32_t kb[4];
        ldsm4(kb, sb + 10240 +
            (uint32_t)((nt*8 + (lane & 7))*40 + (lane >> 3)*8)*2);
        float D[4] = {0.f, 0.f, 0.f, 0.f};
        mma_bf16(D, qa[0], kb + 0);
        mma_bf16(D, qa[1], kb + 2);
        int o0 = nt*8 + t2;
        float b0 = sBias[o0], b1 = sBias[o0 + 1];
        float v0 = D[0] + b0; v0 = (v0 > 0.f) ? v0 : al*v0;
        float v1 = D[1] + b1; v1 = (v1 > 0.f) ? v1 : al*v1;
        float v2 = D[2] + b0; v2 = (v2 > 0.f) ? v2 : al*v2;
        float v3 = D[3] + b1; v3 = (v3 > 0.f) ? v3 : al*v3;
        int p = w*16 + g;
        sOutF[o0*132 + p]           = v0;
        sOutF[(o0+1)*132 + p]       = v1;
        sOutF[o0*132 + p + 8]       = v2;
        sOutF[(o0+1)*132 + p + 8]   = v3;
    }
    __syncthreads();

    #pragma unroll
    for (int j = 0; j < 8; j++) {
        int idx = tid + j*256;
        int o = idx >> 5, p4 = (idx & 31)*4;
        float4 acc = *(const float4*)&sOutF[o*132 + p4];
        float4 xr = *(const float4*)(xin + (size_t)b*Cn*Sn + (size_t)o*Sn + p0 + p4);
        *(float4*)(outp + (size_t)b*Cn*Sn + (size_t)o*Sn + p0 + p4) =
            make_float4(acc.x + xr.x, acc.y + xr.y, acc.z + xr.z, acc.w + xr.w);
    }
}

// =====================================================================
// Launch
// =====================================================================
extern "C" void kernel_launch(void* const* d_in, const int* in_sizes, int n_in,
                              void* d_out, int out_size) {
    const float* inp  = (const float*)d_in[0];
    const float* x    = (const float*)d_in[1];
    const float* fqkW = (const float*)d_in[2];
    const float* fqkb = (const float*)d_in[3];
    const float* fqkg = (const float*)d_in[4];
    const float* fqkbe= (const float*)d_in[5];
    const float* fqkm = (const float*)d_in[6];
    const float* fqkv = (const float*)d_in[7];
    const float* fqka = (const float*)d_in[8];
    const float* fvW  = (const float*)d_in[9];
    const float* fvb  = (const float*)d_in[10];
    const float* fvg  = (const float*)d_in[11];
    const float* fvbe = (const float*)d_in[12];
    const float* fvm  = (const float*)d_in[13];
    const float* fvv  = (const float*)d_in[14];
    const float* fva  = (const float*)d_in[15];
    const float* tqkW = (const float*)d_in[16];
    const float* tqkb = (const float*)d_in[17];
    const float* tqkg = (const float*)d_in[18];
    const float* tqkbe= (const float*)d_in[19];
    const float* tqkm = (const float*)d_in[20];
    const float* tqkv = (const float*)d_in[21];
    const float* tqka = (const float*)d_in[22];
    const float* prW  = (const float*)d_in[23];
    const float* prb  = (const float*)d_in[24];
    const float* prg  = (const float*)d_in[25];
    const float* prbe = (const float*)d_in[26];
    const float* prm  = (const float*)d_in[27];
    const float* prv  = (const float*)d_in[28];
    const float* pra  = (const float*)d_in[29];
    float* out = (float*)d_out;

    cudaFuncSetAttribute(conv_qk_kernel,
                         cudaFuncAttributeMaxDynamicSharedMemorySize, CQK_SMEM);
    cudaFuncSetAttribute(conv_v_kernel,
                         cudaFuncAttributeMaxDynamicSharedMemorySize, CV_SMEM);
    cudaFuncSetAttribute(proj_kernel,
                         cudaFuncAttributeMaxDynamicSharedMemorySize, PR_SMEM);
    cudaFuncSetAttribute(attn_kernel<false>,
                         cudaFuncAttributeMaxDynamicSharedMemorySize, ATTN_SMEM);
    cudaFuncSetAttribute(attn_kernel<true>,
                         cudaFuncAttributeMaxDynamicSharedMemorySize, ATTN_SMEM);

    fold_kernel<<<1, 256>>>(
        fqkW, fqkb, fqkg, fqkbe, fqkm, fqkv,
        tqkW, tqkb, tqkg, tqkbe, tqkm, tqkv,
        fvW,  fvb,  fvg,  fvbe,  fvm,  fvv,
        prW,  prb,  prg,  prbe,  prm,  prv);

    conv_qk_kernel<<<dim3(512, Bn), 256, CQK_SMEM>>>(inp, fqka, tqka);

    conv_v_kernel<<<dim3(256, Bn), 256, CV_SMEM>>>(x, fva);

    attn_kernel<false><<<dim3(256, Bn), 256, ATTN_SMEM>>>();

    attn_kernel<true><<<dim3(256, Bn), 256, ATTN_SMEM>>>();

    proj_kernel<<<dim3(512, Bn), 256, PR_SMEM>>>(x, pra, out);
}

// round 14
// speedup vs baseline: 5.8259x; 1.0307x over previous
#include <cuda_runtime.h>
#include <cuda_bf16.h>
#include <cstdint>

// Problem constants
constexpr int Bn  = 4;
constexpr int Cn  = 64;
constexpr int CHn = 32;
constexpr int Fn  = 256;
constexpr int Tn  = 256;
constexpr int Sn  = Fn * Tn;
constexpr float EPSc = 1e-5f;
// q scale folded with log2(e): softmax computed via ex2.approx
constexpr float QSCALE_LOG2E = 0.17677669529663687f * 1.4426950408889634f;

__device__ __forceinline__ uint32_t pkbf2(float lo, float hi) {
    __nv_bfloat162 h = __float22bfloat162_rn(make_float2(lo, hi));
    return *(uint32_t*)&h;
}
__device__ __forceinline__ float ex2(float x) {
    float y;
    asm("ex2.approx.f32 %0, %1;" : "=f"(y) : "f"(x));
    return y;
}

// ---- tensor-core helpers ----
__device__ __forceinline__ void ldsm4(uint32_t* r, uint32_t addr) {
    asm volatile("ldmatrix.sync.aligned.m8n8.x4.shared.b16 {%0,%1,%2,%3}, [%4];\n"
        : "=r"(r[0]), "=r"(r[1]), "=r"(r[2]), "=r"(r[3]) : "r"(addr));
}
__device__ __forceinline__ void ldsm4t(uint32_t* r, uint32_t addr) {
    asm volatile("ldmatrix.sync.aligned.m8n8.x4.trans.shared.b16 {%0,%1,%2,%3}, [%4];\n"
        : "=r"(r[0]), "=r"(r[1]), "=r"(r[2]), "=r"(r[3]) : "r"(addr));
}
__device__ __forceinline__ void mma_bf16(float* d, const uint32_t* a, const uint32_t* b) {
    asm volatile(
        "mma.sync.aligned.m16n8k16.row.col.f32.bf16.bf16.f32 "
        "{%0,%1,%2,%3}, {%4,%5,%6,%7}, {%8,%9}, {%0,%1,%2,%3};\n"
        : "+f"(d[0]), "+f"(d[1]), "+f"(d[2]), "+f"(d[3])
        : "r"(a[0]), "r"(a[1]), "r"(a[2]), "r"(a[3]), "r"(b[0]), "r"(b[1]));
}

// -------- device scratch (all intermediates bf16) --------
__device__ __nv_bfloat16 g_qf[Bn*Tn*Fn*CHn];
__device__ __nv_bfloat16 g_kf[Bn*Tn*Fn*CHn];
__device__ __nv_bfloat16 g_vf[Bn*Tn*Fn*CHn];
__device__ __nv_bfloat16 g_qt[Bn*Fn*Tn*CHn];
__device__ __nv_bfloat16 g_kt[Bn*Fn*Tn*CHn];
__device__ __nv_bfloat16 g_fout[Bn*Fn*Tn*CHn];
__device__ __nv_bfloat16 g_tout[Bn*Fn*Tn*CHn];

// -------- folded bf16 weights [o][k] + fp32 biases --------
__device__ __nv_bfloat16 wqk_bf[128*72];
__device__ float b_qk[128];
__device__ __nv_bfloat16 wv_bf[32*72];
__device__ float b_v[32];
__device__ __nv_bfloat16 wpr_bf[64*40];
__device__ float b_pr[64];

// dynamic-smem sizes (bytes)
constexpr int CQK_SMEM  = 17408 + 18432 + 34816 + 512 + 8;   // 71176
constexpr int CV_SMEM   = 33792 + 4608 + 20480 + 128 + 4;    // 59012
constexpr int PR_SMEM   = 10240 + 5120 + 33792 + 256 + 4;    // 49412
constexpr int ATTN_SMEM = 57856;  // sK[256][40] | sVT[32][264] | sQ[256][40]

// =====================================================================
// Kernel 0: fold BN into bf16 weights / fp32 biases once.
// q channels pre-scaled by 1/sqrt(32) * log2(e)  (ex2-domain softmax)
// =====================================================================
__global__ void fold_kernel(
    const float* __restrict__ W1, const float* __restrict__ b1,
    const float* __restrict__ g1, const float* __restrict__ be1,
    const float* __restrict__ m1, const float* __restrict__ v1,
    const float* __restrict__ W2, const float* __restrict__ b2,
    const float* __restrict__ g2, const float* __restrict__ be2,
    const float* __restrict__ m2, const float* __restrict__ v2,
    const float* __restrict__ Wv, const float* __restrict__ bv,
    const float* __restrict__ gv, const float* __restrict__ bev,
    const float* __restrict__ mv, const float* __restrict__ vvv,
    const float* __restrict__ Wp, const float* __restrict__ bp,
    const float* __restrict__ gp, const float* __restrict__ bep,
    const float* __restrict__ mp, const float* __restrict__ vp)
{
    int tid = threadIdx.x;
    for (int idx = tid; idx < 8192; idx += 256) {
        int o = idx >> 6, k = idx & 63;
        float wv_; int grp, oo;
        if (o < 64) {
            grp = 0; oo = o;
            float sc = g1[o] * rsqrtf(v1[o] + EPSc);
            wv_ = W1[o*64 + k] * sc;
        } else {
            grp = 1; oo = o - 64;
            float sc = g2[oo] * rsqrtf(v2[oo] + EPSc);
            wv_ = W2[oo*64 + k] * sc;
        }
        bool isq = ((oo & 1) == 0);
        if (isq) wv_ *= QSCALE_LOG2E;
        int op = grp*64 + (isq ? 0 : 32) + (oo >> 1);
        wqk_bf[op*72 + k] = __float2bfloat16(wv_);
    }
    if (tid < 128) {
        int o = tid;
        float bias; int grp, oo;
        if (o < 64) {
            grp = 0; oo = o;
            float sc = g1[o] * rsqrtf(v1[o] + EPSc);
            bias = (b1[o] - m1[o]) * sc + be1[o];
        } else {
            grp = 1; oo = o - 64;
            float sc = g2[oo] * rsqrtf(v2[oo] + EPSc);
            bias = (b2[oo] - m2[oo]) * sc + be2[oo];
        }
        bool isq = ((oo & 1) == 0);
        if (isq) bias *= QSCALE_LOG2E;
        int op = grp*64 + (isq ? 0 : 32) + (oo >> 1);
        b_qk[op] = bias;
    }
    for (int idx = tid; idx < 2048; idx += 256) {
        int o = idx >> 6, k = idx & 63;
        float sc = gv[o] * rsqrtf(vvv[o] + EPSc);
        wv_bf[o*72 + k] = __float2bfloat16(Wv[o*64 + k] * sc);
    }
    if (tid < 32) {
        float sc = gv[tid] * rsqrtf(vvv[tid] + EPSc);
        b_v[tid] = (bv[tid] - mv[tid]) * sc + bev[tid];
    }
    for (int idx = tid; idx < 2048; idx += 256) {
        int o = idx >> 5, k = idx & 31;
        float sc = gp[o] * rsqrtf(vp[o] + EPSc);
        wpr_bf[o*40 + k] = __float2bfloat16(Wp[o*32 + k] * sc);
    }
    if (tid < 64) {
        float sc = gp[tid] * rsqrtf(vp[tid] + EPSc);
        b_pr[tid] = (bp[tid] - mp[tid]) * sc + bep[tid];
    }
}

// =====================================================================
// Kernel 1: fused fqk+tqk conv, tensor cores. (unchanged from R13)
// =====================================================================
__global__ void __launch_bounds__(256) conv_qk_kernel(
    const float* __restrict__ inp,
    const float* __restrict__ a1, const float* __restrict__ a2)
{
    extern __shared__ char smc[];
    __nv_bfloat16* sIn = (__nv_bfloat16*)smc;
    __nv_bfloat16* sW  = (__nv_bfloat16*)(smc + 17408);
    __nv_bfloat16* sOut= (__nv_bfloat16*)(smc + 35840);
    float* sBias = (float*)(smc + 70656);
    float* sAl   = (float*)(smc + 71168);
    uint32_t sb = (uint32_t)__cvta_generic_to_shared(smc);

    int tid = threadIdx.x, b = blockIdx.y, tile = blockIdx.x;
    int p0 = tile*128, f = p0 >> 8, t0 = p0 & 255;

    #pragma unroll
    for (int i = tid; i < 1152; i += 256)
        ((uint4*)sW)[i] = ((const uint4*)wqk_bf)[i];
    if (tid < 128) sBias[tid] = b_qk[tid];
    if (tid == 0) { sAl[0] = a1[0]; sAl[1] = a2[0]; }

    const float* ip = inp + (size_t)b*Cn*Sn + p0;
    #pragma unroll
    for (int jj = 0; jj < 8; jj++) {
        int idx4 = tid + jj*256;
        int k = idx4 >> 5, p4 = (idx4 & 31)*4;
        float4 v = *(const float4*)(ip + (size_t)k*Sn + p4);
        *(uint32_t*)&sIn[k*136 + p4]     = pkbf2(v.x, v.y);
        *(uint32_t*)&sIn[k*136 + p4 + 2] = pkbf2(v.z, v.w);
    }
    __syncthreads();

    int lane = tid & 31, w = tid >> 5;
    int g = lane >> 2, t2 = (lane & 3)*2;

    uint32_t qa[4][4];
    {
        int krow = (lane & 7) + ((lane >> 4) << 3);
        int col  = w*16 + ((lane >> 3) & 1)*8;
        #pragma unroll
        for (int ks = 0; ks < 4; ks++)
            ldsm4t(qa[ks], sb + (uint32_t)((ks*16 + krow)*136 + col)*2);
    }

    float alF = sAl[0], alT = sAl[1];
    #pragma unroll
    for (int nt = 0; nt < 16; nt++) {
        uint32_t kb0[4], kb1[4];
        uint32_t baddr = sb + 17408 +
            (uint32_t)((nt*8 + (lane & 7))*72 + (lane >> 3)*8)*2;
        ldsm4(kb0, baddr);
        ldsm4(kb1, baddr + 64);
        float D[4] = {0.f, 0.f, 0.f, 0.f};
        mma_bf16(D, qa[0], kb0 + 0);
        mma_bf16(D, qa[1], kb0 + 2);
        mma_bf16(D, qa[2], kb1 + 0);
        mma_bf16(D, qa[3], kb1 + 2);
        float al = (nt < 8) ? alF : alT;
        float b0 = sBias[nt*8 + t2], b1 = sBias[nt*8 + t2 + 1];
        float v0 = D[0] + b0; v0 = (v0 > 0.f) ? v0 : al*v0;
        float v1 = D[1] + b1; v1 = (v1 > 0.f) ? v1 : al*v1;
        float v2 = D[2] + b0; v2 = (v2 > 0.f) ? v2 : al*v2;
        float v3 = D[3] + b1; v3 = (v3 > 0.f) ? v3 : al*v3;
        int p = w*16 + g;
        *(uint32_t*)&sOut[p*136 + nt*8 + t2]       = pkbf2(v0, v1);
        *(uint32_t*)&sOut[(p+8)*136 + nt*8 + t2]   = pkbf2(v2, v3);
    }
    __syncthreads();

    #pragma unroll
    for (int j = 0; j < 8; j++) {
        int idx = tid + j*256;
        int arr = idx >> 9;
        int pos = (idx >> 2) & 127;
        int c   = (idx & 3)*8;
        uint4 v = *(const uint4*)&sOut[pos*136 + arr*32 + c];
        int t = t0 + pos;
        if (arr == 0)
            *(uint4*)(g_qf + (((size_t)b*Tn + t)*Fn + f)*CHn + c) = v;
        else if (arr == 1)
            *(uint4*)(g_kf + (((size_t)b*Tn + t)*Fn + f)*CHn + c) = v;
        else if (arr == 2)
            *(uint4*)(g_qt + (((size_t)b*Fn + f)*Tn + t)*CHn + c) = v;
        else
            *(uint4*)(g_kt + (((size_t)b*Fn + f)*Tn + t)*CHn + c) = v;
    }
}

// =====================================================================
// Kernel 2: fv conv, tensor cores. (unchanged from R13)
// =====================================================================
__global__ void __launch_bounds__(256) conv_v_kernel(
    const float* __restrict__ xin, const float* __restrict__ aa)
{
    extern __shared__ char smc[];
    __nv_bfloat16* sIn = (__nv_bfloat16*)smc;
    __nv_bfloat16* sW  = (__nv_bfloat16*)(smc + 33792);
    __nv_bfloat16* sOut= (__nv_bfloat16*)(smc + 38400);
    float* sBias = (float*)(smc + 58880);
    float* sAl   = (float*)(smc + 59008);
    uint32_t sb = (uint32_t)__cvta_generic_to_shared(smc);

    int tid = threadIdx.x, f = blockIdx.x, b = blockIdx.y;

    #pragma unroll
    for (int i = tid; i < 288; i += 256)
        ((uint4*)sW)[i] = ((const uint4*)wv_bf)[i];
    if (tid < 32) sBias[tid] = b_v[tid];
    if (tid == 0) sAl[0] = aa[0];

    const float* ip = xin + (size_t)b*Cn*Sn + (size_t)f*Tn;
    #pragma unroll
    for (int jj = 0; jj < 16; jj++) {
        int idx4 = tid + jj*256;
        int k = idx4 >> 6, t4 = (idx4 & 63)*4;
        float4 v = *(const float4*)(ip + (size_t)k*Sn + t4);
        *(uint32_t*)&sIn[k*264 + t4]     = pkbf2(v.x, v.y);
        *(uint32_t*)&sIn[k*264 + t4 + 2] = pkbf2(v.z, v.w);
    }
    __syncthreads();

    int lane = tid & 31, w = tid >> 5;
    int g = lane >> 2, t2 = (lane & 3)*2;

    uint32_t qa[2][4][4];
    {
        int krow = (lane & 7) + ((lane >> 4) << 3);
        #pragma unroll
        for (int mt = 0; mt < 2; mt++) {
            int col = w*32 + mt*16 + ((lane >> 3) & 1)*8;
            #pragma unroll
            for (int ks = 0; ks < 4; ks++)
                ldsm4t(qa[mt][ks], sb + (uint32_t)((ks*16 + krow)*264 + col)*2);
        }
    }

    float al = sAl[0];
    #pragma unroll
    for (int nt = 0; nt < 4; nt++) {
        uint32_t kb0[4], kb1[4];
        uint32_t baddr = sb + 33792 +
            (uint32_t)((nt*8 + (lane & 7))*72 + (lane >> 3)*8)*2;
        ldsm4(kb0, baddr);
        ldsm4(kb1, baddr + 64);
        float b0 = sBias[nt*8 + t2], b1 = sBias[nt*8 + t2 + 1];
        #pragma unroll
        for (int mt = 0; mt < 2; mt++) {
            float D[4] = {0.f, 0.f, 0.f, 0.f};
            mma_bf16(D, qa[mt][0], kb0 + 0);
            mma_bf16(D, qa[mt][1], kb0 + 2);
            mma_bf16(D, qa[mt][2], kb1 + 0);
            mma_bf16(D, qa[mt][3], kb1 + 2);
            float v0 = D[0] + b0; v0 = (v0 > 0.f) ? v0 : al*v0;
            float v1 = D[1] + b1; v1 = (v1 > 0.f) ? v1 : al*v1;
            float v2 = D[2] + b0; v2 = (v2 > 0.f) ? v2 : al*v2;
            float v3 = D[3] + b1; v3 = (v3 > 0.f) ? v3 : al*v3;
            int p = w*32 + mt*16 + g;
            *(uint32_t*)&sOut[p*40 + nt*8 + t2]     = pkbf2(v0, v1);
            *(uint32_t*)&sOut[(p+8)*40 + nt*8 + t2] = pkbf2(v2, v3);
        }
    }
    __syncthreads();

    #pragma unroll
    for (int j = 0; j < 4; j++) {
        int idx = tid + j*256;
        int pos = idx >> 2;
        int c   = (idx & 3)*8;
        uint4 v = *(const uint4*)&sOut[pos*40 + c];
        *(uint4*)(g_vf + (((size_t)b*Tn + pos)*Fn + f)*CHn + c) = v;
    }
}

// =====================================================================
// Attention kernel — v9:
//  * both 16-row tiles fused per warp: K/V fragments loaded ONCE,
//    reused for 2 mmas (halves ldsm traffic)
//  * no-max softmax: scores bounded (BN'd inputs, /sqrt(32)), so raw
//    ex2 accumulation is overflow-safe; sum reduced once at the end
//  * scores arrive in log2 domain (scale folded at fold_kernel)
// =====================================================================
template<bool CAUSAL>
__global__ void __launch_bounds__(256, 2) attn_kernel()
{
    const __nv_bfloat16* __restrict__ qg = CAUSAL ? g_qt : g_qf;
    const __nv_bfloat16* __restrict__ kg = CAUSAL ? g_kt : g_kf;
    const __nv_bfloat16* __restrict__ vg = CAUSAL ? g_fout : g_vf;
    __nv_bfloat16* __restrict__ outg     = CAUSAL ? g_tout : g_fout;

    extern __shared__ char smb[];
    constexpr int KOFF = 0, VOFF = 20480, QOFF = 37376;
    __nv_bfloat16* sK  = (__nv_bfloat16*)(smb + KOFF);   // [256][40]
    __nv_bfloat16* sVT = (__nv_bfloat16*)(smb + VOFF);   // [32][264]
    __nv_bfloat16* sQ  = (__nv_bfloat16*)(smb + QOFF);   // [256][40]
    uint32_t sb = (uint32_t)__cvta_generic_to_shared(smb);

    int tid = threadIdx.x, lane = tid & 31, w = tid >> 5;
    int g = lane >> 2, t2 = (lane & 3)*2;
    int col = blockIdx.x;
    int b   = blockIdx.y;
    size_t base = ((size_t)b*256 + col)*256*CHn;
    const __nv_bfloat16* qp = qg + base;
    const __nv_bfloat16* kp = kg + base;
    const __nv_bfloat16* vp = vg + base;
    size_t out_base, out_stride;
    if (CAUSAL) { out_base = base; out_stride = CHn; }
    else { out_base = ((size_t)b*Sn + col)*CHn; out_stride = (size_t)Tn*CHn; }

    #pragma unroll
    for (int jj = 0; jj < 4; jj++) {
        int idx = tid + jj*256;
        int y = idx >> 2, q4 = idx & 3;
        *(uint4*)&sK[y*40 + q4*8] = *(const uint4*)(kp + y*32 + q4*8);
        *(uint4*)&sQ[y*40 + q4*8] = *(const uint4*)(qp + y*32 + q4*8);
        union { uint4 u; __nv_bfloat16 h[8]; } vv;
        vv.u = *(const uint4*)(vp + y*32 + q4*8);
        #pragma unroll
        for (int c8 = 0; c8 < 8; c8++)
            sVT[(q4*8 + c8)*264 + y] = vv.h[c8];
    }
    __syncthreads();   // the only barrier

    const int r0a = w*16;          // tile 0 rows
    const int r0b = 128 + w*16;    // tile 1 rows

    // Q fragments for both tiles
    uint32_t qa[2][2][4];
    #pragma unroll
    for (int mt = 0; mt < 2; mt++)
        #pragma unroll
        for (int ks = 0; ks < 2; ks++) {
            int row = (mt ? r0b : r0a) + (lane & 15);
            int cc  = ks*16 + (lane >> 4)*8;
            ldsm4(qa[mt][ks], sb + QOFF + (uint32_t)(row*40 + cc)*2);
        }

    float O[2][4][4];
    #pragma unroll
    for (int mt = 0; mt < 2; mt++)
        #pragma unroll
        for (int i = 0; i < 4; i++)
            #pragma unroll
            for (int j = 0; j < 4; j++) O[mt][i][j] = 0.f;
    float sA[2] = {0.f, 0.f}, sB[2] = {0.f, 0.f};

    const int qmaxa = CAUSAL ? ((r0a >> 6) + 1) : 4;
    const int qmaxb = CAUSAL ? ((r0b >> 6) + 1) : 4;

    for (int q = 0; q < qmaxb; q++) {
        const bool acta = q < qmaxa;
        uint32_t P[2][8][2];

        #pragma unroll
        for (int nt = 0; nt < 8; nt++) {
            int y0q = q*64 + nt*8;
            bool needa = acta && (!CAUSAL || (y0q <= r0a + 15));
            bool needb = !CAUSAL || (y0q <= r0b + 15);

            uint32_t kb[4];
            {
                int y = y0q + (lane & 7);
                int k = (lane >> 3)*8;
                ldsm4(kb, sb + KOFF + (uint32_t)(y*40 + k)*2);
            }
            float D0[4] = {0.f,0.f,0.f,0.f}, D1[4] = {0.f,0.f,0.f,0.f};
            if (needa) { mma_bf16(D0, qa[0][0], kb+0); mma_bf16(D0, qa[0][1], kb+2); }
            if (needb) { mma_bf16(D1, qa[1][0], kb+0); mma_bf16(D1, qa[1][1], kb+2); }

            if (CAUSAL) {
                int y0 = y0q + t2;
                int rA0 = r0a + g, rB0 = rA0 + 8;
                if (y0     > rA0) D0[0] = -1e30f;
                if (y0 + 1 > rA0) D0[1] = -1e30f;
                if (y0     > rB0) D0[2] = -1e30f;
                if (y0 + 1 > rB0) D0[3] = -1e30f;
                int rA1 = r0b + g, rB1 = rA1 + 8;
                if (y0     > rA1) D1[0] = -1e30f;
                if (y0 + 1 > rA1) D1[1] = -1e30f;
                if (y0     > rB1) D1[2] = -1e30f;
                if (y0 + 1 > rB1) D1[3] = -1e30f;
            }

            float e00 = needa ? ex2(D0[0]) : 0.f;
            float e01 = needa ? ex2(D0[1]) : 0.f;
            float e02 = needa ? ex2(D0[2]) : 0.f;
            float e03 = needa ? ex2(D0[3]) : 0.f;
            float e10 = needb ? ex2(D1[0]) : 0.f;
            float e11 = needb ? ex2(D1[1]) : 0.f;
            float e12 = needb ? ex2(D1[2]) : 0.f;
            float e13 = needb ? ex2(D1[3]) : 0.f;
            sA[0] += e00 + e01;  sB[0] += e02 + e03;
            sA[1] += e10 + e11;  sB[1] += e12 + e13;
            P[0][nt][0] = pkbf2(e00, e01);
            P[0][nt][1] = pkbf2(e02, e03);
            P[1][nt][0] = pkbf2(e10, e11);
            P[1][nt][1] = pkbf2(e12, e13);
        }

        // ---- PV for both tiles (V fragments loaded once)
        #pragma unroll
        for (int kc2 = 0; kc2 < 2; kc2++) {
            int ybase = q*64 + kc2*32;
            bool pa = acta && (!CAUSAL || (ybase <= r0a + 15));
            bool pb = !CAUSAL || (ybase <= r0b + 15);
            if (!pa && !pb) continue;
            uint32_t a0F0[4] = {P[0][kc2*4+0][0], P[0][kc2*4+0][1],
                                P[0][kc2*4+1][0], P[0][kc2*4+1][1]};
            uint32_t a0F1[4] = {P[0][kc2*4+2][0], P[0][kc2*4+2][1],
                                P[0][kc2*4+3][0], P[0][kc2*4+3][1]};
            uint32_t a1F0[4] = {P[1][kc2*4+0][0], P[1][kc2*4+0][1],
                                P[1][kc2*4+1][0], P[1][kc2*4+1][1]};
            uint32_t a1F1[4] = {P[1][kc2*4+2][0], P[1][kc2*4+2][1],
                                P[1][kc2*4+3][0], P[1][kc2*4+3][1]};
            #pragma unroll
            for (int ntv = 0; ntv < 4; ntv++) {
                uint32_t vb[4];
                int c = ntv*8 + (lane & 7);
                int y = ybase + (lane >> 3)*8;
                ldsm4(vb, sb + VOFF + (uint32_t)(c*264 + y)*2);
                if (pa) {
                    mma_bf16(O[0][ntv], a0F0, &vb[0]);
                    mma_bf16(O[0][ntv], a0F1, &vb[2]);
                }
                if (pb) {
                    mma_bf16(O[1][ntv], a1F0, &vb[0]);
                    mma_bf16(O[1][ntv], a1F1, &vb[2]);
                }
            }
        }
    }

    // ---- single end-of-kernel sum reduction + normalize + write
    #pragma unroll
    for (int dlt = 1; dlt <= 2; dlt <<= 1) {
        sA[0] += __shfl_xor_sync(0xffffffffu, sA[0], dlt);
        sB[0] += __shfl_xor_sync(0xffffffffu, sB[0], dlt);
        sA[1] += __shfl_xor_sync(0xffffffffu, sA[1], dlt);
        sB[1] += __shfl_xor_sync(0xffffffffu, sB[1], dlt);
    }
    #pragma unroll
    for (int mt = 0; mt < 2; mt++) {
        float invA = 1.f / sA[mt], invB = 1.f / sB[mt];
        int rA = (mt ? r0b : r0a) + g, rB = rA + 8;
        #pragma unroll
        for (int ntv = 0; ntv < 4; ntv++) {
            int c = ntv*8 + t2;
            *(uint32_t*)(outg + out_base + (size_t)rA*out_stride + c) =
                pkbf2(O[mt][ntv][0]*invA, O[mt][ntv][1]*invA);
            *(uint32_t*)(outg + out_base + (size_t)rB*out_stride + c) =
                pkbf2(O[mt][ntv][2]*invB, O[mt][ntv][3]*invB);
        }
    }
}

// =====================================================================
// Kernel 5: proj conv, tensor cores, + residual. (unchanged from R13)
// =====================================================================
__global__ void __launch_bounds__(256) proj_kernel(
    const float* __restrict__ xin, const float* __restrict__ aa,
    float* __restrict__ outp)
{
    extern __shared__ char smc[];
    __nv_bfloat16* sIn  = (__nv_bfloat16*)smc;
    __nv_bfloat16* sW   = (__nv_bfloat16*)(smc + 10240);
    float*         sOutF= (float*)(smc + 15360);
    float* sBias = (float*)(smc + 49152);
    float* sAl   = (float*)(smc + 49408);
    uint32_t sb = (uint32_t)__cvta_generic_to_shared(smc);

    int tid = threadIdx.x, tile = blockIdx.x, b = blockIdx.y;
    int p0 = tile*128;

    #pragma unroll
    for (int i = tid; i < 320; i += 256)
        if (i < 320) ((uint4*)sW)[i] = ((const uint4*)wpr_bf)[i];
    if (tid < 64) sBias[tid] = b_pr[tid];
    if (tid == 0) sAl[0] = aa[0];

    const __nv_bfloat16* tp = g_tout + ((size_t)b*Sn + p0)*CHn;
    #pragma unroll
    for (int j = 0; j < 2; j++) {
        int idx = tid + j*256;
        int p = idx >> 2, q4 = idx & 3;
        *(uint4*)&sIn[p*40 + q4*8] = *(const uint4*)(tp + p*32 + q4*8);
    }
    __syncthreads();

    int lane = tid & 31, w = tid >> 5;
    int g = lane >> 2, t2 = (lane & 3)*2;

    uint32_t qa[2][4];
    #pragma unroll
    for (int ks = 0; ks < 2; ks++) {
        int row = w*16 + (lane & 15);
        int cc  = ks*16 + (lane >> 4)*8;
        ldsm4(qa[ks], sb + (uint32_t)(row*40 + cc)*2);
    }

    float al = sAl[0];
    #pragma unroll
    for (int nt = 0; nt < 8; nt++) {
        uint32_t kb[4];
        ldsm4(kb, sb + 10240 +
            (uint32_t)((nt*8 + (lane & 7))*40 + (lane >> 3)*8)*2);
        float D[4] = {0.f, 0.f, 0.f, 0.f};
        mma_bf16(D, qa[0], kb + 0);
        mma_bf16(D, qa[1], kb + 2);
        int o0 = nt*8 + t2;
        float b0 = sBias[o0], b1 = sBias[o0 + 1];
        float v0 = D[0] + b0; v0 = (v0 > 0.f) ? v0 : al*v0;
        float v1 = D[1] + b1; v1 = (v1 > 0.f) ? v1 : al*v1;
        float v2 = D[2] + b0; v2 = (v2 > 0.f) ? v2 : al*v2;
        float v3 = D[3] + b1; v3 = (v3 > 0.f) ? v3 : al*v3;
        int p = w*16 + g;
        sOutF[o0*132 + p]           = v0;
        sOutF[(o0+1)*132 + p]       = v1;
        sOutF[o0*132 + p + 8]       = v2;
        sOutF[(o0+1)*132 + p + 8]   = v3;
    }
    __syncthreads();

    #pragma unroll
    for (int j = 0; j < 8; j++) {
        int idx = tid + j*256;
        int o = idx >> 5, p4 = (idx & 31)*4;
        float4 acc = *(const float4*)&sOutF[o*132 + p4];
        float4 xr = *(const float4*)(xin + (size_t)b*Cn*Sn + (size_t)o*Sn + p0 + p4);
        *(float4*)(outp + (size_t)b*Cn*Sn + (size_t)o*Sn + p0 + p4) =
            make_float4(acc.x + xr.x, acc.y + xr.y, acc.z + xr.z, acc.w + xr.w);
    }
}

// =====================================================================
// Launch
// =====================================================================
extern "C" void kernel_launch(void* const* d_in, const int* in_sizes, int n_in,
                              void* d_out, int out_size) {
    const float* inp  = (const float*)d_in[0];
    const float* x    = (const float*)d_in[1];
    const float* fqkW = (const float*)d_in[2];
    const float* fqkb = (const float*)d_in[3];
    const float* fqkg = (const float*)d_in[4];
    const float* fqkbe= (const float*)d_in[5];
    const float* fqkm = (const float*)d_in[6];
    const float* fqkv = (const float*)d_in[7];
    const float* fqka = (const float*)d_in[8];
    const float* fvW  = (const float*)d_in[9];
    const float* fvb  = (const float*)d_in[10];
    const float* fvg  = (const float*)d_in[11];
    const float* fvbe = (const float*)d_in[12];
    const float* fvm  = (const float*)d_in[13];
    const float* fvv  = (const float*)d_in[14];
    const float* fva  = (const float*)d_in[15];
    const float* tqkW = (const float*)d_in[16];
    const float* tqkb = (const float*)d_in[17];
    const float* tqkg = (const float*)d_in[18];
    const float* tqkbe= (const float*)d_in[19];
    const float* tqkm = (const float*)d_in[20];
    const float* tqkv = (const float*)d_in[21];
    const float* tqka = (const float*)d_in[22];
    const float* prW  = (const float*)d_in[23];
    const float* prb  = (const float*)d_in[24];
    const float* prg  = (const float*)d_in[25];
    const float* prbe = (const float*)d_in[26];
    const float* prm  = (const float*)d_in[27];
    const float* prv  = (const float*)d_in[28];
    const float* pra  = (const float*)d_in[29];
    float* out = (float*)d_out;

    cudaFuncSetAttribute(conv_qk_kernel,
                         cudaFuncAttributeMaxDynamicSharedMemorySize, CQK_SMEM);
    cudaFuncSetAttribute(conv_v_kernel,
                         cudaFuncAttributeMaxDynamicSharedMemorySize, CV_SMEM);
    cudaFuncSetAttribute(proj_kernel,
                         cudaFuncAttributeMaxDynamicSharedMemorySize, PR_SMEM);
    cudaFuncSetAttribute(attn_kernel<false>,
                         cudaFuncAttributeMaxDynamicSharedMemorySize, ATTN_SMEM);
    cudaFuncSetAttribute(attn_kernel<true>,
                         cudaFuncAttributeMaxDynamicSharedMemorySize, ATTN_SMEM);

    fold_kernel<<<1, 256>>>(
        fqkW, fqkb, fqkg, fqkbe, fqkm, fqkv,
        tqkW, tqkb, tqkg, tqkbe, tqkm, tqkv,
        fvW,  fvb,  fvg,  fvbe,  fvm,  fvv,
        prW,  prb,  prg,  prbe,  prm,  prv);

    conv_qk_kernel<<<dim3(512, Bn), 256, CQK_SMEM>>>(inp, fqka, tqka);

    conv_v_kernel<<<dim3(256, Bn), 256, CV_SMEM>>>(x, fva);

    attn_kernel<false><<<dim3(256, Bn), 256, ATTN_SMEM>>>();

    attn_kernel<true><<<dim3(256, Bn), 256, ATTN_SMEM>>>();

    proj_kernel<<<dim3(512, Bn), 256, PR_SMEM>>>(x, pra, out);
}

// round 15
// speedup vs baseline: 6.0306x; 1.0351x over previous
#include <cuda_runtime.h>
#include <cuda_bf16.h>
#include <cstdint>

// Problem constants
constexpr int Bn  = 4;
constexpr int Cn  = 64;
constexpr int CHn = 32;
constexpr int Fn  = 256;
constexpr int Tn  = 256;
constexpr int Sn  = Fn * Tn;
constexpr float EPSc = 1e-5f;
// q scale folded with log2(e): softmax computed via ex2.approx
constexpr float QSCALE_LOG2E = 0.17677669529663687f * 1.4426950408889634f;

__device__ __forceinline__ uint32_t pkbf2(float lo, float hi) {
    __nv_bfloat162 h = __float22bfloat162_rn(make_float2(lo, hi));
    return *(uint32_t*)&h;
}
__device__ __forceinline__ float ex2(float x) {
    float y;
    asm("ex2.approx.f32 %0, %1;" : "=f"(y) : "f"(x));
    return y;
}

// ---- tensor-core helpers ----
__device__ __forceinline__ void ldsm4(uint32_t* r, uint32_t addr) {
    asm volatile("ldmatrix.sync.aligned.m8n8.x4.shared.b16 {%0,%1,%2,%3}, [%4];\n"
        : "=r"(r[0]), "=r"(r[1]), "=r"(r[2]), "=r"(r[3]) : "r"(addr));
}
__device__ __forceinline__ void ldsm4t(uint32_t* r, uint32_t addr) {
    asm volatile("ldmatrix.sync.aligned.m8n8.x4.trans.shared.b16 {%0,%1,%2,%3}, [%4];\n"
        : "=r"(r[0]), "=r"(r[1]), "=r"(r[2]), "=r"(r[3]) : "r"(addr));
}
__device__ __forceinline__ void mma_bf16(float* d, const uint32_t* a, const uint32_t* b) {
    asm volatile(
        "mma.sync.aligned.m16n8k16.row.col.f32.bf16.bf16.f32 "
        "{%0,%1,%2,%3}, {%4,%5,%6,%7}, {%8,%9}, {%0,%1,%2,%3};\n"
        : "+f"(d[0]), "+f"(d[1]), "+f"(d[2]), "+f"(d[3])
        : "r"(a[0]), "r"(a[1]), "r"(a[2]), "r"(a[3]), "r"(b[0]), "r"(b[1]));
}

// -------- device scratch (all intermediates bf16) --------
__device__ __nv_bfloat16 g_qf[Bn*Tn*Fn*CHn];
__device__ __nv_bfloat16 g_kf[Bn*Tn*Fn*CHn];
__device__ __nv_bfloat16 g_vf[Bn*Tn*Fn*CHn];
__device__ __nv_bfloat16 g_qt[Bn*Fn*Tn*CHn];
__device__ __nv_bfloat16 g_kt[Bn*Fn*Tn*CHn];
__device__ __nv_bfloat16 g_fout[Bn*Fn*Tn*CHn];
__device__ __nv_bfloat16 g_tout[Bn*Fn*Tn*CHn];

// -------- folded bf16 weights [o][k] + fp32 biases --------
__device__ __nv_bfloat16 wqk_bf[128*72];
__device__ float b_qk[128];
__device__ __nv_bfloat16 wv_bf[32*72];
__device__ float b_v[32];
__device__ __nv_bfloat16 wpr_bf[64*40];
__device__ float b_pr[64];

// dynamic-smem sizes (bytes)
constexpr int CQK_SMEM  = 17408 + 18432 + 34816 + 512 + 8;   // 71176
constexpr int CV_SMEM   = 33792 + 4608 + 20480 + 128 + 4;    // 59012
constexpr int PR_SMEM   = 10240 + 5120 + 33792 + 256 + 4;    // 49412
// attn: sK[256][40] @0 | sV[256][40] @20480 | sQ[256][40] @40960
constexpr int ATTN_SMEM = 61440;

// =====================================================================
// Kernel 0: fold BN into bf16 weights / fp32 biases once.
// =====================================================================
__global__ void fold_kernel(
    const float* __restrict__ W1, const float* __restrict__ b1,
    const float* __restrict__ g1, const float* __restrict__ be1,
    const float* __restrict__ m1, const float* __restrict__ v1,
    const float* __restrict__ W2, const float* __restrict__ b2,
    const float* __restrict__ g2, const float* __restrict__ be2,
    const float* __restrict__ m2, const float* __restrict__ v2,
    const float* __restrict__ Wv, const float* __restrict__ bv,
    const float* __restrict__ gv, const float* __restrict__ bev,
    const float* __restrict__ mv, const float* __restrict__ vvv,
    const float* __restrict__ Wp, const float* __restrict__ bp,
    const float* __restrict__ gp, const float* __restrict__ bep,
    const float* __restrict__ mp, const float* __restrict__ vp)
{
    int tid = threadIdx.x;
    for (int idx = tid; idx < 8192; idx += 256) {
        int o = idx >> 6, k = idx & 63;
        float wv_; int grp, oo;
        if (o < 64) {
            grp = 0; oo = o;
            float sc = g1[o] * rsqrtf(v1[o] + EPSc);
            wv_ = W1[o*64 + k] * sc;
        } else {
            grp = 1; oo = o - 64;
            float sc = g2[oo] * rsqrtf(v2[oo] + EPSc);
            wv_ = W2[oo*64 + k] * sc;
        }
        bool isq = ((oo & 1) == 0);
        if (isq) wv_ *= QSCALE_LOG2E;
        int op = grp*64 + (isq ? 0 : 32) + (oo >> 1);
        wqk_bf[op*72 + k] = __float2bfloat16(wv_);
    }
    if (tid < 128) {
        int o = tid;
        float bias; int grp, oo;
        if (o < 64) {
            grp = 0; oo = o;
            float sc = g1[o] * rsqrtf(v1[o] + EPSc);
            bias = (b1[o] - m1[o]) * sc + be1[o];
        } else {
            grp = 1; oo = o - 64;
            float sc = g2[oo] * rsqrtf(v2[oo] + EPSc);
            bias = (b2[oo] - m2[oo]) * sc + be2[oo];
        }
        bool isq = ((oo & 1) == 0);
        if (isq) bias *= QSCALE_LOG2E;
        int op = grp*64 + (isq ? 0 : 32) + (oo >> 1);
        b_qk[op] = bias;
    }
    for (int idx = tid; idx < 2048; idx += 256) {
        int o = idx >> 6, k = idx & 63;
        float sc = gv[o] * rsqrtf(vvv[o] + EPSc);
        wv_bf[o*72 + k] = __float2bfloat16(Wv[o*64 + k] * sc);
    }
    if (tid < 32) {
        float sc = gv[tid] * rsqrtf(vvv[tid] + EPSc);
        b_v[tid] = (bv[tid] - mv[tid]) * sc + bev[tid];
    }
    for (int idx = tid; idx < 2048; idx += 256) {
        int o = idx >> 5, k = idx & 31;
        float sc = gp[o] * rsqrtf(vp[o] + EPSc);
        wpr_bf[o*40 + k] = __float2bfloat16(Wp[o*32 + k] * sc);
    }
    if (tid < 64) {
        float sc = gp[tid] * rsqrtf(vp[tid] + EPSc);
        b_pr[tid] = (bp[tid] - mp[tid]) * sc + bep[tid];
    }
}

// =====================================================================
// Kernel 1: fused fqk+tqk conv, tensor cores. (unchanged)
// =====================================================================
__global__ void __launch_bounds__(256) conv_qk_kernel(
    const float* __restrict__ inp,
    const float* __restrict__ a1, const float* __restrict__ a2)
{
    extern __shared__ char smc[];
    __nv_bfloat16* sIn = (__nv_bfloat16*)smc;
    __nv_bfloat16* sW  = (__nv_bfloat16*)(smc + 17408);
    __nv_bfloat16* sOut= (__nv_bfloat16*)(smc + 35840);
    float* sBias = (float*)(smc + 70656);
    float* sAl   = (float*)(smc + 71168);
    uint32_t sb = (uint32_t)__cvta_generic_to_shared(smc);

    int tid = threadIdx.x, b = blockIdx.y, tile = blockIdx.x;
    int p0 = tile*128, f = p0 >> 8, t0 = p0 & 255;

    #pragma unroll
    for (int i = tid; i < 1152; i += 256)
        ((uint4*)sW)[i] = ((const uint4*)wqk_bf)[i];
    if (tid < 128) sBias[tid] = b_qk[tid];
    if (tid == 0) { sAl[0] = a1[0]; sAl[1] = a2[0]; }

    const float* ip = inp + (size_t)b*Cn*Sn + p0;
    #pragma unroll
    for (int jj = 0; jj < 8; jj++) {
        int idx4 = tid + jj*256;
        int k = idx4 >> 5, p4 = (idx4 & 31)*4;
        float4 v = *(const float4*)(ip + (size_t)k*Sn + p4);
        *(uint32_t*)&sIn[k*136 + p4]     = pkbf2(v.x, v.y);
        *(uint32_t*)&sIn[k*136 + p4 + 2] = pkbf2(v.z, v.w);
    }
    __syncthreads();

    int lane = tid & 31, w = tid >> 5;
    int g = lane >> 2, t2 = (lane & 3)*2;

    uint32_t qa[4][4];
    {
        int krow = (lane & 7) + ((lane >> 4) << 3);
        int col  = w*16 + ((lane >> 3) & 1)*8;
        #pragma unroll
        for (int ks = 0; ks < 4; ks++)
            ldsm4t(qa[ks], sb + (uint32_t)((ks*16 + krow)*136 + col)*2);
    }

    float alF = sAl[0], alT = sAl[1];
    #pragma unroll
    for (int nt = 0; nt < 16; nt++) {
        uint32_t kb0[4], kb1[4];
        uint32_t baddr = sb + 17408 +
            (uint32_t)((nt*8 + (lane & 7))*72 + (lane >> 3)*8)*2;
        ldsm4(kb0, baddr);
        ldsm4(kb1, baddr + 64);
        float D[4] = {0.f, 0.f, 0.f, 0.f};
        mma_bf16(D, qa[0], kb0 + 0);
        mma_bf16(D, qa[1], kb0 + 2);
        mma_bf16(D, qa[2], kb1 + 0);
        mma_bf16(D, qa[3], kb1 + 2);
        float al = (nt < 8) ? alF : alT;
        float b0 = sBias[nt*8 + t2], b1 = sBias[nt*8 + t2 + 1];
        float v0 = D[0] + b0; v0 = (v0 > 0.f) ? v0 : al*v0;
        float v1 = D[1] + b1; v1 = (v1 > 0.f) ? v1 : al*v1;
        float v2 = D[2] + b0; v2 = (v2 > 0.f) ? v2 : al*v2;
        float v3 = D[3] + b1; v3 = (v3 > 0.f) ? v3 : al*v3;
        int p = w*16 + g;
        *(uint32_t*)&sOut[p*136 + nt*8 + t2]       = pkbf2(v0, v1);
        *(uint32_t*)&sOut[(p+8)*136 + nt*8 + t2]   = pkbf2(v2, v3);
    }
    __syncthreads();

    #pragma unroll
    for (int j = 0; j < 8; j++) {
        int idx = tid + j*256;
        int arr = idx >> 9;
        int pos = (idx >> 2) & 127;
        int c   = (idx & 3)*8;
        uint4 v = *(const uint4*)&sOut[pos*136 + arr*32 + c];
        int t = t0 + pos;
        if (arr == 0)
            *(uint4*)(g_qf + (((size_t)b*Tn + t)*Fn + f)*CHn + c) = v;
        else if (arr == 1)
            *(uint4*)(g_kf + (((size_t)b*Tn + t)*Fn + f)*CHn + c) = v;
        else if (arr == 2)
            *(uint4*)(g_qt + (((size_t)b*Fn + f)*Tn + t)*CHn + c) = v;
        else
            *(uint4*)(g_kt + (((size_t)b*Fn + f)*Tn + t)*CHn + c) = v;
    }
}

// =====================================================================
// Kernel 2: fv conv, tensor cores. (unchanged)
// =====================================================================
__global__ void __launch_bounds__(256) conv_v_kernel(
    const float* __restrict__ xin, const float* __restrict__ aa)
{
    extern __shared__ char smc[];
    __nv_bfloat16* sIn = (__nv_bfloat16*)smc;
    __nv_bfloat16* sW  = (__nv_bfloat16*)(smc + 33792);
    __nv_bfloat16* sOut= (__nv_bfloat16*)(smc + 38400);
    float* sBias = (float*)(smc + 58880);
    float* sAl   = (float*)(smc + 59008);
    uint32_t sb = (uint32_t)__cvta_generic_to_shared(smc);

    int tid = threadIdx.x, f = blockIdx.x, b = blockIdx.y;

    #pragma unroll
    for (int i = tid; i < 288; i += 256)
        ((uint4*)sW)[i] = ((const uint4*)wv_bf)[i];
    if (tid < 32) sBias[tid] = b_v[tid];
    if (tid == 0) sAl[0] = aa[0];

    const float* ip = xin + (size_t)b*Cn*Sn + (size_t)f*Tn;
    #pragma unroll
    for (int jj = 0; jj < 16; jj++) {
        int idx4 = tid + jj*256;
        int k = idx4 >> 6, t4 = (idx4 & 63)*4;
        float4 v = *(const float4*)(ip + (size_t)k*Sn + t4);
        *(uint32_t*)&sIn[k*264 + t4]     = pkbf2(v.x, v.y);
        *(uint32_t*)&sIn[k*264 + t4 + 2] = pkbf2(v.z, v.w);
    }
    __syncthreads();

    int lane = tid & 31, w = tid >> 5;
    int g = lane >> 2, t2 = (lane & 3)*2;

    uint32_t qa[2][4][4];
    {
        int krow = (lane & 7) + ((lane >> 4) << 3);
        #pragma unroll
        for (int mt = 0; mt < 2; mt++) {
            int col = w*32 + mt*16 + ((lane >> 3) & 1)*8;
            #pragma unroll
            for (int ks = 0; ks < 4; ks++)
                ldsm4t(qa[mt][ks], sb + (uint32_t)((ks*16 + krow)*264 + col)*2);
        }
    }

    float al = sAl[0];
    #pragma unroll
    for (int nt = 0; nt < 4; nt++) {
        uint32_t kb0[4], kb1[4];
        uint32_t baddr = sb + 33792 +
            (uint32_t)((nt*8 + (lane & 7))*72 + (lane >> 3)*8)*2;
        ldsm4(kb0, baddr);
        ldsm4(kb1, baddr + 64);
        float b0 = sBias[nt*8 + t2], b1 = sBias[nt*8 + t2 + 1];
        #pragma unroll
        for (int mt = 0; mt < 2; mt++) {
            float D[4] = {0.f, 0.f, 0.f, 0.f};
            mma_bf16(D, qa[mt][0], kb0 + 0);
            mma_bf16(D, qa[mt][1], kb0 + 2);
            mma_bf16(D, qa[mt][2], kb1 + 0);
            mma_bf16(D, qa[mt][3], kb1 + 2);
            float v0 = D[0] + b0; v0 = (v0 > 0.f) ? v0 : al*v0;
            float v1 = D[1] + b1; v1 = (v1 > 0.f) ? v1 : al*v1;
            float v2 = D[2] + b0; v2 = (v2 > 0.f) ? v2 : al*v2;
            float v3 = D[3] + b1; v3 = (v3 > 0.f) ? v3 : al*v3;
            int p = w*32 + mt*16 + g;
            *(uint32_t*)&sOut[p*40 + nt*8 + t2]     = pkbf2(v0, v1);
            *(uint32_t*)&sOut[(p+8)*40 + nt*8 + t2] = pkbf2(v2, v3);
        }
    }
    __syncthreads();

    #pragma unroll
    for (int j = 0; j < 4; j++) {
        int idx = tid + j*256;
        int pos = idx >> 2;
        int c   = (idx & 3)*8;
        uint4 v = *(const uint4*)&sOut[pos*40 + c];
        *(uint4*)(g_vf + (((size_t)b*Tn + pos)*Fn + f)*CHn + c) = v;
    }
}

// =====================================================================
// Attention kernel — v10:
//  * V staged in NATURAL [y][40] layout (uint4 copy); PV B-fragments
//    via ldmatrix.trans (conflict-free; kills scalar transpose staging)
//  * PV interleaved per 32-col slice right after its 4 score tiles
//    (P registers halved; shorter chains)
//  * fused dual row-tiles, no-max ex2 softmax (as v9)
// =====================================================================
template<bool CAUSAL>
__global__ void __launch_bounds__(256, 2) attn_kernel()
{
    const __nv_bfloat16* __restrict__ qg = CAUSAL ? g_qt : g_qf;
    const __nv_bfloat16* __restrict__ kg = CAUSAL ? g_kt : g_kf;
    const __nv_bfloat16* __restrict__ vg = CAUSAL ? g_fout : g_vf;
    __nv_bfloat16* __restrict__ outg     = CAUSAL ? g_tout : g_fout;

    extern __shared__ char smb[];
    constexpr int KOFF = 0, VOFF = 20480, QOFF = 40960;
    __nv_bfloat16* sK = (__nv_bfloat16*)(smb + KOFF);   // [256][40]
    __nv_bfloat16* sV = (__nv_bfloat16*)(smb + VOFF);   // [256][40]
    __nv_bfloat16* sQ = (__nv_bfloat16*)(smb + QOFF);   // [256][40]
    uint32_t sb = (uint32_t)__cvta_generic_to_shared(smb);

    int tid = threadIdx.x, lane = tid & 31, w = tid >> 5;
    int g = lane >> 2, t2 = (lane & 3)*2;
    int col = blockIdx.x;
    int b   = blockIdx.y;
    size_t base = ((size_t)b*256 + col)*256*CHn;
    const __nv_bfloat16* qp = qg + base;
    const __nv_bfloat16* kp = kg + base;
    const __nv_bfloat16* vp = vg + base;
    size_t out_base, out_stride;
    if (CAUSAL) { out_base = base; out_stride = CHn; }
    else { out_base = ((size_t)b*Sn + col)*CHn; out_stride = (size_t)Tn*CHn; }

    // ---- stage K, V, Q all in natural [y][40] bf16 layout ----
    #pragma unroll
    for (int jj = 0; jj < 4; jj++) {
        int idx = tid + jj*256;
        int y = idx >> 2, q4 = idx & 3;
        *(uint4*)&sK[y*40 + q4*8] = *(const uint4*)(kp + y*32 + q4*8);
        *(uint4*)&sV[y*40 + q4*8] = *(const uint4*)(vp + y*32 + q4*8);
        *(uint4*)&sQ[y*40 + q4*8] = *(const uint4*)(qp + y*32 + q4*8);
    }
    __syncthreads();   // the only barrier

    const int r0a = w*16;          // tile 0 rows
    const int r0b = 128 + w*16;    // tile 1 rows

    uint32_t qa[2][2][4];
    #pragma unroll
    for (int mt = 0; mt < 2; mt++)
        #pragma unroll
        for (int ks = 0; ks < 2; ks++) {
            int row = (mt ? r0b : r0a) + (lane & 15);
            int cc  = ks*16 + (lane >> 4)*8;
            ldsm4(qa[mt][ks], sb + QOFF + (uint32_t)(row*40 + cc)*2);
        }

    float O[2][4][4];
    #pragma unroll
    for (int mt = 0; mt < 2; mt++)
        #pragma unroll
        for (int i = 0; i < 4; i++)
            #pragma unroll
            for (int j = 0; j < 4; j++) O[mt][i][j] = 0.f;
    float sA[2] = {0.f, 0.f}, sB[2] = {0.f, 0.f};

    const int qmaxa = CAUSAL ? ((r0a >> 6) + 1) : 4;
    const int qmaxb = CAUSAL ? ((r0b >> 6) + 1) : 4;

    for (int q = 0; q < qmaxb; q++) {
        const bool acta = q < qmaxa;

        #pragma unroll
        for (int kc2 = 0; kc2 < 2; kc2++) {
            int ybase = q*64 + kc2*32;
            bool pb = !CAUSAL || (ybase <= r0b + 15);
            bool pa = acta && (!CAUSAL || (ybase <= r0a + 15));
            if (CAUSAL && !pa && !pb) continue;

            // ---- 4 score tiles for this 32-col slice
            uint32_t P[2][4][2];
            #pragma unroll
            for (int ntl = 0; ntl < 4; ntl++) {
                int y0q = ybase + ntl*8;
                bool na = pa && (!CAUSAL || (y0q <= r0a + 15));
                bool nb = pb && (!CAUSAL || (y0q <= r0b + 15));

                uint32_t kb[4];
                {
                    int y = y0q + (lane & 7);
                    int k = (lane >> 3)*8;
                    ldsm4(kb, sb + KOFF + (uint32_t)(y*40 + k)*2);
                }
                float D0[4] = {0.f,0.f,0.f,0.f}, D1[4] = {0.f,0.f,0.f,0.f};
                if (na) { mma_bf16(D0, qa[0][0], kb+0); mma_bf16(D0, qa[0][1], kb+2); }
                if (nb) { mma_bf16(D1, qa[1][0], kb+0); mma_bf16(D1, qa[1][1], kb+2); }

                if (CAUSAL) {
                    int y0 = y0q + t2;
                    int rA0 = r0a + g, rB0 = rA0 + 8;
                    if (y0     > rA0) D0[0] = -1e30f;
                    if (y0 + 1 > rA0) D0[1] = -1e30f;
                    if (y0     > rB0) D0[2] = -1e30f;
                    if (y0 + 1 > rB0) D0[3] = -1e30f;
                    int rA1 = r0b + g, rB1 = rA1 + 8;
                    if (y0     > rA1) D1[0] = -1e30f;
                    if (y0 + 1 > rA1) D1[1] = -1e30f;
                    if (y0     > rB1) D1[2] = -1e30f;
                    if (y0 + 1 > rB1) D1[3] = -1e30f;
                }

                float e00 = na ? ex2(D0[0]) : 0.f;
                float e01 = na ? ex2(D0[1]) : 0.f;
                float e02 = na ? ex2(D0[2]) : 0.f;
                float e03 = na ? ex2(D0[3]) : 0.f;
                float e10 = nb ? ex2(D1[0]) : 0.f;
                float e11 = nb ? ex2(D1[1]) : 0.f;
                float e12 = nb ? ex2(D1[2]) : 0.f;
                float e13 = nb ? ex2(D1[3]) : 0.f;
                sA[0] += e00 + e01;  sB[0] += e02 + e03;
                sA[1] += e10 + e11;  sB[1] += e12 + e13;
                P[0][ntl][0] = pkbf2(e00, e01);
                P[0][ntl][1] = pkbf2(e02, e03);
                P[1][ntl][0] = pkbf2(e10, e11);
                P[1][ntl][1] = pkbf2(e12, e13);
            }

            // ---- PV for this slice (V B-fragments via ldsm.trans,
            //      loaded once, used by both row tiles)
            uint32_t a0F0[4] = {P[0][0][0], P[0][0][1], P[0][1][0], P[0][1][1]};
            uint32_t a0F1[4] = {P[0][2][0], P[0][2][1], P[0][3][0], P[0][3][1]};
            uint32_t a1F0[4] = {P[1][0][0], P[1][0][1], P[1][1][0], P[1][1][1]};
            uint32_t a1F1[4] = {P[1][2][0], P[1][2][1], P[1][3][0], P[1][3][1]};
            #pragma unroll
            for (int ntv = 0; ntv < 4; ntv++) {
                uint32_t vb[4];
                ldsm4t(vb, sb + VOFF +
                    (uint32_t)((ybase + lane)*40 + ntv*8)*2);
                if (pa) {
                    mma_bf16(O[0][ntv], a0F0, &vb[0]);
                    mma_bf16(O[0][ntv], a0F1, &vb[2]);
                }
                if (pb) {
                    mma_bf16(O[1][ntv], a1F0, &vb[0]);
                    mma_bf16(O[1][ntv], a1F1, &vb[2]);
                }
            }
        }
    }

    // ---- single end-of-kernel sum reduction + normalize + write
    #pragma unroll
    for (int dlt = 1; dlt <= 2; dlt <<= 1) {
        sA[0] += __shfl_xor_sync(0xffffffffu, sA[0], dlt);
        sB[0] += __shfl_xor_sync(0xffffffffu, sB[0], dlt);
        sA[1] += __shfl_xor_sync(0xffffffffu, sA[1], dlt);
        sB[1] += __shfl_xor_sync(0xffffffffu, sB[1], dlt);
    }
    #pragma unroll
    for (int mt = 0; mt < 2; mt++) {
        float invA = 1.f / sA[mt], invB = 1.f / sB[mt];
        int rA = (mt ? r0b : r0a) + g, rB = rA + 8;
        #pragma unroll
        for (int ntv = 0; ntv < 4; ntv++) {
            int c = ntv*8 + t2;
            *(uint32_t*)(outg + out_base + (size_t)rA*out_stride + c) =
                pkbf2(O[mt][ntv][0]*invA, O[mt][ntv][1]*invA);
            *(uint32_t*)(outg + out_base + (size_t)rB*out_stride + c) =
                pkbf2(O[mt][ntv][2]*invB, O[mt][ntv][3]*invB);
        }
    }
}

// =====================================================================
// Kernel 5: proj conv, tensor cores, + residual. (unchanged)
// =====================================================================
__global__ void __launch_bounds__(256) proj_kernel(
    const float* __restrict__ xin, const float* __restrict__ aa,
    float* __restrict__ outp)
{
    extern __shared__ char smc[];
    __nv_bfloat16* sIn  = (__nv_bfloat16*)smc;
    __nv_bfloat16* sW   = (__nv_bfloat16*)(smc + 10240);
    float*         sOutF= (float*)(smc + 15360);
    float* sBias = (float*)(smc + 49152);
    float* sAl   = (float*)(smc + 49408);
    uint32_t sb = (uint32_t)__cvta_generic_to_shared(smc);

    int tid = threadIdx.x, tile = blockIdx.x, b = blockIdx.y;
    int p0 = tile*128;

    #pragma unroll
    for (int i = tid; i < 320; i += 256)
        if (i < 320) ((uint4*)sW)[i] = ((const uint4*)wpr_bf)[i];
    if (tid < 64) sBias[tid] = b_pr[tid];
    if (tid == 0) sAl[0] = aa[0];

    const __nv_bfloat16* tp = g_tout + ((size_t)b*Sn + p0)*CHn;
    #pragma unroll
    for (int j = 0; j < 2; j++) {
        int idx = tid + j*256;
        int p = idx >> 2, q4 = idx & 3;
        *(uint4*)&sIn[p*40 + q4*8] = *(const uint4*)(tp + p*32 + q4*8);
    }
    __syncthreads();

    int lane = tid & 31, w = tid >> 5;
    int g = lane >> 2, t2 = (lane & 3)*2;

    uint32_t qa[2][4];
    #pragma unroll
    for (int ks = 0; ks < 2; ks++) {
        int row = w*16 + (lane & 15);
        int cc  = ks*16 + (lane >> 4)*8;
        ldsm4(qa[ks], sb + (uint32_t)(row*40 + cc)*2);
    }

    float al = sAl[0];
    #pragma unroll
    for (int nt = 0; nt < 8; nt++) {
        uint32_t kb[4];
        ldsm4(kb, sb + 10240 +
            (uint32_t)((nt*8 + (lane & 7))*40 + (lane >> 3)*8)*2);
        float D[4] = {0.f, 0.f, 0.f, 0.f};
        mma_bf16(D, qa[0], kb + 0);
        mma_bf16(D, qa[1], kb + 2);
        int o0 = nt*8 + t2;
        float b0 = sBias[o0], b1 = sBias[o0 + 1];
        float v0 = D[0] + b0; v0 = (v0 > 0.f) ? v0 : al*v0;
        float v1 = D[1] + b1; v1 = (v1 > 0.f) ? v1 : al*v1;
        float v2 = D[2] + b0; v2 = (v2 > 0.f) ? v2 : al*v2;
        float v3 = D[3] + b1; v3 = (v3 > 0.f) ? v3 : al*v3;
        int p = w*16 + g;
        sOutF[o0*132 + p]           = v0;
        sOutF[(o0+1)*132 + p]       = v1;
        sOutF[o0*132 + p + 8]       = v2;
        sOutF[(o0+1)*132 + p + 8]   = v3;
    }
    __syncthreads();

    #pragma unroll
    for (int j = 0; j < 8; j++) {
        int idx = tid + j*256;
        int o = idx >> 5, p4 = (idx & 31)*4;
        float4 acc = *(const float4*)&sOutF[o*132 + p4];
        float4 xr = *(const float4*)(xin + (size_t)b*Cn*Sn + (size_t)o*Sn + p0 + p4);
        *(float4*)(outp + (size_t)b*Cn*Sn + (size_t)o*Sn + p0 + p4) =
            make_float4(acc.x + xr.x, acc.y + xr.y, acc.z + xr.z, acc.w + xr.w);
    }
}

// =====================================================================
// Launch
// =====================================================================
extern "C" void kernel_launch(void* const* d_in, const int* in_sizes, int n_in,
                              void* d_out, int out_size) {
    const float* inp  = (const float*)d_in[0];
    const float* x    = (const float*)d_in[1];
    const float* fqkW = (const float*)d_in[2];
    const float* fqkb = (const float*)d_in[3];
    const float* fqkg = (const float*)d_in[4];
    const float* fqkbe= (const float*)d_in[5];
    const float* fqkm = (const float*)d_in[6];
    const float* fqkv = (const float*)d_in[7];
    const float* fqka = (const float*)d_in[8];
    const float* fvW  = (const float*)d_in[9];
    const float* fvb  = (const float*)d_in[10];
    const float* fvg  = (const float*)d_in[11];
    const float* fvbe = (const float*)d_in[12];
    const float* fvm  = (const float*)d_in[13];
    const float* fvv  = (const float*)d_in[14];
    const float* fva  = (const float*)d_in[15];
    const float* tqkW = (const float*)d_in[16];
    const float* tqkb = (const float*)d_in[17];
    const float* tqkg = (const float*)d_in[18];
    const float* tqkbe= (const float*)d_in[19];
    const float* tqkm = (const float*)d_in[20];
    const float* tqkv = (const float*)d_in[21];
    const float* tqka = (const float*)d_in[22];
    const float* prW  = (const float*)d_in[23];
    const float* prb  = (const float*)d_in[24];
    const float* prg  = (const float*)d_in[25];
    const float* prbe = (const float*)d_in[26];
    const float* prm  = (const float*)d_in[27];
    const float* prv  = (const float*)d_in[28];
    const float* pra  = (const float*)d_in[29];
    float* out = (float*)d_out;

    cudaFuncSetAttribute(conv_qk_kernel,
                         cudaFuncAttributeMaxDynamicSharedMemorySize, CQK_SMEM);
    cudaFuncSetAttribute(conv_v_kernel,
                         cudaFuncAttributeMaxDynamicSharedMemorySize, CV_SMEM);
    cudaFuncSetAttribute(proj_kernel,
                         cudaFuncAttributeMaxDynamicSharedMemorySize, PR_SMEM);
    cudaFuncSetAttribute(attn_kernel<false>,
                         cudaFuncAttributeMaxDynamicSharedMemorySize, ATTN_SMEM);
    cudaFuncSetAttribute(attn_kernel<true>,
                         cudaFuncAttributeMaxDynamicSharedMemorySize, ATTN_SMEM);

    fold_kernel<<<1, 256>>>(
        fqkW, fqkb, fqkg, fqkbe, fqkm, fqkv,
        tqkW, tqkb, tqkg, tqkbe, tqkm, tqkv,
        fvW,  fvb,  fvg,  fvbe,  fvm,  fvv,
        prW,  prb,  prg,  prbe,  prm,  prv);

    conv_qk_kernel<<<dim3(512, Bn), 256, CQK_SMEM>>>(inp, fqka, tqka);

    conv_v_kernel<<<dim3(256, Bn), 256, CV_SMEM>>>(x, fva);

    attn_kernel<false><<<dim3(256, Bn), 256, ATTN_SMEM>>>();

    attn_kernel<true><<<dim3(256, Bn), 256, ATTN_SMEM>>>();

    proj_kernel<<<dim3(512, Bn), 256, PR_SMEM>>>(x, pra, out);
}

// round 16
// speedup vs baseline: 6.1086x; 1.0129x over previous
#include <cuda_runtime.h>
#include <cuda_bf16.h>
#include <cstdint>

// Problem constants
constexpr int Bn  = 4;
constexpr int Cn  = 64;
constexpr int CHn = 32;
constexpr int Fn  = 256;
constexpr int Tn  = 256;
constexpr int Sn  = Fn * Tn;
constexpr float EPSc = 1e-5f;
constexpr float QSCALE_LOG2E = 0.17677669529663687f * 1.4426950408889634f;

__device__ __forceinline__ uint32_t pkbf2(float lo, float hi) {
    __nv_bfloat162 h = __float22bfloat162_rn(make_float2(lo, hi));
    return *(uint32_t*)&h;
}
__device__ __forceinline__ float ex2(float x) {
    float y;
    asm("ex2.approx.f32 %0, %1;" : "=f"(y) : "f"(x));
    return y;
}

// ---- tensor-core helpers ----
__device__ __forceinline__ void ldsm4(uint32_t* r, uint32_t addr) {
    asm volatile("ldmatrix.sync.aligned.m8n8.x4.shared.b16 {%0,%1,%2,%3}, [%4];\n"
        : "=r"(r[0]), "=r"(r[1]), "=r"(r[2]), "=r"(r[3]) : "r"(addr));
}
__device__ __forceinline__ void ldsm4t(uint32_t* r, uint32_t addr) {
    asm volatile("ldmatrix.sync.aligned.m8n8.x4.trans.shared.b16 {%0,%1,%2,%3}, [%4];\n"
        : "=r"(r[0]), "=r"(r[1]), "=r"(r[2]), "=r"(r[3]) : "r"(addr));
}
__device__ __forceinline__ void mma_bf16(float* d, const uint32_t* a, const uint32_t* b) {
    asm volatile(
        "mma.sync.aligned.m16n8k16.row.col.f32.bf16.bf16.f32 "
        "{%0,%1,%2,%3}, {%4,%5,%6,%7}, {%8,%9}, {%0,%1,%2,%3};\n"
        : "+f"(d[0]), "+f"(d[1]), "+f"(d[2]), "+f"(d[3])
        : "r"(a[0]), "r"(a[1]), "r"(a[2]), "r"(a[3]), "r"(b[0]), "r"(b[1]));
}

// -------- device scratch (all intermediates bf16) --------
__device__ __nv_bfloat16 g_qf[Bn*Tn*Fn*CHn];
__device__ __nv_bfloat16 g_kf[Bn*Tn*Fn*CHn];
__device__ __nv_bfloat16 g_vf[Bn*Tn*Fn*CHn];
__device__ __nv_bfloat16 g_qt[Bn*Fn*Tn*CHn];
__device__ __nv_bfloat16 g_kt[Bn*Fn*Tn*CHn];
__device__ __nv_bfloat16 g_fout[Bn*Fn*Tn*CHn];
__device__ __nv_bfloat16 g_tout[Bn*Fn*Tn*CHn];

// -------- folded bf16 weights [o][k] + fp32 biases --------
__device__ __nv_bfloat16 wqk_bf[128*72];
__device__ float b_qk[128];
__device__ __nv_bfloat16 wv_bf[32*72];
__device__ float b_v[32];
__device__ __nv_bfloat16 wpr_bf[64*40];
__device__ float b_pr[64];

// dynamic-smem sizes (bytes)
constexpr int CQK_SMEM  = 17408 + 18432 + 34816 + 512 + 8;   // 71176
constexpr int CV_SMEM   = 33792 + 4608 + 20480 + 128 + 4;    // 59012
constexpr int PR_SMEM   = 10240 + 5120 + 33792 + 256 + 4;    // 49412
// attn: sK[256][40] @0 | sV[256][40] @20480 | sQ[128][40] @40960
constexpr int ATTN_SMEM = 51200;

// =====================================================================
// Kernel 0: fold BN into bf16 weights / fp32 biases once.
// =====================================================================
__global__ void fold_kernel(
    const float* __restrict__ W1, const float* __restrict__ b1,
    const float* __restrict__ g1, const float* __restrict__ be1,
    const float* __restrict__ m1, const float* __restrict__ v1,
    const float* __restrict__ W2, const float* __restrict__ b2,
    const float* __restrict__ g2, const float* __restrict__ be2,
    const float* __restrict__ m2, const float* __restrict__ v2,
    const float* __restrict__ Wv, const float* __restrict__ bv,
    const float* __restrict__ gv, const float* __restrict__ bev,
    const float* __restrict__ mv, const float* __restrict__ vvv,
    const float* __restrict__ Wp, const float* __restrict__ bp,
    const float* __restrict__ gp, const float* __restrict__ bep,
    const float* __restrict__ mp, const float* __restrict__ vp)
{
    int tid = threadIdx.x;
    for (int idx = tid; idx < 8192; idx += 256) {
        int o = idx >> 6, k = idx & 63;
        float wv_; int grp, oo;
        if (o < 64) {
            grp = 0; oo = o;
            float sc = g1[o] * rsqrtf(v1[o] + EPSc);
            wv_ = W1[o*64 + k] * sc;
        } else {
            grp = 1; oo = o - 64;
            float sc = g2[oo] * rsqrtf(v2[oo] + EPSc);
            wv_ = W2[oo*64 + k] * sc;
        }
        bool isq = ((oo & 1) == 0);
        if (isq) wv_ *= QSCALE_LOG2E;
        int op = grp*64 + (isq ? 0 : 32) + (oo >> 1);
        wqk_bf[op*72 + k] = __float2bfloat16(wv_);
    }
    if (tid < 128) {
        int o = tid;
        float bias; int grp, oo;
        if (o < 64) {
            grp = 0; oo = o;
            float sc = g1[o] * rsqrtf(v1[o] + EPSc);
            bias = (b1[o] - m1[o]) * sc + be1[o];
        } else {
            grp = 1; oo = o - 64;
            float sc = g2[oo] * rsqrtf(v2[oo] + EPSc);
            bias = (b2[oo] - m2[oo]) * sc + be2[oo];
        }
        bool isq = ((oo & 1) == 0);
        if (isq) bias *= QSCALE_LOG2E;
        int op = grp*64 + (isq ? 0 : 32) + (oo >> 1);
        b_qk[op] = bias;
    }
    for (int idx = tid; idx < 2048; idx += 256) {
        int o = idx >> 6, k = idx & 63;
        float sc = gv[o] * rsqrtf(vvv[o] + EPSc);
        wv_bf[o*72 + k] = __float2bfloat16(Wv[o*64 + k] * sc);
    }
    if (tid < 32) {
        float sc = gv[tid] * rsqrtf(vvv[tid] + EPSc);
        b_v[tid] = (bv[tid] - mv[tid]) * sc + bev[tid];
    }
    for (int idx = tid; idx < 2048; idx += 256) {
        int o = idx >> 5, k = idx & 31;
        float sc = gp[o] * rsqrtf(vp[o] + EPSc);
        wpr_bf[o*40 + k] = __float2bfloat16(Wp[o*32 + k] * sc);
    }
    if (tid < 64) {
        float sc = gp[tid] * rsqrtf(vp[tid] + EPSc);
        b_pr[tid] = (bp[tid] - mp[tid]) * sc + bep[tid];
    }
}

// =====================================================================
// Kernel 1: fused fqk+tqk conv, tensor cores. (unchanged)
// =====================================================================
__global__ void __launch_bounds__(256) conv_qk_kernel(
    const float* __restrict__ inp,
    const float* __restrict__ a1, const float* __restrict__ a2)
{
    extern __shared__ char smc[];
    __nv_bfloat16* sIn = (__nv_bfloat16*)smc;
    __nv_bfloat16* sW  = (__nv_bfloat16*)(smc + 17408);
    __nv_bfloat16* sOut= (__nv_bfloat16*)(smc + 35840);
    float* sBias = (float*)(smc + 70656);
    float* sAl   = (float*)(smc + 71168);
    uint32_t sb = (uint32_t)__cvta_generic_to_shared(smc);

    int tid = threadIdx.x, b = blockIdx.y, tile = blockIdx.x;
    int p0 = tile*128, f = p0 >> 8, t0 = p0 & 255;

    #pragma unroll
    for (int i = tid; i < 1152; i += 256)
        ((uint4*)sW)[i] = ((const uint4*)wqk_bf)[i];
    if (tid < 128) sBias[tid] = b_qk[tid];
    if (tid == 0) { sAl[0] = a1[0]; sAl[1] = a2[0]; }

    const float* ip = inp + (size_t)b*Cn*Sn + p0;
    #pragma unroll
    for (int jj = 0; jj < 8; jj++) {
        int idx4 = tid + jj*256;
        int k = idx4 >> 5, p4 = (idx4 & 31)*4;
        float4 v = *(const float4*)(ip + (size_t)k*Sn + p4);
        *(uint32_t*)&sIn[k*136 + p4]     = pkbf2(v.x, v.y);
        *(uint32_t*)&sIn[k*136 + p4 + 2] = pkbf2(v.z, v.w);
    }
    __syncthreads();

    int lane = tid & 31, w = tid >> 5;
    int g = lane >> 2, t2 = (lane & 3)*2;

    uint32_t qa[4][4];
    {
        int krow = (lane & 7) + ((lane >> 4) << 3);
        int col  = w*16 + ((lane >> 3) & 1)*8;
        #pragma unroll
        for (int ks = 0; ks < 4; ks++)
            ldsm4t(qa[ks], sb + (uint32_t)((ks*16 + krow)*136 + col)*2);
    }

    float alF = sAl[0], alT = sAl[1];
    #pragma unroll
    for (int nt = 0; nt < 16; nt++) {
        uint32_t kb0[4], kb1[4];
        uint32_t baddr = sb + 17408 +
            (uint32_t)((nt*8 + (lane & 7))*72 + (lane >> 3)*8)*2;
        ldsm4(kb0, baddr);
        ldsm4(kb1, baddr + 64);
        float D[4] = {0.f, 0.f, 0.f, 0.f};
        mma_bf16(D, qa[0], kb0 + 0);
        mma_bf16(D, qa[1], kb0 + 2);
        mma_bf16(D, qa[2], kb1 + 0);
        mma_bf16(D, qa[3], kb1 + 2);
        float al = (nt < 8) ? alF : alT;
        float b0 = sBias[nt*8 + t2], b1 = sBias[nt*8 + t2 + 1];
        float v0 = D[0] + b0; v0 = (v0 > 0.f) ? v0 : al*v0;
        float v1 = D[1] + b1; v1 = (v1 > 0.f) ? v1 : al*v1;
        float v2 = D[2] + b0; v2 = (v2 > 0.f) ? v2 : al*v2;
        float v3 = D[3] + b1; v3 = (v3 > 0.f) ? v3 : al*v3;
        int p = w*16 + g;
        *(uint32_t*)&sOut[p*136 + nt*8 + t2]       = pkbf2(v0, v1);
        *(uint32_t*)&sOut[(p+8)*136 + nt*8 + t2]   = pkbf2(v2, v3);
    }
    __syncthreads();

    #pragma unroll
    for (int j = 0; j < 8; j++) {
        int idx = tid + j*256;
        int arr = idx >> 9;
        int pos = (idx >> 2) & 127;
        int c   = (idx & 3)*8;
        uint4 v = *(const uint4*)&sOut[pos*136 + arr*32 + c];
        int t = t0 + pos;
        if (arr == 0)
            *(uint4*)(g_qf + (((size_t)b*Tn + t)*Fn + f)*CHn + c) = v;
        else if (arr == 1)
            *(uint4*)(g_kf + (((size_t)b*Tn + t)*Fn + f)*CHn + c) = v;
        else if (arr == 2)
            *(uint4*)(g_qt + (((size_t)b*Fn + f)*Tn + t)*CHn + c) = v;
        else
            *(uint4*)(g_kt + (((size_t)b*Fn + f)*Tn + t)*CHn + c) = v;
    }
}

// =====================================================================
// Kernel 2: fv conv, tensor cores. (unchanged)
// =====================================================================
__global__ void __launch_bounds__(256) conv_v_kernel(
    const float* __restrict__ xin, const float* __restrict__ aa)
{
    extern __shared__ char smc[];
    __nv_bfloat16* sIn = (__nv_bfloat16*)smc;
    __nv_bfloat16* sW  = (__nv_bfloat16*)(smc + 33792);
    __nv_bfloat16* sOut= (__nv_bfloat16*)(smc + 38400);
    float* sBias = (float*)(smc + 58880);
    float* sAl   = (float*)(smc + 59008);
    uint32_t sb = (uint32_t)__cvta_generic_to_shared(smc);

    int tid = threadIdx.x, f = blockIdx.x, b = blockIdx.y;

    #pragma unroll
    for (int i = tid; i < 288; i += 256)
        ((uint4*)sW)[i] = ((const uint4*)wv_bf)[i];
    if (tid < 32) sBias[tid] = b_v[tid];
    if (tid == 0) sAl[0] = aa[0];

    const float* ip = xin + (size_t)b*Cn*Sn + (size_t)f*Tn;
    #pragma unroll
    for (int jj = 0; jj < 16; jj++) {
        int idx4 = tid + jj*256;
        int k = idx4 >> 6, t4 = (idx4 & 63)*4;
        float4 v = *(const float4*)(ip + (size_t)k*Sn + t4);
        *(uint32_t*)&sIn[k*264 + t4]     = pkbf2(v.x, v.y);
        *(uint32_t*)&sIn[k*264 + t4 + 2] = pkbf2(v.z, v.w);
    }
    __syncthreads();

    int lane = tid & 31, w = tid >> 5;
    int g = lane >> 2, t2 = (lane & 3)*2;

    uint32_t qa[2][4][4];
    {
        int krow = (lane & 7) + ((lane >> 4) << 3);
        #pragma unroll
        for (int mt = 0; mt < 2; mt++) {
            int col = w*32 + mt*16 + ((lane >> 3) & 1)*8;
            #pragma unroll
            for (int ks = 0; ks < 4; ks++)
                ldsm4t(qa[mt][ks], sb + (uint32_t)((ks*16 + krow)*264 + col)*2);
        }
    }

    float al = sAl[0];
    #pragma unroll
    for (int nt = 0; nt < 4; nt++) {
        uint32_t kb0[4], kb1[4];
        uint32_t baddr = sb + 33792 +
            (uint32_t)((nt*8 + (lane & 7))*72 + (lane >> 3)*8)*2;
        ldsm4(kb0, baddr);
        ldsm4(kb1, baddr + 64);
        float b0 = sBias[nt*8 + t2], b1 = sBias[nt*8 + t2 + 1];
        #pragma unroll
        for (int mt = 0; mt < 2; mt++) {
            float D[4] = {0.f, 0.f, 0.f, 0.f};
            mma_bf16(D, qa[mt][0], kb0 + 0);
            mma_bf16(D, qa[mt][1], kb0 + 2);
            mma_bf16(D, qa[mt][2], kb1 + 0);
            mma_bf16(D, qa[mt][3], kb1 + 2);
            float v0 = D[0] + b0; v0 = (v0 > 0.f) ? v0 : al*v0;
            float v1 = D[1] + b1; v1 = (v1 > 0.f) ? v1 : al*v1;
            float v2 = D[2] + b0; v2 = (v2 > 0.f) ? v2 : al*v2;
            float v3 = D[3] + b1; v3 = (v3 > 0.f) ? v3 : al*v3;
            int p = w*32 + mt*16 + g;
            *(uint32_t*)&sOut[p*40 + nt*8 + t2]     = pkbf2(v0, v1);
            *(uint32_t*)&sOut[(p+8)*40 + nt*8 + t2] = pkbf2(v2, v3);
        }
    }
    __syncthreads();

    #pragma unroll
    for (int j = 0; j < 4; j++) {
        int idx = tid + j*256;
        int pos = idx >> 2;
        int c   = (idx & 3)*8;
        uint4 v = *(const uint4*)&sOut[pos*40 + c];
        *(uint4*)(g_vf + (((size_t)b*Tn + pos)*Fn + f)*CHn + c) = v;
    }
}

// =====================================================================
// Attention kernel — v11: row-split blocks.
//  * grid (512, Bn): block = (col, half h); handles 128 rows
//  * K, V staged fully; Q staged for this half only
//  * 1 tile/warp -> ~80 regs -> 3 blocks/SM; 2048 blocks -> smooth waves
//  * no-max ex2 softmax, trans-ldsm V, interleaved PV (as v10)
// =====================================================================
template<bool CAUSAL>
__global__ void __launch_bounds__(256, 3) attn_kernel()
{
    const __nv_bfloat16* __restrict__ qg = CAUSAL ? g_qt : g_qf;
    const __nv_bfloat16* __restrict__ kg = CAUSAL ? g_kt : g_kf;
    const __nv_bfloat16* __restrict__ vg = CAUSAL ? g_fout : g_vf;
    __nv_bfloat16* __restrict__ outg     = CAUSAL ? g_tout : g_fout;

    extern __shared__ char smb[];
    constexpr int KOFF = 0, VOFF = 20480, QOFF = 40960;
    __nv_bfloat16* sK = (__nv_bfloat16*)(smb + KOFF);   // [256][40]
    __nv_bfloat16* sV = (__nv_bfloat16*)(smb + VOFF);   // [256][40]
    __nv_bfloat16* sQ = (__nv_bfloat16*)(smb + QOFF);   // [128][40]
    uint32_t sb = (uint32_t)__cvta_generic_to_shared(smb);

    int tid = threadIdx.x, lane = tid & 31, w = tid >> 5;
    int g = lane >> 2, t2 = (lane & 3)*2;
    int col = blockIdx.x & 255;
    int h   = blockIdx.x >> 8;        // row half: 0 or 1
    int b   = blockIdx.y;
    size_t base = ((size_t)b*256 + col)*256*CHn;
    const __nv_bfloat16* qp = qg + base + (size_t)h*128*CHn;
    const __nv_bfloat16* kp = kg + base;
    const __nv_bfloat16* vp = vg + base;
    size_t out_base, out_stride;
    if (CAUSAL) { out_base = base; out_stride = CHn; }
    else { out_base = ((size_t)b*Sn + col)*CHn; out_stride = (size_t)Tn*CHn; }

    // ---- stage K, V (full 256) and Q (this half's 128 rows) ----
    #pragma unroll
    for (int jj = 0; jj < 4; jj++) {
        int idx = tid + jj*256;
        int y = idx >> 2, q4 = idx & 3;
        *(uint4*)&sK[y*40 + q4*8] = *(const uint4*)(kp + y*32 + q4*8);
        *(uint4*)&sV[y*40 + q4*8] = *(const uint4*)(vp + y*32 + q4*8);
    }
    #pragma unroll
    for (int jj = 0; jj < 2; jj++) {
        int idx = tid + jj*256;
        int y = idx >> 2, q4 = idx & 3;
        *(uint4*)&sQ[y*40 + q4*8] = *(const uint4*)(qp + y*32 + q4*8);
    }
    __syncthreads();   // the only barrier

    const int r0 = h*128 + w*16;       // global row base for this warp

    uint32_t qa[2][4];
    #pragma unroll
    for (int ks = 0; ks < 2; ks++) {
        int row = w*16 + (lane & 15);  // local Q row
        int cc  = ks*16 + (lane >> 4)*8;
        ldsm4(qa[ks], sb + QOFF + (uint32_t)(row*40 + cc)*2);
    }

    float O[4][4];
    #pragma unroll
    for (int i = 0; i < 4; i++)
        #pragma unroll
        for (int j = 0; j < 4; j++) O[i][j] = 0.f;
    float sA = 0.f, sB = 0.f;

    const int qmax = CAUSAL ? ((r0 >> 6) + 1) : 4;

    for (int q = 0; q < qmax; q++) {
        #pragma unroll
        for (int kc2 = 0; kc2 < 2; kc2++) {
            int ybase = q*64 + kc2*32;
            if (CAUSAL && (ybase > r0 + 15)) continue;

            // ---- 4 score tiles for this 32-col slice
            uint32_t P[4][2];
            #pragma unroll
            for (int ntl = 0; ntl < 4; ntl++) {
                int y0q = ybase + ntl*8;
                bool need = !CAUSAL || (y0q <= r0 + 15);

                float D[4] = {0.f,0.f,0.f,0.f};
                if (need) {
                    uint32_t kb[4];
                    int y = y0q + (lane & 7);
                    int k = (lane >> 3)*8;
                    ldsm4(kb, sb + KOFF + (uint32_t)(y*40 + k)*2);
                    mma_bf16(D, qa[0], kb+0);
                    mma_bf16(D, qa[1], kb+2);
                }

                if (CAUSAL) {
                    int y0 = y0q + t2;
                    int rA = r0 + g, rB = rA + 8;
                    if (y0     > rA) D[0] = -1e30f;
                    if (y0 + 1 > rA) D[1] = -1e30f;
                    if (y0     > rB) D[2] = -1e30f;
                    if (y0 + 1 > rB) D[3] = -1e30f;
                }

                float e0 = need ? ex2(D[0]) : 0.f;
                float e1 = need ? ex2(D[1]) : 0.f;
                float e2 = need ? ex2(D[2]) : 0.f;
                float e3 = need ? ex2(D[3]) : 0.f;
                sA += e0 + e1;  sB += e2 + e3;
                P[ntl][0] = pkbf2(e0, e1);
                P[ntl][1] = pkbf2(e2, e3);
            }

            // ---- PV for this slice
            uint32_t aF0[4] = {P[0][0], P[0][1], P[1][0], P[1][1]};
            uint32_t aF1[4] = {P[2][0], P[2][1], P[3][0], P[3][1]};
            #pragma unroll
            for (int ntv = 0; ntv < 4; ntv++) {
                uint32_t vb[4];
                ldsm4t(vb, sb + VOFF +
                    (uint32_t)((ybase + lane)*40 + ntv*8)*2);
                mma_bf16(O[ntv], aF0, &vb[0]);
                mma_bf16(O[ntv], aF1, &vb[2]);
            }
        }
    }

    // ---- sum reduction + normalize + write
    #pragma unroll
    for (int dlt = 1; dlt <= 2; dlt <<= 1) {
        sA += __shfl_xor_sync(0xffffffffu, sA, dlt);
        sB += __shfl_xor_sync(0xffffffffu, sB, dlt);
    }
    float invA = 1.f / sA, invB = 1.f / sB;
    int rA = r0 + g, rB = rA + 8;
    #pragma unroll
    for (int ntv = 0; ntv < 4; ntv++) {
        int c = ntv*8 + t2;
        *(uint32_t*)(outg + out_base + (size_t)rA*out_stride + c) =
            pkbf2(O[ntv][0]*invA, O[ntv][1]*invA);
        *(uint32_t*)(outg + out_base + (size_t)rB*out_stride + c) =
            pkbf2(O[ntv][2]*invB, O[ntv][3]*invB);
    }
}

// =====================================================================
// Kernel 5: proj conv, tensor cores, + residual. (unchanged)
// =====================================================================
__global__ void __launch_bounds__(256) proj_kernel(
    const float* __restrict__ xin, const float* __restrict__ aa,
    float* __restrict__ outp)
{
    extern __shared__ char smc[];
    __nv_bfloat16* sIn  = (__nv_bfloat16*)smc;
    __nv_bfloat16* sW   = (__nv_bfloat16*)(smc + 10240);
    float*         sOutF= (float*)(smc + 15360);
    float* sBias = (float*)(smc + 49152);
    float* sAl   = (float*)(smc + 49408);
    uint32_t sb = (uint32_t)__cvta_generic_to_shared(smc);

    int tid = threadIdx.x, tile = blockIdx.x, b = blockIdx.y;
    int p0 = tile*128;

    #pragma unroll
    for (int i = tid; i < 320; i += 256)
        if (i < 320) ((uint4*)sW)[i] = ((const uint4*)wpr_bf)[i];
    if (tid < 64) sBias[tid] = b_pr[tid];
    if (tid == 0) sAl[0] = aa[0];

    const __nv_bfloat16* tp = g_tout + ((size_t)b*Sn + p0)*CHn;
    #pragma unroll
    for (int j = 0; j < 2; j++) {
        int idx = tid + j*256;
        int p = idx >> 2, q4 = idx & 3;
        *(uint4*)&sIn[p*40 + q4*8] = *(const uint4*)(tp + p*32 + q4*8);
    }
    __syncthreads();

    int lane = tid & 31, w = tid >> 5;
    int g = lane >> 2, t2 = (lane & 3)*2;

    uint32_t qa[2][4];
    #pragma unroll
    for (int ks = 0; ks < 2; ks++) {
        int row = w*16 + (lane & 15);
        int cc  = ks*16 + (lane >> 4)*8;
        ldsm4(qa[ks], sb + (uint32_t)(row*40 + cc)*2);
    }

    float al = sAl[0];
    #pragma unroll
    for (int nt = 0; nt < 8; nt++) {
        uint32_t kb[4];
        ldsm4(kb, sb + 10240 +
            (uint32_t)((nt*8 + (lane & 7))*40 + (lane >> 3)*8)*2);
        float D[4] = {0.f, 0.f, 0.f, 0.f};
        mma_bf16(D, qa[0], kb + 0);
        mma_bf16(D, qa[1], kb + 2);
        int o0 = nt*8 + t2;
        float b0 = sBias[o0], b1 = sBias[o0 + 1];
        float v0 = D[0] + b0; v0 = (v0 > 0.f) ? v0 : al*v0;
        float v1 = D[1] + b1; v1 = (v1 > 0.f) ? v1 : al*v1;
        float v2 = D[2] + b0; v2 = (v2 > 0.f) ? v2 : al*v2;
        float v3 = D[3] + b1; v3 = (v3 > 0.f) ? v3 : al*v3;
        int p = w*16 + g;
        sOutF[o0*132 + p]           = v0;
        sOutF[(o0+1)*132 + p]       = v1;
        sOutF[o0*132 + p + 8]       = v2;
        sOutF[(o0+1)*132 + p + 8]   = v3;
    }
    __syncthreads();

    #pragma unroll
    for (int j = 0; j < 8; j++) {
        int idx = tid + j*256;
        int o = idx >> 5, p4 = (idx & 31)*4;
        float4 acc = *(const float4*)&sOutF[o*132 + p4];
        float4 xr = *(const float4*)(xin + (size_t)b*Cn*Sn + (size_t)o*Sn + p0 + p4);
        *(float4*)(outp + (size_t)b*Cn*Sn + (size_t)o*Sn + p0 + p4) =
            make_float4(acc.x + xr.x, acc.y + xr.y, acc.z + xr.z, acc.w + xr.w);
    }
}

// =====================================================================
// Launch
// =====================================================================
extern "C" void kernel_launch(void* const* d_in, const int* in_sizes, int n_in,
                              void* d_out, int out_size) {
    const float* inp  = (const float*)d_in[0];
    const float* x    = (const float*)d_in[1];
    const float* fqkW = (const float*)d_in[2];
    const float* fqkb = (const float*)d_in[3];
    const float* fqkg = (const float*)d_in[4];
    const float* fqkbe= (const float*)d_in[5];
    const float* fqkm = (const float*)d_in[6];
    const float* fqkv = (const float*)d_in[7];
    const float* fqka = (const float*)d_in[8];
    const float* fvW  = (const float*)d_in[9];
    const float* fvb  = (const float*)d_in[10];
    const float* fvg  = (const float*)d_in[11];
    const float* fvbe = (const float*)d_in[12];
    const float* fvm  = (const float*)d_in[13];
    const float* fvv  = (const float*)d_in[14];
    const float* fva  = (const float*)d_in[15];
    const float* tqkW = (const float*)d_in[16];
    const float* tqkb = (const float*)d_in[17];
    const float* tqkg = (const float*)d_in[18];
    const float* tqkbe= (const float*)d_in[19];
    const float* tqkm = (const float*)d_in[20];
    const float* tqkv = (const float*)d_in[21];
    const float* tqka = (const float*)d_in[22];
    const float* prW  = (const float*)d_in[23];
    const float* prb  = (const float*)d_in[24];
    const float* prg  = (const float*)d_in[25];
    const float* prbe = (const float*)d_in[26];
    const float* prm  = (const float*)d_in[27];
    const float* prv  = (const float*)d_in[28];
    const float* pra  = (const float*)d_in[29];
    float* out = (float*)d_out;

    cudaFuncSetAttribute(conv_qk_kernel,
                         cudaFuncAttributeMaxDynamicSharedMemorySize, CQK_SMEM);
    cudaFuncSetAttribute(conv_v_kernel,
                         cudaFuncAttributeMaxDynamicSharedMemorySize, CV_SMEM);
    cudaFuncSetAttribute(proj_kernel,
                         cudaFuncAttributeMaxDynamicSharedMemorySize, PR_SMEM);
    cudaFuncSetAttribute(attn_kernel<false>,
                         cudaFuncAttributeMaxDynamicSharedMemorySize, ATTN_SMEM);
    cudaFuncSetAttribute(attn_kernel<true>,
                         cudaFuncAttributeMaxDynamicSharedMemorySize, ATTN_SMEM);

    fold_kernel<<<1, 256>>>(
        fqkW, fqkb, fqkg, fqkbe, fqkm, fqkv,
        tqkW, tqkb, tqkg, tqkbe, tqkm, tqkv,
        fvW,  fvb,  fvg,  fvbe,  fvm,  fvv,
        prW,  prb,  prg,  prbe,  prm,  prv);

    conv_qk_kernel<<<dim3(512, Bn), 256, CQK_SMEM>>>(inp, fqka, tqka);

    conv_v_kernel<<<dim3(256, Bn), 256, CV_SMEM>>>(x, fva);

    attn_kernel<false><<<dim3(512, Bn), 256, ATTN_SMEM>>>();

    attn_kernel<true><<<dim3(512, Bn), 256, ATTN_SMEM>>>();

    proj_kernel<<<dim3(512, Bn), 256, PR_SMEM>>>(x, pra, out);
}

// round 17
// speedup vs baseline: 6.8011x; 1.1134x over previous
#include <cuda_runtime.h>
#include <cuda_bf16.h>
#include <cstdint>

// Problem constants
constexpr int Bn  = 4;
constexpr int Cn  = 64;
constexpr int CHn = 32;
constexpr int Fn  = 256;
constexpr int Tn  = 256;
constexpr int Sn  = Fn * Tn;
constexpr float EPSc = 1e-5f;
constexpr float QSCALE_LOG2E = 0.17677669529663687f * 1.4426950408889634f;

__device__ __forceinline__ uint32_t pkbf2(float lo, float hi) {
    __nv_bfloat162 h = __float22bfloat162_rn(make_float2(lo, hi));
    return *(uint32_t*)&h;
}
__device__ __forceinline__ float ex2(float x) {
    float y;
    asm("ex2.approx.f32 %0, %1;" : "=f"(y) : "f"(x));
    return y;
}

// ---- tensor-core helpers ----
__device__ __forceinline__ void ldsm4(uint32_t* r, uint32_t addr) {
    asm volatile("ldmatrix.sync.aligned.m8n8.x4.shared.b16 {%0,%1,%2,%3}, [%4];\n"
        : "=r"(r[0]), "=r"(r[1]), "=r"(r[2]), "=r"(r[3]) : "r"(addr));
}
__device__ __forceinline__ void ldsm4t(uint32_t* r, uint32_t addr) {
    asm volatile("ldmatrix.sync.aligned.m8n8.x4.trans.shared.b16 {%0,%1,%2,%3}, [%4];\n"
        : "=r"(r[0]), "=r"(r[1]), "=r"(r[2]), "=r"(r[3]) : "r"(addr));
}
__device__ __forceinline__ void mma_bf16(float* d, const uint32_t* a, const uint32_t* b) {
    asm volatile(
        "mma.sync.aligned.m16n8k16.row.col.f32.bf16.bf16.f32 "
        "{%0,%1,%2,%3}, {%4,%5,%6,%7}, {%8,%9}, {%0,%1,%2,%3};\n"
        : "+f"(d[0]), "+f"(d[1]), "+f"(d[2]), "+f"(d[3])
        : "r"(a[0]), "r"(a[1]), "r"(a[2]), "r"(a[3]), "r"(b[0]), "r"(b[1]));
}

// -------- device scratch (all intermediates bf16) --------
__device__ __nv_bfloat16 g_qf[Bn*Tn*Fn*CHn];
__device__ __nv_bfloat16 g_kf[Bn*Tn*Fn*CHn];
__device__ __nv_bfloat16 g_vf[Bn*Tn*Fn*CHn];
__device__ __nv_bfloat16 g_qt[Bn*Fn*Tn*CHn];
__device__ __nv_bfloat16 g_kt[Bn*Fn*Tn*CHn];
__device__ __nv_bfloat16 g_fout[Bn*Fn*Tn*CHn];
__device__ __nv_bfloat16 g_tout[Bn*Fn*Tn*CHn];

// -------- folded bf16 weights [o][k] + fp32 biases --------
__device__ __nv_bfloat16 wqk_bf[128*72];
__device__ float b_qk[128];
__device__ __nv_bfloat16 wv_bf[32*72];
__device__ float b_v[32];
__device__ __nv_bfloat16 wpr_bf[64*40];
__device__ float b_pr[64];

// dynamic-smem sizes (bytes)
constexpr int CQK_SMEM  = 17408 + 18432 + 34816 + 512 + 8;   // 71176
constexpr int CV_SMEM   = 33792 + 4608 + 20480 + 128 + 4;    // 59012
constexpr int PR_SMEM   = 10240 + 5120 + 33792 + 256 + 4;    // 49412
// full attn: sK[256][40] | sV[256][40] | sQ[256][40]
constexpr int ATTN_F_SMEM = 61440;
// split attn: sK[256][40] | sV[256][40] | sQ[128][40]
constexpr int ATTN_C_SMEM = 51200;

// =====================================================================
// Kernel 0: fold BN into bf16 weights / fp32 biases. Parallel (48 blocks).
// =====================================================================
__global__ void fold_kernel(
    const float* __restrict__ W1, const float* __restrict__ b1,
    const float* __restrict__ g1, const float* __restrict__ be1,
    const float* __restrict__ m1, const float* __restrict__ v1,
    const float* __restrict__ W2, const float* __restrict__ b2,
    const float* __restrict__ g2, const float* __restrict__ be2,
    const float* __restrict__ m2, const float* __restrict__ v2,
    const float* __restrict__ Wv, const float* __restrict__ bv,
    const float* __restrict__ gv, const float* __restrict__ bev,
    const float* __restrict__ mv, const float* __restrict__ vvv,
    const float* __restrict__ Wp, const float* __restrict__ bp,
    const float* __restrict__ gp, const float* __restrict__ bep,
    const float* __restrict__ mp, const float* __restrict__ vp)
{
    int gtid = blockIdx.x * blockDim.x + threadIdx.x;
    int nthr = gridDim.x * blockDim.x;
    for (int idx = gtid; idx < 8192; idx += nthr) {
        int o = idx >> 6, k = idx & 63;
        float wv_; int grp, oo;
        if (o < 64) {
            grp = 0; oo = o;
            float sc = g1[o] * rsqrtf(v1[o] + EPSc);
            wv_ = W1[o*64 + k] * sc;
        } else {
            grp = 1; oo = o - 64;
            float sc = g2[oo] * rsqrtf(v2[oo] + EPSc);
            wv_ = W2[oo*64 + k] * sc;
        }
        bool isq = ((oo & 1) == 0);
        if (isq) wv_ *= QSCALE_LOG2E;
        int op = grp*64 + (isq ? 0 : 32) + (oo >> 1);
        wqk_bf[op*72 + k] = __float2bfloat16(wv_);
    }
    for (int o = gtid; o < 128; o += nthr) {
        float bias; int grp, oo;
        if (o < 64) {
            grp = 0; oo = o;
            float sc = g1[o] * rsqrtf(v1[o] + EPSc);
            bias = (b1[o] - m1[o]) * sc + be1[o];
        } else {
            grp = 1; oo = o - 64;
            float sc = g2[oo] * rsqrtf(v2[oo] + EPSc);
            bias = (b2[oo] - m2[oo]) * sc + be2[oo];
        }
        bool isq = ((oo & 1) == 0);
        if (isq) bias *= QSCALE_LOG2E;
        int op = grp*64 + (isq ? 0 : 32) + (oo >> 1);
        b_qk[op] = bias;
    }
    for (int idx = gtid; idx < 2048; idx += nthr) {
        int o = idx >> 6, k = idx & 63;
        float sc = gv[o] * rsqrtf(vvv[o] + EPSc);
        wv_bf[o*72 + k] = __float2bfloat16(Wv[o*64 + k] * sc);
    }
    for (int o = gtid; o < 32; o += nthr) {
        float sc = gv[o] * rsqrtf(vvv[o] + EPSc);
        b_v[o] = (bv[o] - mv[o]) * sc + bev[o];
    }
    for (int idx = gtid; idx < 2048; idx += nthr) {
        int o = idx >> 5, k = idx & 31;
        float sc = gp[o] * rsqrtf(vp[o] + EPSc);
        wpr_bf[o*40 + k] = __float2bfloat16(Wp[o*32 + k] * sc);
    }
    for (int o = gtid; o < 64; o += nthr) {
        float sc = gp[o] * rsqrtf(vp[o] + EPSc);
        b_pr[o] = (bp[o] - mp[o]) * sc + bep[o];
    }
}

// =====================================================================
// Kernel 1: fused fqk+tqk conv, tensor cores.
// =====================================================================
__global__ void __launch_bounds__(256) conv_qk_kernel(
    const float* __restrict__ inp,
    const float* __restrict__ a1, const float* __restrict__ a2)
{
    extern __shared__ char smc[];
    __nv_bfloat16* sIn = (__nv_bfloat16*)smc;
    __nv_bfloat16* sW  = (__nv_bfloat16*)(smc + 17408);
    __nv_bfloat16* sOut= (__nv_bfloat16*)(smc + 35840);
    float* sBias = (float*)(smc + 70656);
    float* sAl   = (float*)(smc + 71168);
    uint32_t sb = (uint32_t)__cvta_generic_to_shared(smc);

    int tid = threadIdx.x, b = blockIdx.y, tile = blockIdx.x;
    int p0 = tile*128, f = p0 >> 8, t0 = p0 & 255;

    #pragma unroll
    for (int i = tid; i < 1152; i += 256)
        ((uint4*)sW)[i] = ((const uint4*)wqk_bf)[i];
    if (tid < 128) sBias[tid] = b_qk[tid];
    if (tid == 0) { sAl[0] = a1[0]; sAl[1] = a2[0]; }

    const float* ip = inp + (size_t)b*Cn*Sn + p0;
    #pragma unroll
    for (int jj = 0; jj < 8; jj++) {
        int idx4 = tid + jj*256;
        int k = idx4 >> 5, p4 = (idx4 & 31)*4;
        float4 v = *(const float4*)(ip + (size_t)k*Sn + p4);
        uint2 u = make_uint2(pkbf2(v.x, v.y), pkbf2(v.z, v.w));
        *(uint2*)&sIn[k*136 + p4] = u;
    }
    __syncthreads();

    int lane = tid & 31, w = tid >> 5;
    int g = lane >> 2, t2 = (lane & 3)*2;

    uint32_t qa[4][4];
    {
        int krow = (lane & 7) + ((lane >> 4) << 3);
        int col  = w*16 + ((lane >> 3) & 1)*8;
        #pragma unroll
        for (int ks = 0; ks < 4; ks++)
            ldsm4t(qa[ks], sb + (uint32_t)((ks*16 + krow)*136 + col)*2);
    }

    float alF = sAl[0], alT = sAl[1];
    #pragma unroll
    for (int nt = 0; nt < 16; nt++) {
        uint32_t kb0[4], kb1[4];
        uint32_t baddr = sb + 17408 +
            (uint32_t)((nt*8 + (lane & 7))*72 + (lane >> 3)*8)*2;
        ldsm4(kb0, baddr);
        ldsm4(kb1, baddr + 64);
        float D[4] = {0.f, 0.f, 0.f, 0.f};
        mma_bf16(D, qa[0], kb0 + 0);
        mma_bf16(D, qa[1], kb0 + 2);
        mma_bf16(D, qa[2], kb1 + 0);
        mma_bf16(D, qa[3], kb1 + 2);
        float al = (nt < 8) ? alF : alT;
        float b0 = sBias[nt*8 + t2], b1 = sBias[nt*8 + t2 + 1];
        float v0 = D[0] + b0; v0 = (v0 > 0.f) ? v0 : al*v0;
        float v1 = D[1] + b1; v1 = (v1 > 0.f) ? v1 : al*v1;
        float v2 = D[2] + b0; v2 = (v2 > 0.f) ? v2 : al*v2;
        float v3 = D[3] + b1; v3 = (v3 > 0.f) ? v3 : al*v3;
        int p = w*16 + g;
        *(uint32_t*)&sOut[p*136 + nt*8 + t2]       = pkbf2(v0, v1);
        *(uint32_t*)&sOut[(p+8)*136 + nt*8 + t2]   = pkbf2(v2, v3);
    }
    __syncthreads();

    #pragma unroll
    for (int j = 0; j < 8; j++) {
        int idx = tid + j*256;
        int arr = idx >> 9;
        int pos = (idx >> 2) & 127;
        int c   = (idx & 3)*8;
        uint4 v = *(const uint4*)&sOut[pos*136 + arr*32 + c];
        int t = t0 + pos;
        if (arr == 0)
            *(uint4*)(g_qf + (((size_t)b*Tn + t)*Fn + f)*CHn + c) = v;
        else if (arr == 1)
            *(uint4*)(g_kf + (((size_t)b*Tn + t)*Fn + f)*CHn + c) = v;
        else if (arr == 2)
            *(uint4*)(g_qt + (((size_t)b*Fn + f)*Tn + t)*CHn + c) = v;
        else
            *(uint4*)(g_kt + (((size_t)b*Fn + f)*Tn + t)*CHn + c) = v;
    }
}

// =====================================================================
// Kernel 2: fv conv, tensor cores.
// =====================================================================
__global__ void __launch_bounds__(256) conv_v_kernel(
    const float* __restrict__ xin, const float* __restrict__ aa)
{
    extern __shared__ char smc[];
    __nv_bfloat16* sIn = (__nv_bfloat16*)smc;
    __nv_bfloat16* sW  = (__nv_bfloat16*)(smc + 33792);
    __nv_bfloat16* sOut= (__nv_bfloat16*)(smc + 38400);
    float* sBias = (float*)(smc + 58880);
    float* sAl   = (float*)(smc + 59008);
    uint32_t sb = (uint32_t)__cvta_generic_to_shared(smc);

    int tid = threadIdx.x, f = blockIdx.x, b = blockIdx.y;

    #pragma unroll
    for (int i = tid; i < 288; i += 256)
        ((uint4*)sW)[i] = ((const uint4*)wv_bf)[i];
    if (tid < 32) sBias[tid] = b_v[tid];
    if (tid == 0) sAl[0] = aa[0];

    const float* ip = xin + (size_t)b*Cn*Sn + (size_t)f*Tn;
    #pragma unroll
    for (int jj = 0; jj < 16; jj++) {
        int idx4 = tid + jj*256;
        int k = idx4 >> 6, t4 = (idx4 & 63)*4;
        float4 v = *(const float4*)(ip + (size_t)k*Sn + t4);
        uint2 u = make_uint2(pkbf2(v.x, v.y), pkbf2(v.z, v.w));
        *(uint2*)&sIn[k*264 + t4] = u;
    }
    __syncthreads();

    int lane = tid & 31, w = tid >> 5;
    int g = lane >> 2, t2 = (lane & 3)*2;

    uint32_t qa[2][4][4];
    {
        int krow = (lane & 7) + ((lane >> 4) << 3);
        #pragma unroll
        for (int mt = 0; mt < 2; mt++) {
            int col = w*32 + mt*16 + ((lane >> 3) & 1)*8;
            #pragma unroll
            for (int ks = 0; ks < 4; ks++)
                ldsm4t(qa[mt][ks], sb + (uint32_t)((ks*16 + krow)*264 + col)*2);
        }
    }

    float al = sAl[0];
    #pragma unroll
    for (int nt = 0; nt < 4; nt++) {
        uint32_t kb0[4], kb1[4];
        uint32_t baddr = sb + 33792 +
            (uint32_t)((nt*8 + (lane & 7))*72 + (lane >> 3)*8)*2;
        ldsm4(kb0, baddr);
        ldsm4(kb1, baddr + 64);
        float b0 = sBias[nt*8 + t2], b1 = sBias[nt*8 + t2 + 1];
        #pragma unroll
        for (int mt = 0; mt < 2; mt++) {
            float D[4] = {0.f, 0.f, 0.f, 0.f};
            mma_bf16(D, qa[mt][0], kb0 + 0);
            mma_bf16(D, qa[mt][1], kb0 + 2);
            mma_bf16(D, qa[mt][2], kb1 + 0);
            mma_bf16(D, qa[mt][3], kb1 + 2);
            float v0 = D[0] + b0; v0 = (v0 > 0.f) ? v0 : al*v0;
            float v1 = D[1] + b1; v1 = (v1 > 0.f) ? v1 : al*v1;
            float v2 = D[2] + b0; v2 = (v2 > 0.f) ? v2 : al*v2;
            float v3 = D[3] + b1; v3 = (v3 > 0.f) ? v3 : al*v3;
            int p = w*32 + mt*16 + g;
            *(uint32_t*)&sOut[p*40 + nt*8 + t2]     = pkbf2(v0, v1);
            *(uint32_t*)&sOut[(p+8)*40 + nt*8 + t2] = pkbf2(v2, v3);
        }
    }
    __syncthreads();

    #pragma unroll
    for (int j = 0; j < 4; j++) {
        int idx = tid + j*256;
        int pos = idx >> 2;
        int c   = (idx & 3)*8;
        uint4 v = *(const uint4*)&sOut[pos*40 + c];
        *(uint4*)(g_vf + (((size_t)b*Tn + pos)*Fn + f)*CHn + c) = v;
    }
}

// =====================================================================
// Attention — NON-CAUSAL: full-column block, 2 fused row tiles/warp
// (R15 shape: measured 35.3us). grid (256, Bn).
// =====================================================================
__global__ void __launch_bounds__(256, 2) attn_full_kernel()
{
    extern __shared__ char smb[];
    constexpr int KOFF = 0, VOFF = 20480, QOFF = 40960;
    __nv_bfloat16* sK = (__nv_bfloat16*)(smb + KOFF);   // [256][40]
    __nv_bfloat16* sV = (__nv_bfloat16*)(smb + VOFF);   // [256][40]
    __nv_bfloat16* sQ = (__nv_bfloat16*)(smb + QOFF);   // [256][40]
    uint32_t sb = (uint32_t)__cvta_generic_to_shared(smb);

    int tid = threadIdx.x, lane = tid & 31, w = tid >> 5;
    int g = lane >> 2, t2 = (lane & 3)*2;
    int col = blockIdx.x;
    int b   = blockIdx.y;
    size_t base = ((size_t)b*256 + col)*256*CHn;
    const __nv_bfloat16* qp = g_qf + base;
    const __nv_bfloat16* kp = g_kf + base;
    const __nv_bfloat16* vp = g_vf + base;
    size_t out_base = ((size_t)b*Sn + col)*CHn;
    size_t out_stride = (size_t)Tn*CHn;

    #pragma unroll
    for (int jj = 0; jj < 4; jj++) {
        int idx = tid + jj*256;
        int y = idx >> 2, q4 = idx & 3;
        *(uint4*)&sK[y*40 + q4*8] = *(const uint4*)(kp + y*32 + q4*8);
        *(uint4*)&sV[y*40 + q4*8] = *(const uint4*)(vp + y*32 + q4*8);
        *(uint4*)&sQ[y*40 + q4*8] = *(const uint4*)(qp + y*32 + q4*8);
    }
    __syncthreads();

    const int r0a = w*16;
    const int r0b = 128 + w*16;

    uint32_t qa[2][2][4];
    #pragma unroll
    for (int mt = 0; mt < 2; mt++)
        #pragma unroll
        for (int ks = 0; ks < 2; ks++) {
            int row = (mt ? r0b : r0a) + (lane & 15);
            int cc  = ks*16 + (lane >> 4)*8;
            ldsm4(qa[mt][ks], sb + QOFF + (uint32_t)(row*40 + cc)*2);
        }

    float O[2][4][4];
    #pragma unroll
    for (int mt = 0; mt < 2; mt++)
        #pragma unroll
        for (int i = 0; i < 4; i++)
            #pragma unroll
            for (int j = 0; j < 4; j++) O[mt][i][j] = 0.f;
    float sA[2] = {0.f, 0.f}, sB[2] = {0.f, 0.f};

    #pragma unroll
    for (int q = 0; q < 4; q++) {
        #pragma unroll
        for (int kc2 = 0; kc2 < 2; kc2++) {
            int ybase = q*64 + kc2*32;

            uint32_t P[2][4][2];
            #pragma unroll
            for (int ntl = 0; ntl < 4; ntl++) {
                int y0q = ybase + ntl*8;
                uint32_t kb[4];
                {
                    int y = y0q + (lane & 7);
                    int k = (lane >> 3)*8;
                    ldsm4(kb, sb + KOFF + (uint32_t)(y*40 + k)*2);
                }
                float D0[4] = {0.f,0.f,0.f,0.f}, D1[4] = {0.f,0.f,0.f,0.f};
                mma_bf16(D0, qa[0][0], kb+0); mma_bf16(D0, qa[0][1], kb+2);
                mma_bf16(D1, qa[1][0], kb+0); mma_bf16(D1, qa[1][1], kb+2);

                float e00 = ex2(D0[0]), e01 = ex2(D0[1]);
                float e02 = ex2(D0[2]), e03 = ex2(D0[3]);
                float e10 = ex2(D1[0]), e11 = ex2(D1[1]);
                float e12 = ex2(D1[2]), e13 = ex2(D1[3]);
                sA[0] += e00 + e01;  sB[0] += e02 + e03;
                sA[1] += e10 + e11;  sB[1] += e12 + e13;
                P[0][ntl][0] = pkbf2(e00, e01);
                P[0][ntl][1] = pkbf2(e02, e03);
                P[1][ntl][0] = pkbf2(e10, e11);
                P[1][ntl][1] = pkbf2(e12, e13);
            }

            uint32_t a0F0[4] = {P[0][0][0], P[0][0][1], P[0][1][0], P[0][1][1]};
            uint32_t a0F1[4] = {P[0][2][0], P[0][2][1], P[0][3][0], P[0][3][1]};
            uint32_t a1F0[4] = {P[1][0][0], P[1][0][1], P[1][1][0], P[1][1][1]};
            uint32_t a1F1[4] = {P[1][2][0], P[1][2][1], P[1][3][0], P[1][3][1]};
            #pragma unroll
            for (int ntv = 0; ntv < 4; ntv++) {
                uint32_t vb[4];
                ldsm4t(vb, sb + VOFF +
                    (uint32_t)((ybase + lane)*40 + ntv*8)*2);
                mma_bf16(O[0][ntv], a0F0, &vb[0]);
                mma_bf16(O[0][ntv], a0F1, &vb[2]);
                mma_bf16(O[1][ntv], a1F0, &vb[0]);
                mma_bf16(O[1][ntv], a1F1, &vb[2]);
            }
        }
    }

    #pragma unroll
    for (int dlt = 1; dlt <= 2; dlt <<= 1) {
        sA[0] += __shfl_xor_sync(0xffffffffu, sA[0], dlt);
        sB[0] += __shfl_xor_sync(0xffffffffu, sB[0], dlt);
        sA[1] += __shfl_xor_sync(0xffffffffu, sA[1], dlt);
        sB[1] += __shfl_xor_sync(0xffffffffu, sB[1], dlt);
    }
    #pragma unroll
    for (int mt = 0; mt < 2; mt++) {
        float invA = 1.f / sA[mt], invB = 1.f / sB[mt];
        int rA = (mt ? r0b : r0a) + g, rB = rA + 8;
        #pragma unroll
        for (int ntv = 0; ntv < 4; ntv++) {
            int c = ntv*8 + t2;
            *(uint32_t*)(g_fout + out_base + (size_t)rA*out_stride + c) =
                pkbf2(O[mt][ntv][0]*invA, O[mt][ntv][1]*invA);
            *(uint32_t*)(g_fout + out_base + (size_t)rB*out_stride + c) =
                pkbf2(O[mt][ntv][2]*invB, O[mt][ntv][3]*invB);
        }
    }
}

// =====================================================================
// Attention — CAUSAL: row-split blocks (R16 shape). grid (512, Bn).
// =====================================================================
__global__ void __launch_bounds__(256, 3) attn_causal_kernel()
{
    extern __shared__ char smb[];
    constexpr int KOFF = 0, VOFF = 20480, QOFF = 40960;
    __nv_bfloat16* sK = (__nv_bfloat16*)(smb + KOFF);   // [256][40]
    __nv_bfloat16* sV = (__nv_bfloat16*)(smb + VOFF);   // [256][40]
    __nv_bfloat16* sQ = (__nv_bfloat16*)(smb + QOFF);   // [128][40]
    uint32_t sb = (uint32_t)__cvta_generic_to_shared(smb);

    int tid = threadIdx.x, lane = tid & 31, w = tid >> 5;
    int g = lane >> 2, t2 = (lane & 3)*2;
    int col = blockIdx.x & 255;
    int h   = blockIdx.x >> 8;
    int b   = blockIdx.y;
    size_t base = ((size_t)b*256 + col)*256*CHn;
    const __nv_bfloat16* qp = g_qt + base + (size_t)h*128*CHn;
    const __nv_bfloat16* kp = g_kt + base;
    const __nv_bfloat16* vp = g_fout + base;

    #pragma unroll
    for (int jj = 0; jj < 4; jj++) {
        int idx = tid + jj*256;
        int y = idx >> 2, q4 = idx & 3;
        *(uint4*)&sK[y*40 + q4*8] = *(const uint4*)(kp + y*32 + q4*8);
        *(uint4*)&sV[y*40 + q4*8] = *(const uint4*)(vp + y*32 + q4*8);
    }
    #pragma unroll
    for (int jj = 0; jj < 2; jj++) {
        int idx = tid + jj*256;
        int y = idx >> 2, q4 = idx & 3;
        *(uint4*)&sQ[y*40 + q4*8] = *(const uint4*)(qp + y*32 + q4*8);
    }
    __syncthreads();

    const int r0 = h*128 + w*16;

    uint32_t qa[2][4];
    #pragma unroll
    for (int ks = 0; ks < 2; ks++) {
        int row = w*16 + (lane & 15);
        int cc  = ks*16 + (lane >> 4)*8;
        ldsm4(qa[ks], sb + QOFF + (uint32_t)(row*40 + cc)*2);
    }

    float O[4][4];
    #pragma unroll
    for (int i = 0; i < 4; i++)
        #pragma unroll
        for (int j = 0; j < 4; j++) O[i][j] = 0.f;
    float sA = 0.f, sB = 0.f;

    const int qmax = (r0 >> 6) + 1;

    for (int q = 0; q < qmax; q++) {
        #pragma unroll
        for (int kc2 = 0; kc2 < 2; kc2++) {
            int ybase = q*64 + kc2*32;
            if (ybase > r0 + 15) continue;

            uint32_t P[4][2];
            #pragma unroll
            for (int ntl = 0; ntl < 4; ntl++) {
                int y0q = ybase + ntl*8;
                bool need = (y0q <= r0 + 15);

                float D[4] = {0.f,0.f,0.f,0.f};
                if (need) {
                    uint32_t kb[4];
                    int y = y0q + (lane & 7);
                    int k = (lane >> 3)*8;
                    ldsm4(kb, sb + KOFF + (uint32_t)(y*40 + k)*2);
                    mma_bf16(D, qa[0], kb+0);
                    mma_bf16(D, qa[1], kb+2);
                }

                int y0 = y0q + t2;
                int rA = r0 + g, rB = rA + 8;
                if (y0     > rA) D[0] = -1e30f;
                if (y0 + 1 > rA) D[1] = -1e30f;
                if (y0     > rB) D[2] = -1e30f;
                if (y0 + 1 > rB) D[3] = -1e30f;

                float e0 = need ? ex2(D[0]) : 0.f;
                float e1 = need ? ex2(D[1]) : 0.f;
                float e2 = need ? ex2(D[2]) : 0.f;
                float e3 = need ? ex2(D[3]) : 0.f;
                sA += e0 + e1;  sB += e2 + e3;
                P[ntl][0] = pkbf2(e0, e1);
                P[ntl][1] = pkbf2(e2, e3);
            }

            uint32_t aF0[4] = {P[0][0], P[0][1], P[1][0], P[1][1]};
            uint32_t aF1[4] = {P[2][0], P[2][1], P[3][0], P[3][1]};
            #pragma unroll
            for (int ntv = 0; ntv < 4; ntv++) {
                uint32_t vb[4];
                ldsm4t(vb, sb + VOFF +
                    (uint32_t)((ybase + lane)*40 + ntv*8)*2);
                mma_bf16(O[ntv], aF0, &vb[0]);
                mma_bf16(O[ntv], aF1, &vb[2]);
            }
        }
    }

    #pragma unroll
    for (int dlt = 1; dlt <= 2; dlt <<= 1) {
        sA += __shfl_xor_sync(0xffffffffu, sA, dlt);
        sB += __shfl_xor_sync(0xffffffffu, sB, dlt);
    }
    float invA = 1.f / sA, invB = 1.f / sB;
    int rA = r0 + g, rB = rA + 8;
    #pragma unroll
    for (int ntv = 0; ntv < 4; ntv++) {
        int c = ntv*8 + t2;
        *(uint32_t*)(g_tout + base + (size_t)rA*CHn + c) =
            pkbf2(O[ntv][0]*invA, O[ntv][1]*invA);
        *(uint32_t*)(g_tout + base + (size_t)rB*CHn + c) =
            pkbf2(O[ntv][2]*invB, O[ntv][3]*invB);
    }
}

// =====================================================================
// Kernel 5: proj conv, tensor cores, + residual.
// =====================================================================
__global__ void __launch_bounds__(256) proj_kernel(
    const float* __restrict__ xin, const float* __restrict__ aa,
    float* __restrict__ outp)
{
    extern __shared__ char smc[];
    __nv_bfloat16* sIn  = (__nv_bfloat16*)smc;
    __nv_bfloat16* sW   = (__nv_bfloat16*)(smc + 10240);
    float*         sOutF= (float*)(smc + 15360);
    float* sBias = (float*)(smc + 49152);
    float* sAl   = (float*)(smc + 49408);
    uint32_t sb = (uint32_t)__cvta_generic_to_shared(smc);

    int tid = threadIdx.x, tile = blockIdx.x, b = blockIdx.y;
    int p0 = tile*128;

    #pragma unroll
    for (int i = tid; i < 320; i += 256)
        if (i < 320) ((uint4*)sW)[i] = ((const uint4*)wpr_bf)[i];
    if (tid < 64) sBias[tid] = b_pr[tid];
    if (tid == 0) sAl[0] = aa[0];

    const __nv_bfloat16* tp = g_tout + ((size_t)b*Sn + p0)*CHn;
    #pragma unroll
    for (int j = 0; j < 2; j++) {
        int idx = tid + j*256;
        int p = idx >> 2, q4 = idx & 3;
        *(uint4*)&sIn[p*40 + q4*8] = *(const uint4*)(tp + p*32 + q4*8);
    }
    __syncthreads();

    int lane = tid & 31, w = tid >> 5;
    int g = lane >> 2, t2 = (lane & 3)*2;

    uint32_t qa[2][4];
    #pragma unroll
    for (int ks = 0; ks < 2; ks++) {
        int row = w*16 + (lane & 15);
        int cc  = ks*16 + (lane >> 4)*8;
        ldsm4(qa[ks], sb + (uint32_t)(row*40 + cc)*2);
    }

    float al = sAl[0];
    #pragma unroll
    for (int nt = 0; nt < 8; nt++) {
        uint32_t kb[4];
        ldsm4(kb, sb + 10240 +
            (uint32_t)((nt*8 + (lane & 7))*40 + (lane >> 3)*8)*2);
        float D[4] = {0.f, 0.f, 0.f, 0.f};
        mma_bf16(D, qa[0], kb + 0);
        mma_bf16(D, qa[1], kb + 2);
        int o0 = nt*8 + t2;
        float b0 = sBias[o0], b1 = sBias[o0 + 1];
        float v0 = D[0] + b0; v0 = (v0 > 0.f) ? v0 : al*v0;
        float v1 = D[1] + b1; v1 = (v1 > 0.f) ? v1 : al*v1;
        float v2 = D[2] + b0; v2 = (v2 > 0.f) ? v2 : al*v2;
        float v3 = D[3] + b1; v3 = (v3 > 0.f) ? v3 : al*v3;
        int p = w*16 + g;
        sOutF[o0*132 + p]           = v0;
        sOutF[(o0+1)*132 + p]       = v1;
        sOutF[o0*132 + p + 8]       = v2;
        sOutF[(o0+1)*132 + p + 8]   = v3;
    }
    __syncthreads();

    #pragma unroll
    for (int j = 0; j < 8; j++) {
        int idx = tid + j*256;
        int o = idx >> 5, p4 = (idx & 31)*4;
        float4 acc = *(const float4*)&sOutF[o*132 + p4];
        float4 xr = *(const float4*)(xin + (size_t)b*Cn*Sn + (size_t)o*Sn + p0 + p4);
        *(float4*)(outp + (size_t)b*Cn*Sn + (size_t)o*Sn + p0 + p4) =
            make_float4(acc.x + xr.x, acc.y + xr.y, acc.z + xr.z, acc.w + xr.w);
    }
}

// =====================================================================
// Launch
// =====================================================================
extern "C" void kernel_launch(void* const* d_in, const int* in_sizes, int n_in,
                              void* d_out, int out_size) {
    const float* inp  = (const float*)d_in[0];
    const float* x    = (const float*)d_in[1];
    const float* fqkW = (const float*)d_in[2];
    const float* fqkb = (const float*)d_in[3];
    const float* fqkg = (const float*)d_in[4];
    const float* fqkbe= (const float*)d_in[5];
    const float* fqkm = (const float*)d_in[6];
    const float* fqkv = (const float*)d_in[7];
    const float* fqka = (const float*)d_in[8];
    const float* fvW  = (const float*)d_in[9];
    const float* fvb  = (const float*)d_in[10];
    const float* fvg  = (const float*)d_in[11];
    const float* fvbe = (const float*)d_in[12];
    const float* fvm  = (const float*)d_in[13];
    const float* fvv  = (const float*)d_in[14];
    const float* fva  = (const float*)d_in[15];
    const float* tqkW = (const float*)d_in[16];
    const float* tqkb = (const float*)d_in[17];
    const float* tqkg = (const float*)d_in[18];
    const float* tqkbe= (const float*)d_in[19];
    const float* tqkm = (const float*)d_in[20];
    const float* tqkv = (const float*)d_in[21];
    const float* tqka = (const float*)d_in[22];
    const float* prW  = (const float*)d_in[23];
    const float* prb  = (const float*)d_in[24];
    const float* prg  = (const float*)d_in[25];
    const float* prbe = (const float*)d_in[26];
    const float* prm  = (const float*)d_in[27];
    const float* prv  = (const float*)d_in[28];
    const float* pra  = (const float*)d_in[29];
    float* out = (float*)d_out;

    cudaFuncSetAttribute(conv_qk_kernel,
                         cudaFuncAttributeMaxDynamicSharedMemorySize, CQK_SMEM);
    cudaFuncSetAttribute(conv_v_kernel,
                         cudaFuncAttributeMaxDynamicSharedMemorySize, CV_SMEM);
    cudaFuncSetAttribute(proj_kernel,
                         cudaFuncAttributeMaxDynamicSharedMemorySize, PR_SMEM);
    cudaFuncSetAttribute(attn_full_kernel,
                         cudaFuncAttributeMaxDynamicSharedMemorySize, ATTN_F_SMEM);
    cudaFuncSetAttribute(attn_causal_kernel,
                         cudaFuncAttributeMaxDynamicSharedMemorySize, ATTN_C_SMEM);

    fold_kernel<<<48, 256>>>(
        fqkW, fqkb, fqkg, fqkbe, fqkm, fqkv,
        tqkW, tqkb, tqkg, tqkbe, tqkm, tqkv,
        fvW,  fvb,  fvg,  fvbe,  fvm,  fvv,
        prW,  prb,  prg,  prbe,  prm,  prv);

    conv_qk_kernel<<<dim3(512, Bn), 256, CQK_SMEM>>>(inp, fqka, tqka);

    conv_v_kernel<<<dim3(256, Bn), 256, CV_SMEM>>>(x, fva);

    attn_full_kernel<<<dim3(256, Bn), 256, ATTN_F_SMEM>>>();

    attn_causal_kernel<<<dim3(512, Bn), 256, ATTN_C_SMEM>>>();

    proj_kernel<<<dim3(512, Bn), 256, PR_SMEM>>>(x, pra, out);
}